// round 12
// baseline (speedup 1.0000x reference)
#include <cuda_runtime.h>
#include <cuda_fp16.h>
#include <math.h>

// ---------------- problem constants ----------------
#define Bq 2
#define Tt 2048
#define Cc 2048
#define Hh 32
#define Nn 64
#define Ff 7168
#define MM (Bq*Tt)          // 4096 tokens
#define NF1 (Ff + Cc)       // 9216 rows in merged [Wck^T ; Wcr^T] buffer
#define CH 16               // scan chunks
#define CL (Tt/CH)          // 128 steps per chunk
#define LDA_A 320           // padded a16 row stride

typedef unsigned int u32;
typedef unsigned long long u64;

// ---------------- device scratch (no allocs allowed) ----------------
__device__ float g_h  [(size_t)MM*Cc];
__device__ float g_xx [(size_t)MM*Cc];
__device__ float g_w  [(size_t)MM*Cc];
__device__ float g_wt [(size_t)MM*64];
__device__ float g_y  [(size_t)MM*Cc];
__device__ float g_x1 [(size_t)MM*Cc];
__device__ float g_sig[(size_t)MM*Cc];
__device__ float g_out4[(size_t)4*MM*Cc];   // r,k,v,g
__device__ float g_rq [(size_t)MM*Cc];      // r * cumdecay (scan phase A)
__device__ float g_P  [(size_t)64*CH*4096]; // chunk-final local states
__device__ float g_D  [(size_t)64*CH*64];   // chunk decay products
__device__ float g_S0 [(size_t)64*CH*4096]; // chunk initial states

// fp16 activations
__device__ __align__(16) __half g_a16  [(size_t)MM*LDA_A];  // tanh(xxx@maa_w1), padded
__device__ __align__(16) __half g_xxx16[(size_t)MM*Cc];
__device__ __align__(16) __half g_xw16 [(size_t)MM*Cc];
__device__ __align__(16) __half g_act4 [(size_t)4*MM*Cc];   // xr,xk,xv,xg
__device__ __align__(16) __half g_att16[(size_t)MM*Cc];
__device__ __align__(16) __half g_xk216[(size_t)MM*Cc];
__device__ __align__(16) __half g_xr216[(size_t)MM*Cc];
__device__ __align__(16) __half g_kf16 [(size_t)MM*Ff];

// fp16 transposed weights ([N,K] K-major)
__device__ __align__(16) __half g_W4_16 [(size_t)4*Cc*Cc];  // Wr,Wk,Wv,Wg
__device__ __align__(16) __half g_Wo16  [(size_t)Cc*Cc];
__device__ __align__(16) __half g_Wffn1 [(size_t)NF1*Cc];   // [Wck^T ; Wcr^T]
__device__ __align__(16) __half g_Wcv16 [(size_t)Ff*Cc];    // [2048,7168]
__device__ __align__(16) __half g_maaw1T[(size_t)256*Cc];   // padded [256,2048]
__device__ __align__(16) __half g_tdw1T [(size_t)128*Cc];   // padded [128,2048]
__device__ __align__(16) __half g_w2T   [(size_t)5*Cc*128]; // per-f [2048,128], cols>=32 zero

// ---------------- PTX helpers (baseline PTX; no sm_103a-only features) ----
__device__ __forceinline__ u32 smem_u32(const void* p){
    u32 a;
    asm("{ .reg .u64 t; cvta.to.shared.u64 t, %1; cvt.u32.u64 %0, t; }" : "=r"(a) : "l"(p));
    return a;
}
__device__ __forceinline__ void cp16(u32 s, const void* g){
    asm volatile("cp.async.cg.shared.global [%0], [%1], 16;" :: "r"(s), "l"(g) : "memory");
}
__device__ __forceinline__ void cp_commit(){
    asm volatile("cp.async.commit_group;" ::: "memory");
}
template<int NG> __device__ __forceinline__ void cp_wait(){
    asm volatile("cp.async.wait_group %0;" :: "n"(NG) : "memory");
}
__device__ __forceinline__ void ldsm4(u32* r, u32 a){
    asm volatile("ldmatrix.sync.aligned.m8n8.x4.shared.b16 {%0,%1,%2,%3}, [%4];"
        : "=r"(r[0]), "=r"(r[1]), "=r"(r[2]), "=r"(r[3]) : "r"(a));
}
__device__ __forceinline__ void hmma16(float* c, const u32* a, u32 b0, u32 b1){
    asm volatile(
        "mma.sync.aligned.m16n8k16.row.col.f32.f16.f16.f32 "
        "{%0,%1,%2,%3},{%4,%5,%6,%7},{%8,%9},{%0,%1,%2,%3};"
        : "+f"(c[0]), "+f"(c[1]), "+f"(c[2]), "+f"(c[3])
        : "r"(a[0]), "r"(a[1]), "r"(a[2]), "r"(a[3]), "r"(b0), "r"(b1));
}

// ---------------- fp16 HMMA GEMM body, templated tile-M ----------------
enum { TC_NONE=0, TC_SILU, TC_ADDX, TC_SIGM, TC_CVMIX, TC_TANH, TC_RELU2H,
       TC_TANH16, TC_MIX };

#define SM_MMA_128 (3*32768)   // 3 stages x (A 16K + B 16K)
#define SM_MMA_64  (3*24576)   // 3 stages x (A 8K  + B 16K)

template<int EPI, int TM>
__device__ __forceinline__
void mma_body(const __half* __restrict__ A16, const __half* __restrict__ B16,
              float* __restrict__ C, int M, int N, int K, int lda, int ldb,
              int ldc, int nvalid,
              const float* __restrict__ aux0, const float* __restrict__ aux1,
              const float* __restrict__ aux2, __half* __restrict__ Ch)
{
    constexpr int MI = TM / 32;             // warp m-subtiles of 16 rows
    constexpr u32 A_BYTES = (u32)TM * 128u;
    constexpr u32 STG = A_BYTES + 16384u;

    extern __shared__ char sm_dyn[];
    const u32 sb = smem_u32(sm_dyn);
    const int tid  = threadIdx.x;
    const int wid  = tid >> 5;
    const int lane = tid & 31;
    const int m0 = blockIdx.y * TM;
    const int n0 = blockIdx.x * 128;
    const int wm = (wid & 1) * (TM / 2);
    const int wn = (wid >> 1) * 32;

    const int col16 = tid & 7;
    const int lrow  = tid >> 3;             // 0..31
    const u32 soff  = (u32)(lrow * 128 + col16 * 16);
    const u32 swz   = soff ^ ((soff >> 3) & 0x70);
    const size_t rstep_a = (size_t)32 * lda * 2;
    const size_t rstep_b = (size_t)32 * ldb * 2;
    const char* gA = (const char*)A16 + ((size_t)(m0 + lrow) * lda + col16 * 8) * 2;
    const char* gB = (const char*)B16 + ((size_t)(n0 + lrow) * ldb + col16 * 8) * 2;

    auto load_stage = [&](int s){
        u32 base = sb + (u32)(s % 3) * STG + swz;
        size_t ko = (size_t)s * 128;        // 64 fp16 = 128B along K
        #pragma unroll
        for (int i = 0; i < TM/32; i++)
            cp16(base + i*4096u, gA + ko + i*rstep_a);
        #pragma unroll
        for (int i = 0; i < 4; i++)
            cp16(base + A_BYTES + i*4096u, gB + ko + i*rstep_b);
        cp_commit();
    };

    const u32 a_row = (u32)(wm + ((lane >> 3) & 1) * 8 + (lane & 7));
    const u32 a_kb  = (u32)((lane >> 4) * 16);
    const u32 b_row = (u32)(wn + (lane >> 4) * 8 + (lane & 7));
    const u32 b_kb  = (u32)(((lane >> 3) & 1) * 16);

    float acc[MI][4][4];
    #pragma unroll
    for (int mi = 0; mi < MI; mi++)
        #pragma unroll
        for (int ni = 0; ni < 4; ni++)
            #pragma unroll
            for (int q = 0; q < 4; q++) acc[mi][ni][q] = 0.f;

    auto compute_stage = [&](u32 base){
        #pragma unroll
        for (int kk = 0; kk < 4; kk++){
            u32 aa[MI][4], bb[2][4];
            #pragma unroll
            for (int mi = 0; mi < MI; mi++){
                u32 off = (a_row + mi*16u) * 128u + (u32)kk*32u + a_kb;
                off ^= (off >> 3) & 0x70;
                ldsm4(aa[mi], base + off);
            }
            #pragma unroll
            for (int nj = 0; nj < 2; nj++){
                u32 off = (b_row + nj*16u) * 128u + (u32)kk*32u + b_kb;
                off ^= (off >> 3) & 0x70;
                ldsm4(bb[nj], base + A_BYTES + off);
            }
            #pragma unroll
            for (int mi = 0; mi < MI; mi++)
                #pragma unroll
                for (int ni = 0; ni < 4; ni++){
                    const u32* pb = &bb[ni >> 1][(ni & 1) * 2];
                    hmma16(acc[mi][ni], aa[mi], pb[0], pb[1]);
                }
        }
    };

    const int NS = K >> 6;
    load_stage(0);
    load_stage(1);
    for (int s = 0; s < NS; s++){
        if (s + 1 < NS) cp_wait<1>(); else cp_wait<0>();
        __syncthreads();
        if (s + 2 < NS) load_stage(s + 2);
        compute_stage(sb + (u32)(s % 3) * STG);
    }

    #pragma unroll
    for (int mi = 0; mi < MI; mi++){
        #pragma unroll
        for (int ni = 0; ni < 4; ni++){
            const int n = n0 + wn + ni*8 + (lane & 3)*2;
            if (n >= nvalid) continue;
            #pragma unroll
            for (int half = 0; half < 2; half++){
                const int m = m0 + wm + mi*16 + (lane >> 2) + half*8;
                const size_t idx = (size_t)m * ldc + n;
                float v0 = acc[mi][ni][half*2 + 0];
                float v1 = acc[mi][ni][half*2 + 1];
                if (EPI == TC_RELU2H){
                    float r0 = v0 > 0.f ? v0 : 0.f;
                    float r1 = v1 > 0.f ? v1 : 0.f;
                    __half2 hp;
                    hp.x = __float2half_rn(r0 * r0);
                    hp.y = __float2half_rn(r1 * r1);
                    *reinterpret_cast<__half2*>(Ch + idx) = hp;
                    continue;
                }
                if (EPI == TC_TANH16){
                    __half2 hp;
                    hp.x = __float2half_rn(tanhf(v0));
                    hp.y = __float2half_rn(tanhf(v1));
                    *reinterpret_cast<__half2*>(Ch + idx) = hp;
                    continue;
                }
                if (EPI == TC_MIX){
                    float o0 = aux0[idx]     + aux1[idx]     * (aux2[n]     + v0);
                    float o1 = aux0[idx + 1] + aux1[idx + 1] * (aux2[n + 1] + v1);
                    __half2 hp;
                    hp.x = __float2half_rn(o0);
                    hp.y = __float2half_rn(o1);
                    *reinterpret_cast<__half2*>(Ch + idx) = hp;
                    continue;
                }
                if (EPI == TC_SILU){
                    v0 = v0 / (1.f + expf(-v0));
                    v1 = v1 / (1.f + expf(-v1));
                } else if (EPI == TC_TANH){
                    v0 = tanhf(v0); v1 = tanhf(v1);
                } else if (EPI == TC_ADDX){
                    v0 += aux0[idx]; v1 += aux0[idx + 1];
                } else if (EPI == TC_SIGM){
                    v0 = 1.f / (1.f + expf(-v0));
                    v1 = 1.f / (1.f + expf(-v1));
                } else if (EPI == TC_CVMIX){
                    v0 = aux0[idx]     + aux1[idx]     * v0;
                    v1 = aux0[idx + 1] + aux1[idx + 1] * v1;
                }
                float2 o; o.x = v0; o.y = v1;
                *reinterpret_cast<float2*>(C + idx) = o;
            }
        }
    }
}

template<int EPI, int TM>
__global__ __launch_bounds__(256, 2)
void gemm_mma(const __half* __restrict__ A16, const __half* __restrict__ B16,
              float* __restrict__ C, int M, int N, int K, int lda, int ldb,
              int ldc, int nvalid,
              const float* __restrict__ aux0, const float* __restrict__ aux1,
              const float* __restrict__ aux2, __half* __restrict__ Ch)
{
    mma_body<EPI, TM>(A16, B16, C, M, N, K, lda, ldb, ldc, nvalid,
                      aux0, aux1, aux2, Ch);
}

// mix GEMM: z = f in [0,5). A = a16 + f*32 (lda=320), B = w2T[f] (ldb=128, K=64).
__global__ __launch_bounds__(256, 2)
void gemm_mix(const __half* __restrict__ a16, const __half* __restrict__ w2T,
              const float* __restrict__ tm_maa,
              const float* __restrict__ h, const float* __restrict__ xx,
              __half* __restrict__ xw16, __half* __restrict__ a4)
{
    const int f = blockIdx.z;
    const int slot = (f == 1) ? 1 : (f == 2) ? 2 : (f == 3) ? 0 : 3;
    __half* Ch = (f == 0) ? xw16 : a4 + (size_t)slot * MM * Cc;
    mma_body<TC_MIX, 128>(a16 + f*32, w2T + (size_t)f * Cc * 128, nullptr,
                          MM, Cc, 64, LDA_A, 128, Cc, Cc,
                          h, xx, tm_maa + (size_t)(1 + f) * Cc, Ch);
}

// merged r/k/v/g + td GEMM: z=0..3 rkvg (z==3 silu); z==4: td tanh (x==0 only)
__global__ __launch_bounds__(256, 2)
void gemm_rkvg5(const __half* __restrict__ A4, const __half* __restrict__ W4,
                float* __restrict__ C4,
                const __half* __restrict__ xw16, const __half* __restrict__ tdT,
                float* __restrict__ wt)
{
    const int z = blockIdx.z;
    if (z == 4){
        if (blockIdx.x != 0) return;
        mma_body<TC_TANH, 128>(xw16, tdT, wt, MM, 128, Cc, Cc, Cc, 64, 64,
                               nullptr, nullptr, nullptr, nullptr);
        return;
    }
    const size_t ao = (size_t)z * MM * Cc;
    const size_t wo = (size_t)z * Cc * Cc;
    if (z == 3)
        mma_body<TC_SILU, 128>(A4 + ao, W4 + wo, C4 + ao, MM, Cc, Cc, Cc, Cc, Cc, Cc,
                               nullptr, nullptr, nullptr, nullptr);
    else
        mma_body<TC_NONE, 128>(A4 + ao, W4 + wo, C4 + ao, MM, Cc, Cc, Cc, Cc, Cc, Cc,
                               nullptr, nullptr, nullptr, nullptr);
}

// merged ffn1: grid (72, 32). Tiles [0,56): relu2(xk2@Wck)->kf16.
// Tiles [56,72): sigmoid(xr2@Wcr)->psig (bases shifted by -Ff to rebase n).
__global__ __launch_bounds__(256, 2)
void gemm_ffn1(const __half* __restrict__ xk2, const __half* __restrict__ xr2,
               const __half* __restrict__ Wf, __half* __restrict__ kf,
               float* __restrict__ sig, int split)
{
    if ((int)blockIdx.x < split){
        mma_body<TC_RELU2H, 128>(xk2, Wf, nullptr, MM, Ff, Cc, Cc, Cc, Ff, Ff,
                                 nullptr, nullptr, nullptr, kf);
    } else {
        mma_body<TC_SIGM, 128>(xr2, Wf, sig - Ff, MM, NF1, Cc, Cc, Cc, Cc, NF1,
                               nullptr, nullptr, nullptr, nullptr);
    }
}

// ---------------- merged weight prep: all transposes in one launch ----------
#define WT_TOTAL 54336
__global__ __launch_bounds__(256)
void wtrans_all(const float* __restrict__ Wr, const float* __restrict__ Wk,
                const float* __restrict__ Wv, const float* __restrict__ Wg,
                const float* __restrict__ Wo, const float* __restrict__ Wcr,
                const float* __restrict__ Wck, const float* __restrict__ Wcv,
                const float* __restrict__ maa_w1, const float* __restrict__ td_w1,
                const float* __restrict__ maa_w2,
                __half* __restrict__ T4, __half* __restrict__ To,
                __half* __restrict__ Tcr, __half* __restrict__ Tck,
                __half* __restrict__ Tcv, __half* __restrict__ TmaaT,
                __half* __restrict__ TtdT, __half* __restrict__ w2T)
{
    __shared__ float s[32][33];
    const int t = blockIdx.x;
    const int tx = threadIdx.x & 31, ty = threadIdx.x >> 5;

    if (t >= 54016){
        const int r = t - 54016;
        const int f = r >> 6;
        const int c0 = (r & 63) * 32;
        #pragma unroll
        for (int rr = 0; rr < 32; rr += 8)
            s[ty + rr][tx] = maa_w2[((size_t)f * 32 + ty + rr) * Cc + c0 + tx];
        __syncthreads();
        const int c = threadIdx.x >> 3;
        const int dseg = (threadIdx.x & 7) * 16;
        __half* outp = w2T + ((size_t)f * Cc + c0 + c) * 128 + dseg;
        #pragma unroll
        for (int dd = 0; dd < 16; dd += 2){
            int d0 = dseg + dd;
            __half2 hp;
            hp.x = __float2half_rn(d0     < 32 ? s[d0][c]     : 0.f);
            hp.y = __float2half_rn(d0 + 1 < 32 ? s[d0 + 1][c] : 0.f);
            *reinterpret_cast<__half2*>(outp + dd) = hp;
        }
        return;
    }

    const float* W; __half* T; int K, N, bx, by; bool pad = false;
    if (t < 24576){
        int z = t >> 12, r = t & 4095;
        W = (z==0)?Wr:(z==1)?Wk:(z==2)?Wv:(z==3)?Wg:(z==4)?Wo:Wcr;
        T = (z < 4) ? T4 + (size_t)z * Cc * Cc : (z == 4 ? To : Tcr);
        K = Cc; N = Cc; bx = r & 63; by = r >> 6;
    } else if (t < 38912){
        int r = t - 24576;
        W = Wck; T = Tck; K = Cc; N = Ff; bx = r % 224; by = r / 224;
    } else if (t < 53248){
        int r = t - 38912;
        W = Wcv; T = Tcv; K = Ff; N = Cc; bx = r & 63; by = r >> 6;
    } else if (t < 53760){
        int r = t - 53248;
        W = maa_w1; T = TmaaT; K = Cc; N = 160; pad = true; bx = r & 7; by = r >> 3;
    } else {
        int r = t - 53760;
        W = td_w1; T = TtdT; K = Cc; N = 64; pad = true; bx = r & 3; by = r >> 2;
    }

    const int n0 = bx * 32, k0 = by * 32;
    #pragma unroll
    for (int rr = 0; rr < 32; rr += 8){
        int n = n0 + tx;
        s[ty + rr][tx] = (!pad || n < N) ? W[(size_t)(k0 + ty + rr) * N + n] : 0.f;
    }
    __syncthreads();
    #pragma unroll
    for (int rr = 0; rr < 32; rr += 8)
        T[(size_t)(n0 + ty + rr) * K + k0 + tx] = __float2half_rn(s[tx][ty + rr]);
}

// ---------------- small SIMT fp32 GEMM (td_w2 only) ----------------
#define BMt 128
#define BNt 128
#define BKt 8
#define TMt 8
#define TNt 8
__global__ __launch_bounds__(256)
void gemm_addvec(const float* __restrict__ A, const float* __restrict__ Bm,
                 float* __restrict__ Cm, int M, int N, int K, int lda, int ldc,
                 const float* __restrict__ aux0)
{
    __shared__ float As[BKt][BMt];
    __shared__ float Bs[BKt][BNt];
    const int bm = blockIdx.y * BMt;
    const int bn = blockIdx.x * BNt;
    const int tid = threadIdx.x;
    const int tcol = tid & 15;
    const int trow = tid >> 4;
    const int a_row = tid >> 1;
    const int a_col = (tid & 1) * 4;
    const int b_row = tid >> 5;
    const int b_col = (tid & 31) * 4;

    float acc[TMt][TNt];
    #pragma unroll
    for (int i = 0; i < TMt; i++)
        #pragma unroll
        for (int j = 0; j < TNt; j++) acc[i][j] = 0.f;

    for (int k0 = 0; k0 < K; k0 += BKt) {
        float4 av = *reinterpret_cast<const float4*>(A + (size_t)(bm + a_row)*lda + k0 + a_col);
        As[a_col+0][a_row] = av.x;
        As[a_col+1][a_row] = av.y;
        As[a_col+2][a_row] = av.z;
        As[a_col+3][a_row] = av.w;
        *reinterpret_cast<float4*>(&Bs[b_row][b_col]) =
            *reinterpret_cast<const float4*>(Bm + (size_t)(k0 + b_row)*N + bn + b_col);
        __syncthreads();
        #pragma unroll
        for (int kk = 0; kk < BKt; kk++) {
            float regM[TMt], regN[TNt];
            *(float4*)&regM[0] = *(const float4*)&As[kk][trow*TMt];
            *(float4*)&regM[4] = *(const float4*)&As[kk][trow*TMt + 4];
            *(float4*)&regN[0] = *(const float4*)&Bs[kk][tcol*TNt];
            *(float4*)&regN[4] = *(const float4*)&Bs[kk][tcol*TNt + 4];
            #pragma unroll
            for (int i = 0; i < TMt; i++)
                #pragma unroll
                for (int j = 0; j < TNt; j++)
                    acc[i][j] = fmaf(regM[i], regN[j], acc[i][j]);
        }
        __syncthreads();
    }

    #pragma unroll
    for (int i = 0; i < TMt; i++) {
        int m = bm + trow*TMt + i;
        #pragma unroll
        for (int j = 0; j < TNt; j++) {
            int n = bn + tcol*TNt + j;
            Cm[(size_t)m * ldc + n] = aux0[n] + acc[i][j];
        }
    }
}

// ---------------- LayerNorm over C per token ----------------
__global__ __launch_bounds__(256)
void ln_kernel(const float* __restrict__ x, const float* __restrict__ w,
               const float* __restrict__ b, float* __restrict__ out, float eps)
{
    const size_t base = (size_t)blockIdx.x * Cc;
    float sum = 0.f, sq = 0.f;
    for (int c = threadIdx.x; c < Cc; c += 256) { float v = x[base + c]; sum += v; sq += v*v; }
    #pragma unroll
    for (int o = 16; o; o >>= 1) {
        sum += __shfl_xor_sync(0xffffffffu, sum, o);
        sq  += __shfl_xor_sync(0xffffffffu, sq,  o);
    }
    __shared__ float s1[8], s2[8];
    int wid = threadIdx.x >> 5, lane = threadIdx.x & 31;
    if (!lane) { s1[wid] = sum; s2[wid] = sq; }
    __syncthreads();
    if (threadIdx.x == 0) {
        float ts = 0.f, tq = 0.f;
        #pragma unroll
        for (int i = 0; i < 8; i++) { ts += s1[i]; tq += s2[i]; }
        float m = ts / (float)Cc;
        float var = tq / (float)Cc - m*m;
        s1[0] = m; s2[0] = rsqrtf(var + eps);
    }
    __syncthreads();
    float m = s1[0], rstd = s2[0];
    for (int c = threadIdx.x; c < Cc; c += 256)
        out[base + c] = (x[base + c] - m) * rstd * w[c] + b[c];
}

// ---------------- token shift + first mix -> fp16 ----------------
__global__ void shift1_kernel(const float* __restrict__ tm_maa)
{
    size_t idx = (size_t)blockIdx.x * 256 + threadIdx.x;
    int c  = (int)(idx % Cc);
    int tt = (int)(idx / Cc);
    int t  = tt % Tt;
    float hv = g_h[idx];
    float hp = t ? g_h[idx - Cc] : 0.f;
    float d = hp - hv;
    g_xx[idx] = d;
    g_xxx16[idx] = __float2half_rn(hv + d * tm_maa[c]);
}

// ---------------- token shift (channel mixing) -> fp16 ----------------
__global__ void shift2_kernel(const float* __restrict__ cm_maa)
{
    size_t idx = (size_t)blockIdx.x * 256 + threadIdx.x;
    int c  = (int)(idx % Cc);
    int tt = (int)(idx / Cc);
    int t  = tt % Tt;
    float hv = g_h[idx];
    float hp = t ? g_h[idx - Cc] : 0.f;
    float d = hp - hv;
    g_xk216[idx] = __float2half_rn(hv + d * cm_maa[c]);
    g_xr216[idx] = __float2half_rn(hv + d * cm_maa[Cc + c]);
}

// ---------------- WKV6 chunk-parallel scan ----------------
__global__ __launch_bounds__(256)
void wkv6_partA(const float* __restrict__ u,
                const float* __restrict__ rr, const float* __restrict__ kk,
                const float* __restrict__ vv, const float* __restrict__ ww,
                float* __restrict__ yy, float* __restrict__ rq,
                float* __restrict__ Pc, float* __restrict__ Dc)
{
    const int blk = blockIdx.x;
    const int bh = blk >> 4;
    const int ch = blk & (CH - 1);
    const int b = bh >> 5, hh = bh & 31;
    const int tid = threadIdx.x;
    const int j = tid & 63;
    const int ib = (tid >> 6) * 16;
    __shared__ float4 sv[64];
    __shared__ float  yp[256];
    float S[16];
    #pragma unroll
    for (int i = 0; i < 16; i++) S[i] = 0.f;
    size_t off = (size_t)b * Tt * Cc + (size_t)ch * CL * Cc + (size_t)hh * Nn;
    float ur = (tid < 64) ? u[hh * Nn + j] : 0.f;
    float cum = 1.f;

    float rn = 0.f, kn = 0.f, wn = 0.f, vn;
    if (tid < 64){ rn = rr[off + j]; kn = kk[off + j]; wn = ww[off + j]; }
    vn = vv[off + j];

    for (int t = 0; t < CL; t++) {
        float rc = rn, kc = kn, wc = wn, vc = vn;
        size_t offn = off + Cc;
        if (t + 1 < CL){
            if (tid < 64){ rn = rr[offn + j]; kn = kk[offn + j]; wn = ww[offn + j]; }
            vn = vv[offn + j];
        }
        if (tid < 64){
            float d = expf(-expf(wc));
            rq[off + j] = rc * cum;
            cum *= d;
            sv[j] = make_float4(rc, kc, ur * kc, d);
        }
        __syncthreads();
        float a0 = 0.f, a1 = 0.f;
        #pragma unroll
        for (int ii = 0; ii < 16; ii += 2) {
            float4 q0 = sv[ib + ii];
            float4 q1 = sv[ib + ii + 1];
            a0 = fmaf(q0.x, fmaf(q0.z, vc, S[ii]), a0);
            S[ii] = fmaf(S[ii], q0.w, q0.y * vc);
            a1 = fmaf(q1.x, fmaf(q1.z, vc, S[ii + 1]), a1);
            S[ii + 1] = fmaf(S[ii + 1], q1.w, q1.y * vc);
        }
        yp[tid] = a0 + a1;
        __syncthreads();
        if (tid < 64) yy[off + j] = yp[j] + yp[64 + j] + yp[128 + j] + yp[192 + j];
        off = offn;
    }
    const size_t pbase = ((size_t)bh * CH + ch) * 4096;
    #pragma unroll
    for (int ii = 0; ii < 16; ii++)
        Pc[pbase + (size_t)(ib + ii) * 64 + j] = S[ii];
    if (tid < 64) Dc[((size_t)bh * CH + ch) * 64 + j] = cum;
}

__global__ __launch_bounds__(256)
void wkv6_partB(const float* __restrict__ Pc, const float* __restrict__ Dc,
                float* __restrict__ S0)
{
    const int bh = blockIdx.x;
    const int tid = threadIdx.x;
    const int e0 = tid * 16;
    const int i  = e0 >> 6;
    float4 s[4];
    #pragma unroll
    for (int q = 0; q < 4; q++) s[q] = make_float4(0.f, 0.f, 0.f, 0.f);
    for (int ch = 0; ch < CH; ch++){
        const size_t base = ((size_t)bh * CH + ch) * 4096 + e0;
        #pragma unroll
        for (int q = 0; q < 4; q++)
            *reinterpret_cast<float4*>(&S0[base + q*4]) = s[q];
        const float d = Dc[((size_t)bh * CH + ch) * 64 + i];
        #pragma unroll
        for (int q = 0; q < 4; q++){
            float4 p = *reinterpret_cast<const float4*>(&Pc[base + q*4]);
            s[q].x = fmaf(s[q].x, d, p.x);
            s[q].y = fmaf(s[q].y, d, p.y);
            s[q].z = fmaf(s[q].z, d, p.z);
            s[q].w = fmaf(s[q].w, d, p.w);
        }
    }
}

__global__ __launch_bounds__(256)
void wkv6_partC(const float* __restrict__ rq, const float* __restrict__ S0,
                float* __restrict__ yy)
{
    const int x = blockIdx.x;
    const int half = x & 1;
    const int ch = (x >> 1) & (CH - 1);
    const int bh = x >> 5;
    if (ch == 0) return;
    const int b = bh >> 5, hh = bh & 31;
    __shared__ float sS0[64][68];
    __shared__ float sRq[64][68];
    const int tid = threadIdx.x;
    const size_t off = (size_t)b * Tt * Cc
                     + (size_t)(ch * CL + half * 64) * Cc + (size_t)hh * Nn;
    const size_t sbase = ((size_t)bh * CH + ch) * 4096;

    {
        const int e0 = tid * 16;
        const int r = e0 >> 6, c = e0 & 63;
        #pragma unroll
        for (int q = 0; q < 4; q++){
            float4 v = *reinterpret_cast<const float4*>(&S0[sbase + e0 + q*4]);
            *reinterpret_cast<float4*>(&sS0[r][c + q*4]) = v;
            float4 w = *reinterpret_cast<const float4*>(&rq[off + (size_t)r * Cc + c + q*4]);
            *reinterpret_cast<float4*>(&sRq[r][c + q*4]) = w;
        }
    }
    __syncthreads();

    const int tr = tid >> 2;
    const int jq = (tid & 3) * 16;
    float acc[16];
    #pragma unroll
    for (int q = 0; q < 16; q++) acc[q] = 0.f;
    #pragma unroll 4
    for (int i = 0; i < 64; i++){
        float rv = sRq[tr][i];
        #pragma unroll
        for (int q = 0; q < 16; q++)
            acc[q] = fmaf(rv, sS0[i][jq + q], acc[q]);
    }
    const size_t ybase = off + (size_t)tr * Cc + jq;
    #pragma unroll
    for (int q = 0; q < 16; q += 4){
        float4 y4 = *reinterpret_cast<float4*>(&yy[ybase + q]);
        y4.x += acc[q];     y4.y += acc[q + 1];
        y4.z += acc[q + 2]; y4.w += acc[q + 3];
        *reinterpret_cast<float4*>(&yy[ybase + q]) = y4;
    }
}

// ---------------- GroupNorm(H) * silu-gate -> att fp16 ----------------
__global__ __launch_bounds__(256)
void gnsilu_kernel(const float* __restrict__ lnw, const float* __restrict__ lnb,
                   const float* __restrict__ gg, const float* __restrict__ yy)
{
    int gw  = blockIdx.x * 8 + (threadIdx.x >> 5);
    int lane = threadIdx.x & 31;
    int t  = gw >> 5;
    int hh = gw & 31;
    size_t base = (size_t)t * Cc + (size_t)hh * Nn;
    float y0 = yy[base + lane], y1 = yy[base + 32 + lane];
    float sum = y0 + y1, sq = y0*y0 + y1*y1;
    #pragma unroll
    for (int o = 16; o; o >>= 1) {
        sum += __shfl_xor_sync(0xffffffffu, sum, o);
        sq  += __shfl_xor_sync(0xffffffffu, sq,  o);
    }
    float m = sum * (1.f / 64.f);
    float rstd = rsqrtf(sq * (1.f / 64.f) - m*m + 6.4e-4f);
    int ch = hh * Nn + lane;
    float gv0 = gg[base + lane], gv1 = gg[base + 32 + lane];
    float o0 = ((y0 - m) * rstd * lnw[ch]      + lnb[ch])      * gv0;
    float o1 = ((y1 - m) * rstd * lnw[ch + 32] + lnb[ch + 32]) * gv1;
    g_att16[base + lane]      = __float2half_rn(o0);
    g_att16[base + 32 + lane] = __float2half_rn(o1);
}

// ---------------- host launch (single stream) ----------------
#define SYMADDR(v, s) cudaGetSymbolAddress((void**)&v, s)

extern "C" void kernel_launch(void* const* d_in, const int* in_sizes, int n_in,
                              void* d_out, int out_size)
{
    (void)in_sizes; (void)n_in; (void)out_size;
    const float* x          = (const float*)d_in[0];
    const float* ln1_w      = (const float*)d_in[1];
    const float* ln1_b      = (const float*)d_in[2];
    const float* ln2_w      = (const float*)d_in[3];
    const float* ln2_b      = (const float*)d_in[4];
    const float* tm_maa     = (const float*)d_in[5];
    const float* maa_w1     = (const float*)d_in[6];
    const float* maa_w2     = (const float*)d_in[7];
    const float* time_decay = (const float*)d_in[8];
    const float* td_w1      = (const float*)d_in[9];
    const float* td_w2      = (const float*)d_in[10];
    const float* time_faaaa = (const float*)d_in[11];
    const float* Wr  = (const float*)d_in[12];
    const float* Wk  = (const float*)d_in[13];
    const float* Wv  = (const float*)d_in[14];
    const float* Wg  = (const float*)d_in[15];
    const float* Wo  = (const float*)d_in[16];
    const float* lnx_w = (const float*)d_in[17];
    const float* lnx_b = (const float*)d_in[18];
    const float* cm_maa = (const float*)d_in[19];
    const float* Wck = (const float*)d_in[20];
    const float* Wcr = (const float*)d_in[21];
    const float* Wcv = (const float*)d_in[22];
    float* out = (float*)d_out;

    float *ph, *pxx, *pw, *pwt, *py, *px1, *psig, *pout4, *prq, *pP, *pD, *pS0;
    SYMADDR(ph, g_h);   SYMADDR(pxx, g_xx);
    SYMADDR(pw, g_w);   SYMADDR(pwt, g_wt); SYMADDR(py, g_y);
    SYMADDR(px1, g_x1); SYMADDR(psig, g_sig); SYMADDR(pout4, g_out4);
    SYMADDR(prq, g_rq); SYMADDR(pP, g_P);   SYMADDR(pD, g_D);  SYMADDR(pS0, g_S0);

    __half *a16,*xxx16,*xw16,*a4,*att16,*xk216,*xr216,*kf16;
    SYMADDR(a16, g_a16);
    SYMADDR(xxx16, g_xxx16); SYMADDR(xw16, g_xw16);
    SYMADDR(a4, g_act4);     SYMADDR(att16, g_att16);
    SYMADDR(xk216, g_xk216); SYMADDR(xr216, g_xr216);
    SYMADDR(kf16, g_kf16);

    __half *w4,*wo16,*wffn1,*wcv16,*maaT,*tdT,*w2T;
    SYMADDR(w4, g_W4_16);    SYMADDR(wo16, g_Wo16);
    SYMADDR(wffn1, g_Wffn1); SYMADDR(wcv16, g_Wcv16);
    SYMADDR(maaT, g_maaw1T); SYMADDR(tdT, g_tdw1T);
    SYMADDR(w2T, g_w2T);

    cudaFuncSetAttribute((const void*)gemm_mma<TC_TANH16,64>, cudaFuncAttributeMaxDynamicSharedMemorySize, SM_MMA_64);
    cudaFuncSetAttribute((const void*)gemm_mma<TC_ADDX,64>,   cudaFuncAttributeMaxDynamicSharedMemorySize, SM_MMA_64);
    cudaFuncSetAttribute((const void*)gemm_mma<TC_CVMIX,64>,  cudaFuncAttributeMaxDynamicSharedMemorySize, SM_MMA_64);
    cudaFuncSetAttribute((const void*)gemm_mix,               cudaFuncAttributeMaxDynamicSharedMemorySize, SM_MMA_128);
    cudaFuncSetAttribute((const void*)gemm_rkvg5,             cudaFuncAttributeMaxDynamicSharedMemorySize, SM_MMA_128);
    cudaFuncSetAttribute((const void*)gemm_ffn1,              cudaFuncAttributeMaxDynamicSharedMemorySize, SM_MMA_128);

    const int ELT_BLOCKS = (MM * Cc) / 256;

    // ---- weight prep: one launch ----
    wtrans_all<<<WT_TOTAL, 256>>>(Wr, Wk, Wv, Wg, Wo, Wcr, Wck, Wcv,
        maa_w1, td_w1, maa_w2,
        w4, wo16, wffn1 + (size_t)Ff * Cc, wffn1, wcv16, maaT, tdT, w2T);

    // ---- time mixing ----
    ln_kernel<<<MM, 256>>>(x, ln1_w, ln1_b, ph, 1e-5f);
    shift1_kernel<<<ELT_BLOCKS, 256>>>(tm_maa);
    gemm_mma<TC_TANH16,64><<<dim3(256/128, MM/64), 256, SM_MMA_64>>>(xxx16, maaT, nullptr,
        MM, 256, Cc, Cc, Cc, LDA_A, 192, nullptr, nullptr, nullptr, a16);
    gemm_mix<<<dim3(Cc/128, MM/128, 5), 256, SM_MMA_128>>>(a16, w2T, tm_maa,
        ph, pxx, xw16, a4);
    gemm_rkvg5<<<dim3(Cc/128, MM/128, 5), 256, SM_MMA_128>>>(a4, w4, pout4,
        xw16, tdT, pwt);
    gemm_addvec<<<dim3(Cc/128, MM/128), 256>>>(pwt, td_w2, pw, MM, Cc, 64, 64, Cc, time_decay);
    wkv6_partA<<<64 * CH, 256>>>(time_faaaa,
        pout4 + (size_t)0*MM*Cc, pout4 + (size_t)1*MM*Cc, pout4 + (size_t)2*MM*Cc,
        pw, py, prq, pP, pD);
    wkv6_partB<<<64, 256>>>(pP, pD, pS0);
    wkv6_partC<<<64 * CH * 2, 256>>>(prq, pS0, py);
    gnsilu_kernel<<<MM * Hh / 8, 256>>>(lnx_w, lnx_b, pout4 + (size_t)3*MM*Cc, py);
    gemm_mma<TC_ADDX,64><<<dim3(Cc/128, MM/64), 256, SM_MMA_64>>>(att16, wo16, px1,
        MM, Cc, Cc, Cc, Cc, Cc, Cc, x, nullptr, nullptr, nullptr);

    // ---- channel mixing ----
    ln_kernel<<<MM, 256>>>(px1, ln2_w, ln2_b, ph, 1e-5f);
    shift2_kernel<<<ELT_BLOCKS, 256>>>(cm_maa);
    gemm_ffn1<<<dim3(NF1/128, MM/128), 256, SM_MMA_128>>>(xk216, xr216, wffn1,
        kf16, psig, Ff/128);
    gemm_mma<TC_CVMIX,64><<<dim3(Cc/128, MM/64), 256, SM_MMA_64>>>(kf16, wcv16, out,
        MM, Cc, Ff, Ff, Ff, Cc, Cc, px1, psig, nullptr, nullptr);
}

// round 13
// speedup vs baseline: 1.0148x; 1.0148x over previous
#include <cuda_runtime.h>
#include <cuda_fp16.h>
#include <math.h>

// ---------------- problem constants ----------------
#define Bq 2
#define Tt 2048
#define Cc 2048
#define Hh 32
#define Nn 64
#define Ff 7168
#define MM (Bq*Tt)          // 4096 tokens
#define NF1 (Ff + Cc)       // 9216 rows in merged [Wck^T ; Wcr^T] buffer
#define CH 16               // scan chunks
#define CL (Tt/CH)          // 128 steps per chunk
#define LDA_A 320           // padded a16 row stride

typedef unsigned int u32;
typedef unsigned long long u64;

// ---------------- device scratch (no allocs allowed) ----------------
__device__ float g_h  [(size_t)MM*Cc];
__device__ float g_xx [(size_t)MM*Cc];
__device__ float g_w  [(size_t)MM*Cc];
__device__ float g_wt [(size_t)MM*64];
__device__ float g_y  [(size_t)MM*Cc];
__device__ float g_x1 [(size_t)MM*Cc];
__device__ float g_sig[(size_t)MM*Cc];
__device__ float g_out4[(size_t)4*MM*Cc];   // r,k,v,g
__device__ float g_rq [(size_t)MM*Cc];      // r * cumdecay (scan phase A)
__device__ float g_P  [(size_t)64*CH*4096]; // chunk-final local states
__device__ float g_D  [(size_t)64*CH*64];   // chunk decay products
__device__ float g_S0 [(size_t)64*CH*4096]; // chunk initial states

// fp16 activations
__device__ __align__(16) __half g_a16  [(size_t)MM*LDA_A];  // tanh(xxx@maa_w1), padded
__device__ __align__(16) __half g_xxx16[(size_t)MM*Cc];
__device__ __align__(16) __half g_xw16 [(size_t)MM*Cc];
__device__ __align__(16) __half g_act4 [(size_t)4*MM*Cc];   // xr,xk,xv,xg
__device__ __align__(16) __half g_att16[(size_t)MM*Cc];
__device__ __align__(16) __half g_xk216[(size_t)MM*Cc];
__device__ __align__(16) __half g_xr216[(size_t)MM*Cc];
__device__ __align__(16) __half g_kf16 [(size_t)MM*Ff];

// fp16 transposed weights ([N,K] K-major)
__device__ __align__(16) __half g_W4_16 [(size_t)4*Cc*Cc];  // Wr,Wk,Wv,Wg
__device__ __align__(16) __half g_Wo16  [(size_t)Cc*Cc];
__device__ __align__(16) __half g_Wffn1 [(size_t)NF1*Cc];   // [Wck^T ; Wcr^T]
__device__ __align__(16) __half g_Wcv16 [(size_t)Ff*Cc];    // [2048,7168]
__device__ __align__(16) __half g_maaw1T[(size_t)256*Cc];   // padded [256,2048]
__device__ __align__(16) __half g_tdw1T [(size_t)128*Cc];   // padded [128,2048]
__device__ __align__(16) __half g_w2T   [(size_t)5*Cc*128]; // per-f [2048,128], cols>=32 zero

// ---------------- PTX helpers (baseline PTX; no sm_103a-only features) ----
__device__ __forceinline__ u32 smem_u32(const void* p){
    u32 a;
    asm("{ .reg .u64 t; cvta.to.shared.u64 t, %1; cvt.u32.u64 %0, t; }" : "=r"(a) : "l"(p));
    return a;
}
__device__ __forceinline__ void cp16(u32 s, const void* g){
    asm volatile("cp.async.cg.shared.global [%0], [%1], 16;" :: "r"(s), "l"(g) : "memory");
}
__device__ __forceinline__ void cp_commit(){
    asm volatile("cp.async.commit_group;" ::: "memory");
}
template<int NG> __device__ __forceinline__ void cp_wait(){
    asm volatile("cp.async.wait_group %0;" :: "n"(NG) : "memory");
}
__device__ __forceinline__ void ldsm4(u32* r, u32 a){
    asm volatile("ldmatrix.sync.aligned.m8n8.x4.shared.b16 {%0,%1,%2,%3}, [%4];"
        : "=r"(r[0]), "=r"(r[1]), "=r"(r[2]), "=r"(r[3]) : "r"(a));
}
__device__ __forceinline__ void hmma16(float* c, const u32* a, u32 b0, u32 b1){
    asm volatile(
        "mma.sync.aligned.m16n8k16.row.col.f32.f16.f16.f32 "
        "{%0,%1,%2,%3},{%4,%5,%6,%7},{%8,%9},{%0,%1,%2,%3};"
        : "+f"(c[0]), "+f"(c[1]), "+f"(c[2]), "+f"(c[3])
        : "r"(a[0]), "r"(a[1]), "r"(a[2]), "r"(a[3]), "r"(b0), "r"(b1));
}

// ---------------- fp16 HMMA GEMM body, templated tile-M ----------------
enum { TC_NONE=0, TC_SILU, TC_ADDX, TC_SIGM, TC_CVMIX, TC_TANH, TC_RELU2H,
       TC_TANH16, TC_MIX };

#define SM_MMA_128 (3*32768)   // 3 stages x (A 16K + B 16K)
#define SM_MMA_64  (3*24576)   // 3 stages x (A 8K  + B 16K)

template<int EPI, int TM>
__device__ __forceinline__
void mma_body(const __half* __restrict__ A16, const __half* __restrict__ B16,
              float* __restrict__ C, int M, int N, int K, int lda, int ldb,
              int ldc, int nvalid,
              const float* __restrict__ aux0, const float* __restrict__ aux1,
              const float* __restrict__ aux2, __half* __restrict__ Ch)
{
    constexpr int MI = TM / 32;             // warp m-subtiles of 16 rows
    constexpr u32 A_BYTES = (u32)TM * 128u;
    constexpr u32 STG = A_BYTES + 16384u;

    extern __shared__ char sm_dyn[];
    const u32 sb = smem_u32(sm_dyn);
    const int tid  = threadIdx.x;
    const int wid  = tid >> 5;
    const int lane = tid & 31;
    const int m0 = blockIdx.y * TM;
    const int n0 = blockIdx.x * 128;
    const int wm = (wid & 1) * (TM / 2);
    const int wn = (wid >> 1) * 32;

    const int col16 = tid & 7;
    const int lrow  = tid >> 3;             // 0..31
    const u32 soff  = (u32)(lrow * 128 + col16 * 16);
    const u32 swz   = soff ^ ((soff >> 3) & 0x70);
    const size_t rstep_a = (size_t)32 * lda * 2;
    const size_t rstep_b = (size_t)32 * ldb * 2;
    const char* gA = (const char*)A16 + ((size_t)(m0 + lrow) * lda + col16 * 8) * 2;
    const char* gB = (const char*)B16 + ((size_t)(n0 + lrow) * ldb + col16 * 8) * 2;

    auto load_stage = [&](int s){
        u32 base = sb + (u32)(s % 3) * STG + swz;
        size_t ko = (size_t)s * 128;        // 64 fp16 = 128B along K
        #pragma unroll
        for (int i = 0; i < TM/32; i++)
            cp16(base + i*4096u, gA + ko + i*rstep_a);
        #pragma unroll
        for (int i = 0; i < 4; i++)
            cp16(base + A_BYTES + i*4096u, gB + ko + i*rstep_b);
        cp_commit();
    };

    const u32 a_row = (u32)(wm + ((lane >> 3) & 1) * 8 + (lane & 7));
    const u32 a_kb  = (u32)((lane >> 4) * 16);
    const u32 b_row = (u32)(wn + (lane >> 4) * 8 + (lane & 7));
    const u32 b_kb  = (u32)(((lane >> 3) & 1) * 16);

    float acc[MI][4][4];
    #pragma unroll
    for (int mi = 0; mi < MI; mi++)
        #pragma unroll
        for (int ni = 0; ni < 4; ni++)
            #pragma unroll
            for (int q = 0; q < 4; q++) acc[mi][ni][q] = 0.f;

    auto compute_stage = [&](u32 base){
        #pragma unroll
        for (int kk = 0; kk < 4; kk++){
            u32 aa[MI][4], bb[2][4];
            #pragma unroll
            for (int mi = 0; mi < MI; mi++){
                u32 off = (a_row + mi*16u) * 128u + (u32)kk*32u + a_kb;
                off ^= (off >> 3) & 0x70;
                ldsm4(aa[mi], base + off);
            }
            #pragma unroll
            for (int nj = 0; nj < 2; nj++){
                u32 off = (b_row + nj*16u) * 128u + (u32)kk*32u + b_kb;
                off ^= (off >> 3) & 0x70;
                ldsm4(bb[nj], base + A_BYTES + off);
            }
            #pragma unroll
            for (int mi = 0; mi < MI; mi++)
                #pragma unroll
                for (int ni = 0; ni < 4; ni++){
                    const u32* pb = &bb[ni >> 1][(ni & 1) * 2];
                    hmma16(acc[mi][ni], aa[mi], pb[0], pb[1]);
                }
        }
    };

    const int NS = K >> 6;
    load_stage(0);
    load_stage(1);
    for (int s = 0; s < NS; s++){
        if (s + 1 < NS) cp_wait<1>(); else cp_wait<0>();
        __syncthreads();
        if (s + 2 < NS) load_stage(s + 2);
        compute_stage(sb + (u32)(s % 3) * STG);
    }

    #pragma unroll
    for (int mi = 0; mi < MI; mi++){
        #pragma unroll
        for (int ni = 0; ni < 4; ni++){
            const int n = n0 + wn + ni*8 + (lane & 3)*2;
            if (n >= nvalid) continue;
            #pragma unroll
            for (int half = 0; half < 2; half++){
                const int m = m0 + wm + mi*16 + (lane >> 2) + half*8;
                const size_t idx = (size_t)m * ldc + n;
                float v0 = acc[mi][ni][half*2 + 0];
                float v1 = acc[mi][ni][half*2 + 1];
                if (EPI == TC_RELU2H){
                    float r0 = v0 > 0.f ? v0 : 0.f;
                    float r1 = v1 > 0.f ? v1 : 0.f;
                    __half2 hp;
                    hp.x = __float2half_rn(r0 * r0);
                    hp.y = __float2half_rn(r1 * r1);
                    *reinterpret_cast<__half2*>(Ch + idx) = hp;
                    continue;
                }
                if (EPI == TC_TANH16){
                    __half2 hp;
                    hp.x = __float2half_rn(tanhf(v0));
                    hp.y = __float2half_rn(tanhf(v1));
                    *reinterpret_cast<__half2*>(Ch + idx) = hp;
                    continue;
                }
                if (EPI == TC_MIX){
                    float o0 = aux0[idx]     + aux1[idx]     * (aux2[n]     + v0);
                    float o1 = aux0[idx + 1] + aux1[idx + 1] * (aux2[n + 1] + v1);
                    __half2 hp;
                    hp.x = __float2half_rn(o0);
                    hp.y = __float2half_rn(o1);
                    *reinterpret_cast<__half2*>(Ch + idx) = hp;
                    continue;
                }
                if (EPI == TC_SILU){
                    v0 = v0 / (1.f + expf(-v0));
                    v1 = v1 / (1.f + expf(-v1));
                } else if (EPI == TC_TANH){
                    v0 = tanhf(v0); v1 = tanhf(v1);
                } else if (EPI == TC_ADDX){
                    v0 += aux0[idx]; v1 += aux0[idx + 1];
                } else if (EPI == TC_SIGM){
                    v0 = 1.f / (1.f + expf(-v0));
                    v1 = 1.f / (1.f + expf(-v1));
                } else if (EPI == TC_CVMIX){
                    v0 = aux0[idx]     + aux1[idx]     * v0;
                    v1 = aux0[idx + 1] + aux1[idx + 1] * v1;
                }
                float2 o; o.x = v0; o.y = v1;
                *reinterpret_cast<float2*>(C + idx) = o;
            }
        }
    }
}

template<int EPI, int TM>
__global__ __launch_bounds__(256, 2)
void gemm_mma(const __half* __restrict__ A16, const __half* __restrict__ B16,
              float* __restrict__ C, int M, int N, int K, int lda, int ldb,
              int ldc, int nvalid,
              const float* __restrict__ aux0, const float* __restrict__ aux1,
              const float* __restrict__ aux2, __half* __restrict__ Ch)
{
    mma_body<EPI, TM>(A16, B16, C, M, N, K, lda, ldb, ldc, nvalid,
                      aux0, aux1, aux2, Ch);
}

// mix GEMM: z = f in [0,5). A = a16 + f*32 (lda=320), B = w2T[f] (ldb=128, K=64).
__global__ __launch_bounds__(256, 2)
void gemm_mix(const __half* __restrict__ a16, const __half* __restrict__ w2T,
              const float* __restrict__ tm_maa,
              const float* __restrict__ h, const float* __restrict__ xx,
              __half* __restrict__ xw16, __half* __restrict__ a4)
{
    const int f = blockIdx.z;
    const int slot = (f == 1) ? 1 : (f == 2) ? 2 : (f == 3) ? 0 : 3;
    __half* Ch = (f == 0) ? xw16 : a4 + (size_t)slot * MM * Cc;
    mma_body<TC_MIX, 128>(a16 + f*32, w2T + (size_t)f * Cc * 128, nullptr,
                          MM, Cc, 64, LDA_A, 128, Cc, Cc,
                          h, xx, tm_maa + (size_t)(1 + f) * Cc, Ch);
}

// merged r/k/v/g + td GEMM: z=0..3 rkvg (z==3 silu); z==4: td tanh (x==0 only)
__global__ __launch_bounds__(256, 2)
void gemm_rkvg5(const __half* __restrict__ A4, const __half* __restrict__ W4,
                float* __restrict__ C4,
                const __half* __restrict__ xw16, const __half* __restrict__ tdT,
                float* __restrict__ wt)
{
    const int z = blockIdx.z;
    if (z == 4){
        if (blockIdx.x != 0) return;
        mma_body<TC_TANH, 128>(xw16, tdT, wt, MM, 128, Cc, Cc, Cc, 64, 64,
                               nullptr, nullptr, nullptr, nullptr);
        return;
    }
    const size_t ao = (size_t)z * MM * Cc;
    const size_t wo = (size_t)z * Cc * Cc;
    if (z == 3)
        mma_body<TC_SILU, 128>(A4 + ao, W4 + wo, C4 + ao, MM, Cc, Cc, Cc, Cc, Cc, Cc,
                               nullptr, nullptr, nullptr, nullptr);
    else
        mma_body<TC_NONE, 128>(A4 + ao, W4 + wo, C4 + ao, MM, Cc, Cc, Cc, Cc, Cc, Cc,
                               nullptr, nullptr, nullptr, nullptr);
}

// merged ffn1: grid (72, 32). Tiles [0,56): relu2(xk2@Wck)->kf16.
// Tiles [56,72): sigmoid(xr2@Wcr)->psig (bases shifted by -Ff to rebase n).
__global__ __launch_bounds__(256, 2)
void gemm_ffn1(const __half* __restrict__ xk2, const __half* __restrict__ xr2,
               const __half* __restrict__ Wf, __half* __restrict__ kf,
               float* __restrict__ sig, int split)
{
    if ((int)blockIdx.x < split){
        mma_body<TC_RELU2H, 128>(xk2, Wf, nullptr, MM, Ff, Cc, Cc, Cc, Ff, Ff,
                                 nullptr, nullptr, nullptr, kf);
    } else {
        mma_body<TC_SIGM, 128>(xr2, Wf, sig - Ff, MM, NF1, Cc, Cc, Cc, Cc, NF1,
                               nullptr, nullptr, nullptr, nullptr);
    }
}

// ---------------- merged weight prep: all transposes in one launch ----------
#define WT_TOTAL 54336
__global__ __launch_bounds__(256)
void wtrans_all(const float* __restrict__ Wr, const float* __restrict__ Wk,
                const float* __restrict__ Wv, const float* __restrict__ Wg,
                const float* __restrict__ Wo, const float* __restrict__ Wcr,
                const float* __restrict__ Wck, const float* __restrict__ Wcv,
                const float* __restrict__ maa_w1, const float* __restrict__ td_w1,
                const float* __restrict__ maa_w2,
                __half* __restrict__ T4, __half* __restrict__ To,
                __half* __restrict__ Tcr, __half* __restrict__ Tck,
                __half* __restrict__ Tcv, __half* __restrict__ TmaaT,
                __half* __restrict__ TtdT, __half* __restrict__ w2T)
{
    __shared__ float s[32][33];
    const int t = blockIdx.x;
    const int tx = threadIdx.x & 31, ty = threadIdx.x >> 5;

    if (t >= 54016){
        const int r = t - 54016;
        const int f = r >> 6;
        const int c0 = (r & 63) * 32;
        #pragma unroll
        for (int rr = 0; rr < 32; rr += 8)
            s[ty + rr][tx] = maa_w2[((size_t)f * 32 + ty + rr) * Cc + c0 + tx];
        __syncthreads();
        const int c = threadIdx.x >> 3;
        const int dseg = (threadIdx.x & 7) * 16;
        __half* outp = w2T + ((size_t)f * Cc + c0 + c) * 128 + dseg;
        #pragma unroll
        for (int dd = 0; dd < 16; dd += 2){
            int d0 = dseg + dd;
            __half2 hp;
            hp.x = __float2half_rn(d0     < 32 ? s[d0][c]     : 0.f);
            hp.y = __float2half_rn(d0 + 1 < 32 ? s[d0 + 1][c] : 0.f);
            *reinterpret_cast<__half2*>(outp + dd) = hp;
        }
        return;
    }

    const float* W; __half* T; int K, N, bx, by; bool pad = false;
    if (t < 24576){
        int z = t >> 12, r = t & 4095;
        W = (z==0)?Wr:(z==1)?Wk:(z==2)?Wv:(z==3)?Wg:(z==4)?Wo:Wcr;
        T = (z < 4) ? T4 + (size_t)z * Cc * Cc : (z == 4 ? To : Tcr);
        K = Cc; N = Cc; bx = r & 63; by = r >> 6;
    } else if (t < 38912){
        int r = t - 24576;
        W = Wck; T = Tck; K = Cc; N = Ff; bx = r % 224; by = r / 224;
    } else if (t < 53248){
        int r = t - 38912;
        W = Wcv; T = Tcv; K = Ff; N = Cc; bx = r & 63; by = r >> 6;
    } else if (t < 53760){
        int r = t - 53248;
        W = maa_w1; T = TmaaT; K = Cc; N = 160; pad = true; bx = r & 7; by = r >> 3;
    } else {
        int r = t - 53760;
        W = td_w1; T = TtdT; K = Cc; N = 64; pad = true; bx = r & 3; by = r >> 2;
    }

    const int n0 = bx * 32, k0 = by * 32;
    #pragma unroll
    for (int rr = 0; rr < 32; rr += 8){
        int n = n0 + tx;
        s[ty + rr][tx] = (!pad || n < N) ? W[(size_t)(k0 + ty + rr) * N + n] : 0.f;
    }
    __syncthreads();
    #pragma unroll
    for (int rr = 0; rr < 32; rr += 8)
        T[(size_t)(n0 + ty + rr) * K + k0 + tx] = __float2half_rn(s[tx][ty + rr]);
}

// ---------------- small SIMT fp32 GEMM (td_w2 only) ----------------
#define BMt 128
#define BNt 128
#define BKt 8
#define TMt 8
#define TNt 8
__global__ __launch_bounds__(256)
void gemm_addvec(const float* __restrict__ A, const float* __restrict__ Bm,
                 float* __restrict__ Cm, int M, int N, int K, int lda, int ldc,
                 const float* __restrict__ aux0)
{
    __shared__ float As[BKt][BMt];
    __shared__ float Bs[BKt][BNt];
    const int bm = blockIdx.y * BMt;
    const int bn = blockIdx.x * BNt;
    const int tid = threadIdx.x;
    const int tcol = tid & 15;
    const int trow = tid >> 4;
    const int a_row = tid >> 1;
    const int a_col = (tid & 1) * 4;
    const int b_row = tid >> 5;
    const int b_col = (tid & 31) * 4;

    float acc[TMt][TNt];
    #pragma unroll
    for (int i = 0; i < TMt; i++)
        #pragma unroll
        for (int j = 0; j < TNt; j++) acc[i][j] = 0.f;

    for (int k0 = 0; k0 < K; k0 += BKt) {
        float4 av = *reinterpret_cast<const float4*>(A + (size_t)(bm + a_row)*lda + k0 + a_col);
        As[a_col+0][a_row] = av.x;
        As[a_col+1][a_row] = av.y;
        As[a_col+2][a_row] = av.z;
        As[a_col+3][a_row] = av.w;
        *reinterpret_cast<float4*>(&Bs[b_row][b_col]) =
            *reinterpret_cast<const float4*>(Bm + (size_t)(k0 + b_row)*N + bn + b_col);
        __syncthreads();
        #pragma unroll
        for (int kk = 0; kk < BKt; kk++) {
            float regM[TMt], regN[TNt];
            *(float4*)&regM[0] = *(const float4*)&As[kk][trow*TMt];
            *(float4*)&regM[4] = *(const float4*)&As[kk][trow*TMt + 4];
            *(float4*)&regN[0] = *(const float4*)&Bs[kk][tcol*TNt];
            *(float4*)&regN[4] = *(const float4*)&Bs[kk][tcol*TNt + 4];
            #pragma unroll
            for (int i = 0; i < TMt; i++)
                #pragma unroll
                for (int j = 0; j < TNt; j++)
                    acc[i][j] = fmaf(regM[i], regN[j], acc[i][j]);
        }
        __syncthreads();
    }

    #pragma unroll
    for (int i = 0; i < TMt; i++) {
        int m = bm + trow*TMt + i;
        #pragma unroll
        for (int j = 0; j < TNt; j++) {
            int n = bn + tcol*TNt + j;
            Cm[(size_t)m * ldc + n] = aux0[n] + acc[i][j];
        }
    }
}

// ---------------- LayerNorm over C per token ----------------
__global__ __launch_bounds__(256)
void ln_kernel(const float* __restrict__ x, const float* __restrict__ w,
               const float* __restrict__ b, float* __restrict__ out, float eps)
{
    const size_t base = (size_t)blockIdx.x * Cc;
    float sum = 0.f, sq = 0.f;
    for (int c = threadIdx.x; c < Cc; c += 256) { float v = x[base + c]; sum += v; sq += v*v; }
    #pragma unroll
    for (int o = 16; o; o >>= 1) {
        sum += __shfl_xor_sync(0xffffffffu, sum, o);
        sq  += __shfl_xor_sync(0xffffffffu, sq,  o);
    }
    __shared__ float s1[8], s2[8];
    int wid = threadIdx.x >> 5, lane = threadIdx.x & 31;
    if (!lane) { s1[wid] = sum; s2[wid] = sq; }
    __syncthreads();
    if (threadIdx.x == 0) {
        float ts = 0.f, tq = 0.f;
        #pragma unroll
        for (int i = 0; i < 8; i++) { ts += s1[i]; tq += s2[i]; }
        float m = ts / (float)Cc;
        float var = tq / (float)Cc - m*m;
        s1[0] = m; s2[0] = rsqrtf(var + eps);
    }
    __syncthreads();
    float m = s1[0], rstd = s2[0];
    for (int c = threadIdx.x; c < Cc; c += 256)
        out[base + c] = (x[base + c] - m) * rstd * w[c] + b[c];
}

// ---------------- token shift + first mix -> fp16 ----------------
__global__ void shift1_kernel(const float* __restrict__ tm_maa)
{
    size_t idx = (size_t)blockIdx.x * 256 + threadIdx.x;
    int c  = (int)(idx % Cc);
    int tt = (int)(idx / Cc);
    int t  = tt % Tt;
    float hv = g_h[idx];
    float hp = t ? g_h[idx - Cc] : 0.f;
    float d = hp - hv;
    g_xx[idx] = d;
    g_xxx16[idx] = __float2half_rn(hv + d * tm_maa[c]);
}

// ---------------- token shift (channel mixing) -> fp16 ----------------
__global__ void shift2_kernel(const float* __restrict__ cm_maa)
{
    size_t idx = (size_t)blockIdx.x * 256 + threadIdx.x;
    int c  = (int)(idx % Cc);
    int tt = (int)(idx / Cc);
    int t  = tt % Tt;
    float hv = g_h[idx];
    float hp = t ? g_h[idx - Cc] : 0.f;
    float d = hp - hv;
    g_xk216[idx] = __float2half_rn(hv + d * cm_maa[c]);
    g_xr216[idx] = __float2half_rn(hv + d * cm_maa[Cc + c]);
}

// ---------------- WKV6 chunk-parallel scan ----------------
__global__ __launch_bounds__(256)
void wkv6_partA(const float* __restrict__ u,
                const float* __restrict__ rr, const float* __restrict__ kk,
                const float* __restrict__ vv, const float* __restrict__ ww,
                float* __restrict__ yy, float* __restrict__ rq,
                float* __restrict__ Pc, float* __restrict__ Dc)
{
    const int blk = blockIdx.x;
    const int bh = blk >> 4;
    const int ch = blk & (CH - 1);
    const int b = bh >> 5, hh = bh & 31;
    const int tid = threadIdx.x;
    const int j = tid & 63;
    const int ib = (tid >> 6) * 16;
    __shared__ float4 sv[64];
    __shared__ float  yp[256];
    float S[16];
    #pragma unroll
    for (int i = 0; i < 16; i++) S[i] = 0.f;
    size_t off = (size_t)b * Tt * Cc + (size_t)ch * CL * Cc + (size_t)hh * Nn;
    float ur = (tid < 64) ? u[hh * Nn + j] : 0.f;
    float cum = 1.f;

    float rn = 0.f, kn = 0.f, wn = 0.f, vn;
    if (tid < 64){ rn = rr[off + j]; kn = kk[off + j]; wn = ww[off + j]; }
    vn = vv[off + j];

    for (int t = 0; t < CL; t++) {
        float rc = rn, kc = kn, wc = wn, vc = vn;
        size_t offn = off + Cc;
        if (t + 1 < CL){
            if (tid < 64){ rn = rr[offn + j]; kn = kk[offn + j]; wn = ww[offn + j]; }
            vn = vv[offn + j];
        }
        if (tid < 64){
            float d = expf(-expf(wc));
            rq[off + j] = rc * cum;
            cum *= d;
            sv[j] = make_float4(rc, kc, ur * kc, d);
        }
        __syncthreads();
        float a0 = 0.f, a1 = 0.f;
        #pragma unroll
        for (int ii = 0; ii < 16; ii += 2) {
            float4 q0 = sv[ib + ii];
            float4 q1 = sv[ib + ii + 1];
            a0 = fmaf(q0.x, fmaf(q0.z, vc, S[ii]), a0);
            S[ii] = fmaf(S[ii], q0.w, q0.y * vc);
            a1 = fmaf(q1.x, fmaf(q1.z, vc, S[ii + 1]), a1);
            S[ii + 1] = fmaf(S[ii + 1], q1.w, q1.y * vc);
        }
        yp[tid] = a0 + a1;
        __syncthreads();
        if (tid < 64) yy[off + j] = yp[j] + yp[64 + j] + yp[128 + j] + yp[192 + j];
        off = offn;
    }
    const size_t pbase = ((size_t)bh * CH + ch) * 4096;
    #pragma unroll
    for (int ii = 0; ii < 16; ii++)
        Pc[pbase + (size_t)(ib + ii) * 64 + j] = S[ii];
    if (tid < 64) Dc[((size_t)bh * CH + ch) * 64 + j] = cum;
}

__global__ __launch_bounds__(256)
void wkv6_partB(const float* __restrict__ Pc, const float* __restrict__ Dc,
                float* __restrict__ S0)
{
    const int bh = blockIdx.x;
    const int tid = threadIdx.x;
    const int e0 = tid * 16;
    const int i  = e0 >> 6;
    float4 s[4];
    #pragma unroll
    for (int q = 0; q < 4; q++) s[q] = make_float4(0.f, 0.f, 0.f, 0.f);
    for (int ch = 0; ch < CH; ch++){
        const size_t base = ((size_t)bh * CH + ch) * 4096 + e0;
        #pragma unroll
        for (int q = 0; q < 4; q++)
            *reinterpret_cast<float4*>(&S0[base + q*4]) = s[q];
        const float d = Dc[((size_t)bh * CH + ch) * 64 + i];
        #pragma unroll
        for (int q = 0; q < 4; q++){
            float4 p = *reinterpret_cast<const float4*>(&Pc[base + q*4]);
            s[q].x = fmaf(s[q].x, d, p.x);
            s[q].y = fmaf(s[q].y, d, p.y);
            s[q].z = fmaf(s[q].z, d, p.z);
            s[q].w = fmaf(s[q].w, d, p.w);
        }
    }
}

__global__ __launch_bounds__(256)
void wkv6_partC(const float* __restrict__ rq, const float* __restrict__ S0,
                float* __restrict__ yy)
{
    const int x = blockIdx.x;
    const int half = x & 1;
    const int ch = (x >> 1) & (CH - 1);
    const int bh = x >> 5;
    if (ch == 0) return;
    const int b = bh >> 5, hh = bh & 31;
    __shared__ float sS0[64][68];
    __shared__ float sRq[64][68];
    const int tid = threadIdx.x;
    const size_t off = (size_t)b * Tt * Cc
                     + (size_t)(ch * CL + half * 64) * Cc + (size_t)hh * Nn;
    const size_t sbase = ((size_t)bh * CH + ch) * 4096;

    {
        const int e0 = tid * 16;
        const int r = e0 >> 6, c = e0 & 63;
        #pragma unroll
        for (int q = 0; q < 4; q++){
            float4 v = *reinterpret_cast<const float4*>(&S0[sbase + e0 + q*4]);
            *reinterpret_cast<float4*>(&sS0[r][c + q*4]) = v;
            float4 w = *reinterpret_cast<const float4*>(&rq[off + (size_t)r * Cc + c + q*4]);
            *reinterpret_cast<float4*>(&sRq[r][c + q*4]) = w;
        }
    }
    __syncthreads();

    const int tr = tid >> 2;
    const int jq = (tid & 3) * 16;
    float acc[16];
    #pragma unroll
    for (int q = 0; q < 16; q++) acc[q] = 0.f;
    #pragma unroll 4
    for (int i = 0; i < 64; i++){
        float rv = sRq[tr][i];
        #pragma unroll
        for (int q = 0; q < 16; q++)
            acc[q] = fmaf(rv, sS0[i][jq + q], acc[q]);
    }
    const size_t ybase = off + (size_t)tr * Cc + jq;
    #pragma unroll
    for (int q = 0; q < 16; q += 4){
        float4 y4 = *reinterpret_cast<float4*>(&yy[ybase + q]);
        y4.x += acc[q];     y4.y += acc[q + 1];
        y4.z += acc[q + 2]; y4.w += acc[q + 3];
        *reinterpret_cast<float4*>(&yy[ybase + q]) = y4;
    }
}

// ---------------- GroupNorm(H) * silu-gate -> att fp16 ----------------
__global__ __launch_bounds__(256)
void gnsilu_kernel(const float* __restrict__ lnw, const float* __restrict__ lnb,
                   const float* __restrict__ gg, const float* __restrict__ yy)
{
    int gw  = blockIdx.x * 8 + (threadIdx.x >> 5);
    int lane = threadIdx.x & 31;
    int t  = gw >> 5;
    int hh = gw & 31;
    size_t base = (size_t)t * Cc + (size_t)hh * Nn;
    float y0 = yy[base + lane], y1 = yy[base + 32 + lane];
    float sum = y0 + y1, sq = y0*y0 + y1*y1;
    #pragma unroll
    for (int o = 16; o; o >>= 1) {
        sum += __shfl_xor_sync(0xffffffffu, sum, o);
        sq  += __shfl_xor_sync(0xffffffffu, sq,  o);
    }
    float m = sum * (1.f / 64.f);
    float rstd = rsqrtf(sq * (1.f / 64.f) - m*m + 6.4e-4f);
    int ch = hh * Nn + lane;
    float gv0 = gg[base + lane], gv1 = gg[base + 32 + lane];
    float o0 = ((y0 - m) * rstd * lnw[ch]      + lnb[ch])      * gv0;
    float o1 = ((y1 - m) * rstd * lnw[ch + 32] + lnb[ch + 32]) * gv1;
    g_att16[base + lane]      = __float2half_rn(o0);
    g_att16[base + 32 + lane] = __float2half_rn(o1);
}

// ---------------- host launch (single stream) ----------------
#define SYMADDR(v, s) cudaGetSymbolAddress((void**)&v, s)

extern "C" void kernel_launch(void* const* d_in, const int* in_sizes, int n_in,
                              void* d_out, int out_size)
{
    (void)in_sizes; (void)n_in; (void)out_size;
    const float* x          = (const float*)d_in[0];
    const float* ln1_w      = (const float*)d_in[1];
    const float* ln1_b      = (const float*)d_in[2];
    const float* ln2_w      = (const float*)d_in[3];
    const float* ln2_b      = (const float*)d_in[4];
    const float* tm_maa     = (const float*)d_in[5];
    const float* maa_w1     = (const float*)d_in[6];
    const float* maa_w2     = (const float*)d_in[7];
    const float* time_decay = (const float*)d_in[8];
    const float* td_w1      = (const float*)d_in[9];
    const float* td_w2      = (const float*)d_in[10];
    const float* time_faaaa = (const float*)d_in[11];
    const float* Wr  = (const float*)d_in[12];
    const float* Wk  = (const float*)d_in[13];
    const float* Wv  = (const float*)d_in[14];
    const float* Wg  = (const float*)d_in[15];
    const float* Wo  = (const float*)d_in[16];
    const float* lnx_w = (const float*)d_in[17];
    const float* lnx_b = (const float*)d_in[18];
    const float* cm_maa = (const float*)d_in[19];
    const float* Wck = (const float*)d_in[20];
    const float* Wcr = (const float*)d_in[21];
    const float* Wcv = (const float*)d_in[22];
    float* out = (float*)d_out;

    float *ph, *pxx, *pw, *pwt, *py, *px1, *psig, *pout4, *prq, *pP, *pD, *pS0;
    SYMADDR(ph, g_h);   SYMADDR(pxx, g_xx);
    SYMADDR(pw, g_w);   SYMADDR(pwt, g_wt); SYMADDR(py, g_y);
    SYMADDR(px1, g_x1); SYMADDR(psig, g_sig); SYMADDR(pout4, g_out4);
    SYMADDR(prq, g_rq); SYMADDR(pP, g_P);   SYMADDR(pD, g_D);  SYMADDR(pS0, g_S0);

    __half *a16,*xxx16,*xw16,*a4,*att16,*xk216,*xr216,*kf16;
    SYMADDR(a16, g_a16);
    SYMADDR(xxx16, g_xxx16); SYMADDR(xw16, g_xw16);
    SYMADDR(a4, g_act4);     SYMADDR(att16, g_att16);
    SYMADDR(xk216, g_xk216); SYMADDR(xr216, g_xr216);
    SYMADDR(kf16, g_kf16);

    __half *w4,*wo16,*wffn1,*wcv16,*maaT,*tdT,*w2T;
    SYMADDR(w4, g_W4_16);    SYMADDR(wo16, g_Wo16);
    SYMADDR(wffn1, g_Wffn1); SYMADDR(wcv16, g_Wcv16);
    SYMADDR(maaT, g_maaw1T); SYMADDR(tdT, g_tdw1T);
    SYMADDR(w2T, g_w2T);

    cudaFuncSetAttribute((const void*)gemm_mma<TC_TANH16,64>, cudaFuncAttributeMaxDynamicSharedMemorySize, SM_MMA_64);
    cudaFuncSetAttribute((const void*)gemm_mma<TC_ADDX,128>,  cudaFuncAttributeMaxDynamicSharedMemorySize, SM_MMA_128);
    cudaFuncSetAttribute((const void*)gemm_mma<TC_CVMIX,128>, cudaFuncAttributeMaxDynamicSharedMemorySize, SM_MMA_128);
    cudaFuncSetAttribute((const void*)gemm_mix,               cudaFuncAttributeMaxDynamicSharedMemorySize, SM_MMA_128);
    cudaFuncSetAttribute((const void*)gemm_rkvg5,             cudaFuncAttributeMaxDynamicSharedMemorySize, SM_MMA_128);
    cudaFuncSetAttribute((const void*)gemm_ffn1,              cudaFuncAttributeMaxDynamicSharedMemorySize, SM_MMA_128);

    const int ELT_BLOCKS = (MM * Cc) / 256;

    // ---- weight prep: one launch ----
    wtrans_all<<<WT_TOTAL, 256>>>(Wr, Wk, Wv, Wg, Wo, Wcr, Wck, Wcv,
        maa_w1, td_w1, maa_w2,
        w4, wo16, wffn1 + (size_t)Ff * Cc, wffn1, wcv16, maaT, tdT, w2T);

    // ---- time mixing ----
    ln_kernel<<<MM, 256>>>(x, ln1_w, ln1_b, ph, 1e-5f);
    shift1_kernel<<<ELT_BLOCKS, 256>>>(tm_maa);
    gemm_mma<TC_TANH16,64><<<dim3(256/128, MM/64), 256, SM_MMA_64>>>(xxx16, maaT, nullptr,
        MM, 256, Cc, Cc, Cc, LDA_A, 192, nullptr, nullptr, nullptr, a16);
    gemm_mix<<<dim3(Cc/128, MM/128, 5), 256, SM_MMA_128>>>(a16, w2T, tm_maa,
        ph, pxx, xw16, a4);
    gemm_rkvg5<<<dim3(Cc/128, MM/128, 5), 256, SM_MMA_128>>>(a4, w4, pout4,
        xw16, tdT, pwt);
    gemm_addvec<<<dim3(Cc/128, MM/128), 256>>>(pwt, td_w2, pw, MM, Cc, 64, 64, Cc, time_decay);
    wkv6_partA<<<64 * CH, 256>>>(time_faaaa,
        pout4 + (size_t)0*MM*Cc, pout4 + (size_t)1*MM*Cc, pout4 + (size_t)2*MM*Cc,
        pw, py, prq, pP, pD);
    wkv6_partB<<<64, 256>>>(pP, pD, pS0);
    wkv6_partC<<<64 * CH * 2, 256>>>(prq, pS0, py);
    gnsilu_kernel<<<MM * Hh / 8, 256>>>(lnx_w, lnx_b, pout4 + (size_t)3*MM*Cc, py);
    gemm_mma<TC_ADDX,128><<<dim3(Cc/128, MM/128), 256, SM_MMA_128>>>(att16, wo16, px1,
        MM, Cc, Cc, Cc, Cc, Cc, Cc, x, nullptr, nullptr, nullptr);

    // ---- channel mixing ----
    ln_kernel<<<MM, 256>>>(px1, ln2_w, ln2_b, ph, 1e-5f);
    shift2_kernel<<<ELT_BLOCKS, 256>>>(cm_maa);
    gemm_ffn1<<<dim3(NF1/128, MM/128), 256, SM_MMA_128>>>(xk216, xr216, wffn1,
        kf16, psig, Ff/128);
    gemm_mma<TC_CVMIX,128><<<dim3(Cc/128, MM/128), 256, SM_MMA_128>>>(kf16, wcv16, out,
        MM, Cc, Ff, Ff, Ff, Cc, Cc, px1, psig, nullptr, nullptr);
}

// round 14
// speedup vs baseline: 1.0699x; 1.0542x over previous
#include <cuda_runtime.h>
#include <cuda_fp16.h>
#include <math.h>

// ---------------- problem constants ----------------
#define Bq 2
#define Tt 2048
#define Cc 2048
#define Hh 32
#define Nn 64
#define Ff 7168
#define MM (Bq*Tt)          // 4096 tokens
#define NF1 (Ff + Cc)       // 9216 rows in merged [Wck^T ; Wcr^T] buffer
#define CH 16               // scan chunks
#define CL (Tt/CH)          // 128 steps per chunk
#define LDA_A 320           // padded a16 row stride

typedef unsigned int u32;
typedef unsigned long long u64;

// ---------------- device scratch (no allocs allowed) ----------------
__device__ float g_h  [(size_t)MM*Cc];
__device__ float g_xx [(size_t)MM*Cc];
__device__ float g_w  [(size_t)MM*Cc];      // now holds decay d = exp(-exp(w))
__device__ float g_y  [(size_t)MM*Cc];
__device__ float g_x1 [(size_t)MM*Cc];
__device__ float g_sig[(size_t)MM*Cc];
__device__ float g_out4[(size_t)4*MM*Cc];   // r,k,v,g
__device__ float g_rq [(size_t)MM*Cc];      // r * cumdecay (scan phase A)
__device__ float g_P  [(size_t)64*CH*4096]; // chunk-final local states
__device__ float g_D  [(size_t)64*CH*64];   // chunk decay products
__device__ float g_S0 [(size_t)64*CH*4096]; // chunk initial states

// fp16 activations
__device__ __align__(16) __half g_a16  [(size_t)MM*LDA_A];  // tanh(xxx@maa_w1), padded
__device__ __align__(16) __half g_xxx16[(size_t)MM*Cc];
__device__ __align__(16) __half g_xw16 [(size_t)MM*Cc];
__device__ __align__(16) __half g_wt16 [(size_t)MM*64 + 256];
__device__ __align__(16) __half g_act4 [(size_t)4*MM*Cc];   // xr,xk,xv,xg
__device__ __align__(16) __half g_att16[(size_t)MM*Cc];
__device__ __align__(16) __half g_xk216[(size_t)MM*Cc];
__device__ __align__(16) __half g_xr216[(size_t)MM*Cc];
__device__ __align__(16) __half g_kf16 [(size_t)MM*Ff];

// fp16 transposed weights ([N,K] K-major)
__device__ __align__(16) __half g_W4_16 [(size_t)4*Cc*Cc];  // Wr,Wk,Wv,Wg
__device__ __align__(16) __half g_Wo16  [(size_t)Cc*Cc];
__device__ __align__(16) __half g_Wffn1 [(size_t)NF1*Cc];   // [Wck^T ; Wcr^T]
__device__ __align__(16) __half g_Wcv16 [(size_t)Ff*Cc];    // [2048,7168]
__device__ __align__(16) __half g_maaw1T[(size_t)256*Cc];   // padded [256,2048]
__device__ __align__(16) __half g_tdw1T [(size_t)128*Cc];   // padded [128,2048]
__device__ __align__(16) __half g_tdw2T [(size_t)Cc*64 + 256]; // [2048,64]
__device__ __align__(16) __half g_w2T   [(size_t)5*Cc*128]; // per-f [2048,128], cols>=32 zero

// ---------------- PTX helpers (baseline PTX; no sm_103a-only features) ----
__device__ __forceinline__ u32 smem_u32(const void* p){
    u32 a;
    asm("{ .reg .u64 t; cvta.to.shared.u64 t, %1; cvt.u32.u64 %0, t; }" : "=r"(a) : "l"(p));
    return a;
}
__device__ __forceinline__ void cp16(u32 s, const void* g){
    asm volatile("cp.async.cg.shared.global [%0], [%1], 16;" :: "r"(s), "l"(g) : "memory");
}
__device__ __forceinline__ void cp_commit(){
    asm volatile("cp.async.commit_group;" ::: "memory");
}
template<int NG> __device__ __forceinline__ void cp_wait(){
    asm volatile("cp.async.wait_group %0;" :: "n"(NG) : "memory");
}
__device__ __forceinline__ void ldsm4(u32* r, u32 a){
    asm volatile("ldmatrix.sync.aligned.m8n8.x4.shared.b16 {%0,%1,%2,%3}, [%4];"
        : "=r"(r[0]), "=r"(r[1]), "=r"(r[2]), "=r"(r[3]) : "r"(a));
}
__device__ __forceinline__ void hmma16(float* c, const u32* a, u32 b0, u32 b1){
    asm volatile(
        "mma.sync.aligned.m16n8k16.row.col.f32.f16.f16.f32 "
        "{%0,%1,%2,%3},{%4,%5,%6,%7},{%8,%9},{%0,%1,%2,%3};"
        : "+f"(c[0]), "+f"(c[1]), "+f"(c[2]), "+f"(c[3])
        : "r"(a[0]), "r"(a[1]), "r"(a[2]), "r"(a[3]), "r"(b0), "r"(b1));
}

// ---------------- fp16 HMMA GEMM body, templated tile-M ----------------
enum { TC_NONE=0, TC_SILU, TC_ADDX, TC_SIGM, TC_CVMIX, TC_RELU2H,
       TC_TANH16, TC_MIX, TC_DECAY };

#define SM_MMA_128 (3*32768)   // 3 stages x (A 16K + B 16K)
#define SM_MMA_64  (3*24576)   // 3 stages x (A 8K  + B 16K)

template<int EPI, int TM>
__device__ __forceinline__
void mma_body(const __half* __restrict__ A16, const __half* __restrict__ B16,
              float* __restrict__ C, int M, int N, int K, int lda, int ldb,
              int ldc, int nvalid,
              const float* __restrict__ aux0, const float* __restrict__ aux1,
              const float* __restrict__ aux2, __half* __restrict__ Ch)
{
    constexpr int MI = TM / 32;             // warp m-subtiles of 16 rows
    constexpr u32 A_BYTES = (u32)TM * 128u;
    constexpr u32 STG = A_BYTES + 16384u;

    extern __shared__ char sm_dyn[];
    const u32 sb = smem_u32(sm_dyn);
    const int tid  = threadIdx.x;
    const int wid  = tid >> 5;
    const int lane = tid & 31;
    const int m0 = blockIdx.y * TM;
    const int n0 = blockIdx.x * 128;
    const int wm = (wid & 1) * (TM / 2);
    const int wn = (wid >> 1) * 32;

    const int col16 = tid & 7;
    const int lrow  = tid >> 3;             // 0..31
    const u32 soff  = (u32)(lrow * 128 + col16 * 16);
    const u32 swz   = soff ^ ((soff >> 3) & 0x70);
    const size_t rstep_a = (size_t)32 * lda * 2;
    const size_t rstep_b = (size_t)32 * ldb * 2;
    const char* gA = (const char*)A16 + ((size_t)(m0 + lrow) * lda + col16 * 8) * 2;
    const char* gB = (const char*)B16 + ((size_t)(n0 + lrow) * ldb + col16 * 8) * 2;

    auto load_stage = [&](int s){
        u32 base = sb + (u32)(s % 3) * STG + swz;
        size_t ko = (size_t)s * 128;        // 64 fp16 = 128B along K
        #pragma unroll
        for (int i = 0; i < TM/32; i++)
            cp16(base + i*4096u, gA + ko + i*rstep_a);
        #pragma unroll
        for (int i = 0; i < 4; i++)
            cp16(base + A_BYTES + i*4096u, gB + ko + i*rstep_b);
        cp_commit();
    };

    const u32 a_row = (u32)(wm + ((lane >> 3) & 1) * 8 + (lane & 7));
    const u32 a_kb  = (u32)((lane >> 4) * 16);
    const u32 b_row = (u32)(wn + (lane >> 4) * 8 + (lane & 7));
    const u32 b_kb  = (u32)(((lane >> 3) & 1) * 16);

    float acc[MI][4][4];
    #pragma unroll
    for (int mi = 0; mi < MI; mi++)
        #pragma unroll
        for (int ni = 0; ni < 4; ni++)
            #pragma unroll
            for (int q = 0; q < 4; q++) acc[mi][ni][q] = 0.f;

    auto compute_stage = [&](u32 base){
        #pragma unroll
        for (int kk = 0; kk < 4; kk++){
            u32 aa[MI][4], bb[2][4];
            #pragma unroll
            for (int mi = 0; mi < MI; mi++){
                u32 off = (a_row + mi*16u) * 128u + (u32)kk*32u + a_kb;
                off ^= (off >> 3) & 0x70;
                ldsm4(aa[mi], base + off);
            }
            #pragma unroll
            for (int nj = 0; nj < 2; nj++){
                u32 off = (b_row + nj*16u) * 128u + (u32)kk*32u + b_kb;
                off ^= (off >> 3) & 0x70;
                ldsm4(bb[nj], base + A_BYTES + off);
            }
            #pragma unroll
            for (int mi = 0; mi < MI; mi++)
                #pragma unroll
                for (int ni = 0; ni < 4; ni++){
                    const u32* pb = &bb[ni >> 1][(ni & 1) * 2];
                    hmma16(acc[mi][ni], aa[mi], pb[0], pb[1]);
                }
        }
    };

    const int NS = K >> 6;
    load_stage(0);
    load_stage(1);
    for (int s = 0; s < NS; s++){
        if (s + 1 < NS) cp_wait<1>(); else cp_wait<0>();
        __syncthreads();
        if (s + 2 < NS) load_stage(s + 2);
        compute_stage(sb + (u32)(s % 3) * STG);
    }

    #pragma unroll
    for (int mi = 0; mi < MI; mi++){
        #pragma unroll
        for (int ni = 0; ni < 4; ni++){
            const int n = n0 + wn + ni*8 + (lane & 3)*2;
            if (n >= nvalid) continue;
            #pragma unroll
            for (int half = 0; half < 2; half++){
                const int m = m0 + wm + mi*16 + (lane >> 2) + half*8;
                const size_t idx = (size_t)m * ldc + n;
                float v0 = acc[mi][ni][half*2 + 0];
                float v1 = acc[mi][ni][half*2 + 1];
                if (EPI == TC_RELU2H){
                    float r0 = v0 > 0.f ? v0 : 0.f;
                    float r1 = v1 > 0.f ? v1 : 0.f;
                    __half2 hp;
                    hp.x = __float2half_rn(r0 * r0);
                    hp.y = __float2half_rn(r1 * r1);
                    *reinterpret_cast<__half2*>(Ch + idx) = hp;
                    continue;
                }
                if (EPI == TC_TANH16){
                    __half2 hp;
                    hp.x = __float2half_rn(tanhf(v0));
                    hp.y = __float2half_rn(tanhf(v1));
                    *reinterpret_cast<__half2*>(Ch + idx) = hp;
                    continue;
                }
                if (EPI == TC_MIX){
                    float o0 = aux0[idx]     + aux1[idx]     * (aux2[n]     + v0);
                    float o1 = aux0[idx + 1] + aux1[idx + 1] * (aux2[n + 1] + v1);
                    __half2 hp;
                    hp.x = __float2half_rn(o0);
                    hp.y = __float2half_rn(o1);
                    *reinterpret_cast<__half2*>(Ch + idx) = hp;
                    continue;
                }
                if (EPI == TC_DECAY){
                    v0 = expf(-expf(v0 + aux2[n]));
                    v1 = expf(-expf(v1 + aux2[n + 1]));
                } else if (EPI == TC_SILU){
                    v0 = v0 / (1.f + expf(-v0));
                    v1 = v1 / (1.f + expf(-v1));
                } else if (EPI == TC_ADDX){
                    v0 += aux0[idx]; v1 += aux0[idx + 1];
                } else if (EPI == TC_SIGM){
                    v0 = 1.f / (1.f + expf(-v0));
                    v1 = 1.f / (1.f + expf(-v1));
                } else if (EPI == TC_CVMIX){
                    v0 = aux0[idx]     + aux1[idx]     * v0;
                    v1 = aux0[idx + 1] + aux1[idx + 1] * v1;
                }
                float2 o; o.x = v0; o.y = v1;
                *reinterpret_cast<float2*>(C + idx) = o;
            }
        }
    }
}

template<int EPI, int TM>
__global__ __launch_bounds__(256, 2)
void gemm_mma(const __half* __restrict__ A16, const __half* __restrict__ B16,
              float* __restrict__ C, int M, int N, int K, int lda, int ldb,
              int ldc, int nvalid,
              const float* __restrict__ aux0, const float* __restrict__ aux1,
              const float* __restrict__ aux2, __half* __restrict__ Ch)
{
    mma_body<EPI, TM>(A16, B16, C, M, N, K, lda, ldb, ldc, nvalid,
                      aux0, aux1, aux2, Ch);
}

// mix GEMM: z = f in [0,5). A = a16 + f*32 (lda=320), B = w2T[f] (ldb=128, K=64).
__global__ __launch_bounds__(256, 2)
void gemm_mix(const __half* __restrict__ a16, const __half* __restrict__ w2T,
              const float* __restrict__ tm_maa,
              const float* __restrict__ h, const float* __restrict__ xx,
              __half* __restrict__ xw16, __half* __restrict__ a4)
{
    const int f = blockIdx.z;
    const int slot = (f == 1) ? 1 : (f == 2) ? 2 : (f == 3) ? 0 : 3;
    __half* Ch = (f == 0) ? xw16 : a4 + (size_t)slot * MM * Cc;
    mma_body<TC_MIX, 128>(a16 + f*32, w2T + (size_t)f * Cc * 128, nullptr,
                          MM, Cc, 64, LDA_A, 128, Cc, Cc,
                          h, xx, tm_maa + (size_t)(1 + f) * Cc, Ch);
}

// merged r/k/v/g + td GEMM: z=0..3 rkvg (z==3 silu); z==4: td tanh -> fp16 wt
__global__ __launch_bounds__(256, 2)
void gemm_rkvg5(const __half* __restrict__ A4, const __half* __restrict__ W4,
                float* __restrict__ C4,
                const __half* __restrict__ xw16, const __half* __restrict__ tdT,
                __half* __restrict__ wt16)
{
    const int z = blockIdx.z;
    if (z == 4){
        if (blockIdx.x != 0) return;
        mma_body<TC_TANH16, 128>(xw16, tdT, nullptr, MM, 128, Cc, Cc, Cc, 64, 64,
                                 nullptr, nullptr, nullptr, wt16);
        return;
    }
    const size_t ao = (size_t)z * MM * Cc;
    const size_t wo = (size_t)z * Cc * Cc;
    if (z == 3)
        mma_body<TC_SILU, 128>(A4 + ao, W4 + wo, C4 + ao, MM, Cc, Cc, Cc, Cc, Cc, Cc,
                               nullptr, nullptr, nullptr, nullptr);
    else
        mma_body<TC_NONE, 128>(A4 + ao, W4 + wo, C4 + ao, MM, Cc, Cc, Cc, Cc, Cc, Cc,
                               nullptr, nullptr, nullptr, nullptr);
}

// merged ffn1: grid (72, 32). Tiles [0,56): relu2(xk2@Wck)->kf16.
// Tiles [56,72): sigmoid(xr2@Wcr)->psig (bases shifted by -Ff to rebase n).
__global__ __launch_bounds__(256, 2)
void gemm_ffn1(const __half* __restrict__ xk2, const __half* __restrict__ xr2,
               const __half* __restrict__ Wf, __half* __restrict__ kf,
               float* __restrict__ sig, int split)
{
    if ((int)blockIdx.x < split){
        mma_body<TC_RELU2H, 128>(xk2, Wf, nullptr, MM, Ff, Cc, Cc, Cc, Ff, Ff,
                                 nullptr, nullptr, nullptr, kf);
    } else {
        mma_body<TC_SIGM, 128>(xr2, Wf, sig - Ff, MM, NF1, Cc, Cc, Cc, Cc, NF1,
                               nullptr, nullptr, nullptr, nullptr);
    }
}

// ---------------- merged weight prep: all transposes in one launch ----------
#define WT_TOTAL 54464
__global__ __launch_bounds__(256)
void wtrans_all(const float* __restrict__ Wr, const float* __restrict__ Wk,
                const float* __restrict__ Wv, const float* __restrict__ Wg,
                const float* __restrict__ Wo, const float* __restrict__ Wcr,
                const float* __restrict__ Wck, const float* __restrict__ Wcv,
                const float* __restrict__ maa_w1, const float* __restrict__ td_w1,
                const float* __restrict__ td_w2, const float* __restrict__ maa_w2,
                __half* __restrict__ T4, __half* __restrict__ To,
                __half* __restrict__ Tcr, __half* __restrict__ Tck,
                __half* __restrict__ Tcv, __half* __restrict__ TmaaT,
                __half* __restrict__ TtdT, __half* __restrict__ Ttd2,
                __half* __restrict__ w2T)
{
    __shared__ float s[32][33];
    const int t = blockIdx.x;
    const int tx = threadIdx.x & 31, ty = threadIdx.x >> 5;

    if (t >= 54016 && t < 54336){
        const int r = t - 54016;
        const int f = r >> 6;
        const int c0 = (r & 63) * 32;
        #pragma unroll
        for (int rr = 0; rr < 32; rr += 8)
            s[ty + rr][tx] = maa_w2[((size_t)f * 32 + ty + rr) * Cc + c0 + tx];
        __syncthreads();
        const int c = threadIdx.x >> 3;
        const int dseg = (threadIdx.x & 7) * 16;
        __half* outp = w2T + ((size_t)f * Cc + c0 + c) * 128 + dseg;
        #pragma unroll
        for (int dd = 0; dd < 16; dd += 2){
            int d0 = dseg + dd;
            __half2 hp;
            hp.x = __float2half_rn(d0     < 32 ? s[d0][c]     : 0.f);
            hp.y = __float2half_rn(d0 + 1 < 32 ? s[d0 + 1][c] : 0.f);
            *reinterpret_cast<__half2*>(outp + dd) = hp;
        }
        return;
    }

    const float* W; __half* T; int K, N, bx, by; bool pad = false;
    if (t < 24576){
        int z = t >> 12, r = t & 4095;
        W = (z==0)?Wr:(z==1)?Wk:(z==2)?Wv:(z==3)?Wg:(z==4)?Wo:Wcr;
        T = (z < 4) ? T4 + (size_t)z * Cc * Cc : (z == 4 ? To : Tcr);
        K = Cc; N = Cc; bx = r & 63; by = r >> 6;
    } else if (t < 38912){
        int r = t - 24576;
        W = Wck; T = Tck; K = Cc; N = Ff; bx = r % 224; by = r / 224;
    } else if (t < 53248){
        int r = t - 38912;
        W = Wcv; T = Tcv; K = Ff; N = Cc; bx = r & 63; by = r >> 6;
    } else if (t < 53760){
        int r = t - 53248;
        W = maa_w1; T = TmaaT; K = Cc; N = 160; pad = true; bx = r & 7; by = r >> 3;
    } else if (t < 54016){
        int r = t - 53760;
        W = td_w1; T = TtdT; K = Cc; N = 64; pad = true; bx = r & 3; by = r >> 2;
    } else {
        int r = t - 54336;                      // [0,128): td_w2 [64,2048] -> [2048,64]
        W = td_w2; T = Ttd2; K = 64; N = Cc; bx = r & 63; by = r >> 6;
    }

    const int n0 = bx * 32, k0 = by * 32;
    #pragma unroll
    for (int rr = 0; rr < 32; rr += 8){
        int n = n0 + tx;
        s[ty + rr][tx] = (!pad || n < N) ? W[(size_t)(k0 + ty + rr) * N + n] : 0.f;
    }
    __syncthreads();
    #pragma unroll
    for (int rr = 0; rr < 32; rr += 8)
        T[(size_t)(n0 + ty + rr) * K + k0 + tx] = __float2half_rn(s[tx][ty + rr]);
}

// ---------------- fused LN + token-shift (time mixing) ----------------
// One block per token: LN(x_t) and LN(x_{t-1}) computed in-block.
// Outputs: g_h (needed by gemm_mix), g_xx, g_xxx16.
__global__ __launch_bounds__(256)
void lnshift1_kernel(const float* __restrict__ x, const float* __restrict__ w,
                     const float* __restrict__ b, const float* __restrict__ tm_maa)
{
    const int token = blockIdx.x;
    const int t = token % Tt;
    const size_t base = (size_t)token * Cc;
    const int tid = threadIdx.x;

    float cur[8], prv[8];
    float sA = 0.f, qA = 0.f, sB = 0.f, qB = 0.f;
    #pragma unroll
    for (int k = 0; k < 8; k++){
        int c = k * 256 + tid;
        float v = x[base + c];
        cur[k] = v; sA += v; qA += v * v;
        float p = (t > 0) ? x[base - Cc + c] : 0.f;
        prv[k] = p; sB += p; qB += p * p;
    }
    #pragma unroll
    for (int o = 16; o; o >>= 1){
        sA += __shfl_xor_sync(0xffffffffu, sA, o);
        qA += __shfl_xor_sync(0xffffffffu, qA, o);
        sB += __shfl_xor_sync(0xffffffffu, sB, o);
        qB += __shfl_xor_sync(0xffffffffu, qB, o);
    }
    __shared__ float r1[8], r2[8], r3[8], r4[8];
    int wid = tid >> 5, lane = tid & 31;
    if (!lane){ r1[wid] = sA; r2[wid] = qA; r3[wid] = sB; r4[wid] = qB; }
    __syncthreads();
    if (tid == 0){
        float a = 0.f, c2 = 0.f, d = 0.f, e = 0.f;
        #pragma unroll
        for (int i = 0; i < 8; i++){ a += r1[i]; c2 += r2[i]; d += r3[i]; e += r4[i]; }
        float mA = a / (float)Cc, mB = d / (float)Cc;
        r1[0] = mA; r2[0] = rsqrtf(c2 / (float)Cc - mA*mA + 1e-5f);
        r3[0] = mB; r4[0] = rsqrtf(e  / (float)Cc - mB*mB + 1e-5f);
    }
    __syncthreads();
    float mA = r1[0], rA = r2[0], mB = r3[0], rB = r4[0];
    #pragma unroll
    for (int k = 0; k < 8; k++){
        int c = k * 256 + tid;
        float hv = (cur[k] - mA) * rA * w[c] + b[c];
        float hp = (t > 0) ? (prv[k] - mB) * rB * w[c] + b[c] : 0.f;
        float d = hp - hv;
        g_h [base + c] = hv;
        g_xx[base + c] = d;
        g_xxx16[base + c] = __float2half_rn(hv + d * tm_maa[c]);
    }
}

// ---------------- fused LN + token-shift (channel mixing) ----------------
// h2/xx2 are not needed downstream — emit only xk2/xr2 fp16.
__global__ __launch_bounds__(256)
void lnshift2_kernel(const float* __restrict__ x, const float* __restrict__ w,
                     const float* __restrict__ b, const float* __restrict__ cm_maa)
{
    const int token = blockIdx.x;
    const int t = token % Tt;
    const size_t base = (size_t)token * Cc;
    const int tid = threadIdx.x;

    float cur[8], prv[8];
    float sA = 0.f, qA = 0.f, sB = 0.f, qB = 0.f;
    #pragma unroll
    for (int k = 0; k < 8; k++){
        int c = k * 256 + tid;
        float v = x[base + c];
        cur[k] = v; sA += v; qA += v * v;
        float p = (t > 0) ? x[base - Cc + c] : 0.f;
        prv[k] = p; sB += p; qB += p * p;
    }
    #pragma unroll
    for (int o = 16; o; o >>= 1){
        sA += __shfl_xor_sync(0xffffffffu, sA, o);
        qA += __shfl_xor_sync(0xffffffffu, qA, o);
        sB += __shfl_xor_sync(0xffffffffu, sB, o);
        qB += __shfl_xor_sync(0xffffffffu, qB, o);
    }
    __shared__ float r1[8], r2[8], r3[8], r4[8];
    int wid = tid >> 5, lane = tid & 31;
    if (!lane){ r1[wid] = sA; r2[wid] = qA; r3[wid] = sB; r4[wid] = qB; }
    __syncthreads();
    if (tid == 0){
        float a = 0.f, c2 = 0.f, d = 0.f, e = 0.f;
        #pragma unroll
        for (int i = 0; i < 8; i++){ a += r1[i]; c2 += r2[i]; d += r3[i]; e += r4[i]; }
        float mA = a / (float)Cc, mB = d / (float)Cc;
        r1[0] = mA; r2[0] = rsqrtf(c2 / (float)Cc - mA*mA + 1e-5f);
        r3[0] = mB; r4[0] = rsqrtf(e  / (float)Cc - mB*mB + 1e-5f);
    }
    __syncthreads();
    float mA = r1[0], rA = r2[0], mB = r3[0], rB = r4[0];
    #pragma unroll
    for (int k = 0; k < 8; k++){
        int c = k * 256 + tid;
        float hv = (cur[k] - mA) * rA * w[c] + b[c];
        float hp = (t > 0) ? (prv[k] - mB) * rB * w[c] + b[c] : 0.f;
        float d = hp - hv;
        g_xk216[base + c] = __float2half_rn(hv + d * cm_maa[c]);
        g_xr216[base + c] = __float2half_rn(hv + d * cm_maa[Cc + c]);
    }
}

// ---------------- WKV6 chunk-parallel scan (decay precomputed) ----------
__global__ __launch_bounds__(256)
void wkv6_partA(const float* __restrict__ u,
                const float* __restrict__ rr, const float* __restrict__ kk,
                const float* __restrict__ vv, const float* __restrict__ dd,
                float* __restrict__ yy, float* __restrict__ rq,
                float* __restrict__ Pc, float* __restrict__ Dc)
{
    const int blk = blockIdx.x;
    const int bh = blk >> 4;
    const int ch = blk & (CH - 1);
    const int b = bh >> 5, hh = bh & 31;
    const int tid = threadIdx.x;
    const int j = tid & 63;
    const int ib = (tid >> 6) * 16;
    __shared__ float4 sv[64];
    __shared__ float  yp[256];
    float S[16];
    #pragma unroll
    for (int i = 0; i < 16; i++) S[i] = 0.f;
    size_t off = (size_t)b * Tt * Cc + (size_t)ch * CL * Cc + (size_t)hh * Nn;
    float ur = (tid < 64) ? u[hh * Nn + j] : 0.f;
    float cum = 1.f;

    float rn = 0.f, kn = 0.f, dn = 0.f, vn;
    if (tid < 64){ rn = rr[off + j]; kn = kk[off + j]; dn = dd[off + j]; }
    vn = vv[off + j];

    for (int t = 0; t < CL; t++) {
        float rc = rn, kc = kn, dc = dn, vc = vn;
        size_t offn = off + Cc;
        if (t + 1 < CL){
            if (tid < 64){ rn = rr[offn + j]; kn = kk[offn + j]; dn = dd[offn + j]; }
            vn = vv[offn + j];
        }
        if (tid < 64){
            rq[off + j] = rc * cum;
            cum *= dc;
            sv[j] = make_float4(rc, kc, ur * kc, dc);
        }
        __syncthreads();
        float a0 = 0.f, a1 = 0.f;
        #pragma unroll
        for (int ii = 0; ii < 16; ii += 2) {
            float4 q0 = sv[ib + ii];
            float4 q1 = sv[ib + ii + 1];
            a0 = fmaf(q0.x, fmaf(q0.z, vc, S[ii]), a0);
            S[ii] = fmaf(S[ii], q0.w, q0.y * vc);
            a1 = fmaf(q1.x, fmaf(q1.z, vc, S[ii + 1]), a1);
            S[ii + 1] = fmaf(S[ii + 1], q1.w, q1.y * vc);
        }
        yp[tid] = a0 + a1;
        __syncthreads();
        if (tid < 64) yy[off + j] = yp[j] + yp[64 + j] + yp[128 + j] + yp[192 + j];
        off = offn;
    }
    const size_t pbase = ((size_t)bh * CH + ch) * 4096;
    #pragma unroll
    for (int ii = 0; ii < 16; ii++)
        Pc[pbase + (size_t)(ib + ii) * 64 + j] = S[ii];
    if (tid < 64) Dc[((size_t)bh * CH + ch) * 64 + j] = cum;
}

__global__ __launch_bounds__(256)
void wkv6_partB(const float* __restrict__ Pc, const float* __restrict__ Dc,
                float* __restrict__ S0)
{
    const int bh = blockIdx.x;
    const int tid = threadIdx.x;
    const int e0 = tid * 16;
    const int i  = e0 >> 6;
    float4 s[4];
    #pragma unroll
    for (int q = 0; q < 4; q++) s[q] = make_float4(0.f, 0.f, 0.f, 0.f);
    for (int ch = 0; ch < CH; ch++){
        const size_t base = ((size_t)bh * CH + ch) * 4096 + e0;
        #pragma unroll
        for (int q = 0; q < 4; q++)
            *reinterpret_cast<float4*>(&S0[base + q*4]) = s[q];
        const float d = Dc[((size_t)bh * CH + ch) * 64 + i];
        #pragma unroll
        for (int q = 0; q < 4; q++){
            float4 p = *reinterpret_cast<const float4*>(&Pc[base + q*4]);
            s[q].x = fmaf(s[q].x, d, p.x);
            s[q].y = fmaf(s[q].y, d, p.y);
            s[q].z = fmaf(s[q].z, d, p.z);
            s[q].w = fmaf(s[q].w, d, p.w);
        }
    }
}

__global__ __launch_bounds__(256)
void wkv6_partC(const float* __restrict__ rq, const float* __restrict__ S0,
                float* __restrict__ yy)
{
    const int x = blockIdx.x;
    const int half = x & 1;
    const int ch = (x >> 1) & (CH - 1);
    const int bh = x >> 5;
    if (ch == 0) return;
    const int b = bh >> 5, hh = bh & 31;
    __shared__ float sS0[64][68];
    __shared__ float sRq[64][68];
    const int tid = threadIdx.x;
    const size_t off = (size_t)b * Tt * Cc
                     + (size_t)(ch * CL + half * 64) * Cc + (size_t)hh * Nn;
    const size_t sbase = ((size_t)bh * CH + ch) * 4096;

    {
        const int e0 = tid * 16;
        const int r = e0 >> 6, c = e0 & 63;
        #pragma unroll
        for (int q = 0; q < 4; q++){
            float4 v = *reinterpret_cast<const float4*>(&S0[sbase + e0 + q*4]);
            *reinterpret_cast<float4*>(&sS0[r][c + q*4]) = v;
            float4 w = *reinterpret_cast<const float4*>(&rq[off + (size_t)r * Cc + c + q*4]);
            *reinterpret_cast<float4*>(&sRq[r][c + q*4]) = w;
        }
    }
    __syncthreads();

    const int tr = tid >> 2;
    const int jq = (tid & 3) * 16;
    float acc[16];
    #pragma unroll
    for (int q = 0; q < 16; q++) acc[q] = 0.f;
    #pragma unroll 4
    for (int i = 0; i < 64; i++){
        float rv = sRq[tr][i];
        #pragma unroll
        for (int q = 0; q < 16; q++)
            acc[q] = fmaf(rv, sS0[i][jq + q], acc[q]);
    }
    const size_t ybase = off + (size_t)tr * Cc + jq;
    #pragma unroll
    for (int q = 0; q < 16; q += 4){
        float4 y4 = *reinterpret_cast<float4*>(&yy[ybase + q]);
        y4.x += acc[q];     y4.y += acc[q + 1];
        y4.z += acc[q + 2]; y4.w += acc[q + 3];
        *reinterpret_cast<float4*>(&yy[ybase + q]) = y4;
    }
}

// ---------------- GroupNorm(H) * silu-gate -> att fp16 ----------------
__global__ __launch_bounds__(256)
void gnsilu_kernel(const float* __restrict__ lnw, const float* __restrict__ lnb,
                   const float* __restrict__ gg, const float* __restrict__ yy)
{
    int gw  = blockIdx.x * 8 + (threadIdx.x >> 5);
    int lane = threadIdx.x & 31;
    int t  = gw >> 5;
    int hh = gw & 31;
    size_t base = (size_t)t * Cc + (size_t)hh * Nn;
    float y0 = yy[base + lane], y1 = yy[base + 32 + lane];
    float sum = y0 + y1, sq = y0*y0 + y1*y1;
    #pragma unroll
    for (int o = 16; o; o >>= 1) {
        sum += __shfl_xor_sync(0xffffffffu, sum, o);
        sq  += __shfl_xor_sync(0xffffffffu, sq,  o);
    }
    float m = sum * (1.f / 64.f);
    float rstd = rsqrtf(sq * (1.f / 64.f) - m*m + 6.4e-4f);
    int ch = hh * Nn + lane;
    float gv0 = gg[base + lane], gv1 = gg[base + 32 + lane];
    float o0 = ((y0 - m) * rstd * lnw[ch]      + lnb[ch])      * gv0;
    float o1 = ((y1 - m) * rstd * lnw[ch + 32] + lnb[ch + 32]) * gv1;
    g_att16[base + lane]      = __float2half_rn(o0);
    g_att16[base + 32 + lane] = __float2half_rn(o1);
}

// ---------------- host launch (single stream) ----------------
#define SYMADDR(v, s) cudaGetSymbolAddress((void**)&v, s)

extern "C" void kernel_launch(void* const* d_in, const int* in_sizes, int n_in,
                              void* d_out, int out_size)
{
    (void)in_sizes; (void)n_in; (void)out_size;
    const float* x          = (const float*)d_in[0];
    const float* ln1_w      = (const float*)d_in[1];
    const float* ln1_b      = (const float*)d_in[2];
    const float* ln2_w      = (const float*)d_in[3];
    const float* ln2_b      = (const float*)d_in[4];
    const float* tm_maa     = (const float*)d_in[5];
    const float* maa_w1     = (const float*)d_in[6];
    const float* maa_w2     = (const float*)d_in[7];
    const float* time_decay = (const float*)d_in[8];
    const float* td_w1      = (const float*)d_in[9];
    const float* td_w2      = (const float*)d_in[10];
    const float* time_faaaa = (const float*)d_in[11];
    const float* Wr  = (const float*)d_in[12];
    const float* Wk  = (const float*)d_in[13];
    const float* Wv  = (const float*)d_in[14];
    const float* Wg  = (const float*)d_in[15];
    const float* Wo  = (const float*)d_in[16];
    const float* lnx_w = (const float*)d_in[17];
    const float* lnx_b = (const float*)d_in[18];
    const float* cm_maa = (const float*)d_in[19];
    const float* Wck = (const float*)d_in[20];
    const float* Wcr = (const float*)d_in[21];
    const float* Wcv = (const float*)d_in[22];
    float* out = (float*)d_out;

    float *ph, *pxx, *pw, *py, *px1, *psig, *pout4, *prq, *pP, *pD, *pS0;
    SYMADDR(ph, g_h);   SYMADDR(pxx, g_xx);
    SYMADDR(pw, g_w);   SYMADDR(py, g_y);
    SYMADDR(px1, g_x1); SYMADDR(psig, g_sig); SYMADDR(pout4, g_out4);
    SYMADDR(prq, g_rq); SYMADDR(pP, g_P);   SYMADDR(pD, g_D);  SYMADDR(pS0, g_S0);

    __half *a16,*xxx16,*xw16,*wt16,*a4,*att16,*xk216,*xr216,*kf16;
    SYMADDR(a16, g_a16);
    SYMADDR(xxx16, g_xxx16); SYMADDR(xw16, g_xw16);
    SYMADDR(wt16, g_wt16);
    SYMADDR(a4, g_act4);     SYMADDR(att16, g_att16);
    SYMADDR(xk216, g_xk216); SYMADDR(xr216, g_xr216);
    SYMADDR(kf16, g_kf16);

    __half *w4,*wo16,*wffn1,*wcv16,*maaT,*tdT,*td2T,*w2T;
    SYMADDR(w4, g_W4_16);    SYMADDR(wo16, g_Wo16);
    SYMADDR(wffn1, g_Wffn1); SYMADDR(wcv16, g_Wcv16);
    SYMADDR(maaT, g_maaw1T); SYMADDR(tdT, g_tdw1T);
    SYMADDR(td2T, g_tdw2T);  SYMADDR(w2T, g_w2T);

    cudaFuncSetAttribute((const void*)gemm_mma<TC_TANH16,64>, cudaFuncAttributeMaxDynamicSharedMemorySize, SM_MMA_64);
    cudaFuncSetAttribute((const void*)gemm_mma<TC_DECAY,128>, cudaFuncAttributeMaxDynamicSharedMemorySize, SM_MMA_128);
    cudaFuncSetAttribute((const void*)gemm_mma<TC_ADDX,128>,  cudaFuncAttributeMaxDynamicSharedMemorySize, SM_MMA_128);
    cudaFuncSetAttribute((const void*)gemm_mma<TC_CVMIX,128>, cudaFuncAttributeMaxDynamicSharedMemorySize, SM_MMA_128);
    cudaFuncSetAttribute((const void*)gemm_mix,               cudaFuncAttributeMaxDynamicSharedMemorySize, SM_MMA_128);
    cudaFuncSetAttribute((const void*)gemm_rkvg5,             cudaFuncAttributeMaxDynamicSharedMemorySize, SM_MMA_128);
    cudaFuncSetAttribute((const void*)gemm_ffn1,              cudaFuncAttributeMaxDynamicSharedMemorySize, SM_MMA_128);

    // ---- weight prep: one launch ----
    wtrans_all<<<WT_TOTAL, 256>>>(Wr, Wk, Wv, Wg, Wo, Wcr, Wck, Wcv,
        maa_w1, td_w1, td_w2, maa_w2,
        w4, wo16, wffn1 + (size_t)Ff * Cc, wffn1, wcv16, maaT, tdT, td2T, w2T);

    // ---- time mixing ----
    lnshift1_kernel<<<MM, 256>>>(x, ln1_w, ln1_b, tm_maa);
    gemm_mma<TC_TANH16,64><<<dim3(256/128, MM/64), 256, SM_MMA_64>>>(xxx16, maaT, nullptr,
        MM, 256, Cc, Cc, Cc, LDA_A, 192, nullptr, nullptr, nullptr, a16);
    gemm_mix<<<dim3(Cc/128, MM/128, 5), 256, SM_MMA_128>>>(a16, w2T, tm_maa,
        ph, pxx, xw16, a4);
    gemm_rkvg5<<<dim3(Cc/128, MM/128, 5), 256, SM_MMA_128>>>(a4, w4, pout4,
        xw16, tdT, wt16);
    gemm_mma<TC_DECAY,128><<<dim3(Cc/128, MM/128), 256, SM_MMA_128>>>(wt16, td2T, pw,
        MM, Cc, 64, 64, 64, Cc, Cc, nullptr, nullptr, time_decay, nullptr);
    wkv6_partA<<<64 * CH, 256>>>(time_faaaa,
        pout4 + (size_t)0*MM*Cc, pout4 + (size_t)1*MM*Cc, pout4 + (size_t)2*MM*Cc,
        pw, py, prq, pP, pD);
    wkv6_partB<<<64, 256>>>(pP, pD, pS0);
    wkv6_partC<<<64 * CH * 2, 256>>>(prq, pS0, py);
    gnsilu_kernel<<<MM * Hh / 8, 256>>>(lnx_w, lnx_b, pout4 + (size_t)3*MM*Cc, py);
    gemm_mma<TC_ADDX,128><<<dim3(Cc/128, MM/128), 256, SM_MMA_128>>>(att16, wo16, px1,
        MM, Cc, Cc, Cc, Cc, Cc, Cc, x, nullptr, nullptr, nullptr);

    // ---- channel mixing ----
    lnshift2_kernel<<<MM, 256>>>(px1, ln2_w, ln2_b, cm_maa);
    gemm_ffn1<<<dim3(NF1/128, MM/128), 256, SM_MMA_128>>>(xk216, xr216, wffn1,
        kf16, psig, Ff/128);
    gemm_mma<TC_CVMIX,128><<<dim3(Cc/128, MM/128), 256, SM_MMA_128>>>(kf16, wcv16, out,
        MM, Cc, Ff, Ff, Ff, Cc, Cc, px1, psig, nullptr, nullptr);
}

// round 15
// speedup vs baseline: 1.0962x; 1.0246x over previous
#include <cuda_runtime.h>
#include <cuda_fp16.h>
#include <math.h>

// ---------------- problem constants ----------------
#define Bq 2
#define Tt 2048
#define Cc 2048
#define Hh 32
#define Nn 64
#define Ff 7168
#define MM (Bq*Tt)          // 4096 tokens
#define NF1 (Ff + Cc)       // 9216 rows in merged [Wck^T ; Wcr^T] buffer
#define CH 16               // scan chunks
#define CL (Tt/CH)          // 128 steps per chunk
#define LDA_A 320           // padded a16 row stride

typedef unsigned int u32;
typedef unsigned long long u64;

// ---------------- device scratch (no allocs allowed) ----------------
__device__ float g_w  [(size_t)MM*Cc];      // decay d = exp(-exp(w))
__device__ float g_y  [(size_t)MM*Cc];
__device__ float g_x1 [(size_t)MM*Cc];
__device__ float g_sig[(size_t)MM*Cc];
__device__ float g_out4[(size_t)4*MM*Cc];   // r,k,v,g
__device__ float g_rq [(size_t)MM*Cc];      // r * cumdecay (scan phase A)
__device__ float g_P  [(size_t)64*CH*4096]; // chunk-final local states
__device__ float g_D  [(size_t)64*CH*64];   // chunk decay products
__device__ float g_S0 [(size_t)64*CH*4096]; // chunk initial states

// fp16 activations
__device__ __align__(16) __half g_h16  [(size_t)MM*Cc];     // LN1 output (mix epilogue only)
__device__ __align__(16) __half g_xx16 [(size_t)MM*Cc];     // token-shift delta
__device__ __align__(16) __half g_a16  [(size_t)MM*LDA_A];  // tanh(xxx@maa_w1), padded
__device__ __align__(16) __half g_xxx16[(size_t)MM*Cc];
__device__ __align__(16) __half g_xw16 [(size_t)MM*Cc];
__device__ __align__(16) __half g_wt16 [(size_t)MM*64 + 256];
__device__ __align__(16) __half g_act4 [(size_t)4*MM*Cc];   // xr,xk,xv,xg
__device__ __align__(16) __half g_att16[(size_t)MM*Cc];
__device__ __align__(16) __half g_xk216[(size_t)MM*Cc];
__device__ __align__(16) __half g_xr216[(size_t)MM*Cc];
__device__ __align__(16) __half g_kf16 [(size_t)MM*Ff];

// fp16 transposed weights ([N,K] K-major)
__device__ __align__(16) __half g_W4_16 [(size_t)4*Cc*Cc];  // Wr,Wk,Wv,Wg
__device__ __align__(16) __half g_Wo16  [(size_t)Cc*Cc];
__device__ __align__(16) __half g_Wffn1 [(size_t)NF1*Cc];   // [Wck^T ; Wcr^T]
__device__ __align__(16) __half g_Wcv16 [(size_t)Ff*Cc];    // [2048,7168]
__device__ __align__(16) __half g_maaw1T[(size_t)256*Cc];   // padded [256,2048]
__device__ __align__(16) __half g_tdw1T [(size_t)128*Cc];   // padded [128,2048]
__device__ __align__(16) __half g_tdw2T [(size_t)Cc*64 + 256]; // [2048,64]
__device__ __align__(16) __half g_w2T   [(size_t)5*Cc*128]; // per-f [2048,128], cols>=32 zero

// ---------------- PTX helpers (baseline PTX; no sm_103a-only features) ----
__device__ __forceinline__ u32 smem_u32(const void* p){
    u32 a;
    asm("{ .reg .u64 t; cvta.to.shared.u64 t, %1; cvt.u32.u64 %0, t; }" : "=r"(a) : "l"(p));
    return a;
}
__device__ __forceinline__ void cp16(u32 s, const void* g){
    asm volatile("cp.async.cg.shared.global [%0], [%1], 16;" :: "r"(s), "l"(g) : "memory");
}
__device__ __forceinline__ void cp_commit(){
    asm volatile("cp.async.commit_group;" ::: "memory");
}
template<int NG> __device__ __forceinline__ void cp_wait(){
    asm volatile("cp.async.wait_group %0;" :: "n"(NG) : "memory");
}
__device__ __forceinline__ void ldsm4(u32* r, u32 a){
    asm volatile("ldmatrix.sync.aligned.m8n8.x4.shared.b16 {%0,%1,%2,%3}, [%4];"
        : "=r"(r[0]), "=r"(r[1]), "=r"(r[2]), "=r"(r[3]) : "r"(a));
}
__device__ __forceinline__ void hmma16(float* c, const u32* a, u32 b0, u32 b1){
    asm volatile(
        "mma.sync.aligned.m16n8k16.row.col.f32.f16.f16.f32 "
        "{%0,%1,%2,%3},{%4,%5,%6,%7},{%8,%9},{%0,%1,%2,%3};"
        : "+f"(c[0]), "+f"(c[1]), "+f"(c[2]), "+f"(c[3])
        : "r"(a[0]), "r"(a[1]), "r"(a[2]), "r"(a[3]), "r"(b0), "r"(b1));
}

// ---------------- fp16 HMMA GEMM body, templated tile-M ----------------
enum { TC_NONE=0, TC_SILU, TC_ADDX, TC_SIGM, TC_CVMIX, TC_RELU2H,
       TC_TANH16, TC_MIX, TC_DECAY };

#define SM_MMA_128 (3*32768)   // 3 stages x (A 16K + B 16K)
#define SM_MMA_64  (3*24576)   // 3 stages x (A 8K  + B 16K)

template<int EPI, int TM>
__device__ __forceinline__
void mma_body(const __half* __restrict__ A16, const __half* __restrict__ B16,
              float* __restrict__ C, int M, int N, int K, int lda, int ldb,
              int ldc, int nvalid,
              const float* __restrict__ aux0, const float* __restrict__ aux1,
              const float* __restrict__ aux2, __half* __restrict__ Ch)
{
    constexpr int MI = TM / 32;             // warp m-subtiles of 16 rows
    constexpr u32 A_BYTES = (u32)TM * 128u;
    constexpr u32 STG = A_BYTES + 16384u;

    extern __shared__ char sm_dyn[];
    const u32 sb = smem_u32(sm_dyn);
    const int tid  = threadIdx.x;
    const int wid  = tid >> 5;
    const int lane = tid & 31;
    const int m0 = blockIdx.y * TM;
    const int n0 = blockIdx.x * 128;
    const int wm = (wid & 1) * (TM / 2);
    const int wn = (wid >> 1) * 32;

    const int col16 = tid & 7;
    const int lrow  = tid >> 3;             // 0..31
    const u32 soff  = (u32)(lrow * 128 + col16 * 16);
    const u32 swz   = soff ^ ((soff >> 3) & 0x70);
    const size_t rstep_a = (size_t)32 * lda * 2;
    const size_t rstep_b = (size_t)32 * ldb * 2;
    const char* gA = (const char*)A16 + ((size_t)(m0 + lrow) * lda + col16 * 8) * 2;
    const char* gB = (const char*)B16 + ((size_t)(n0 + lrow) * ldb + col16 * 8) * 2;

    auto load_stage = [&](int s){
        u32 base = sb + (u32)(s % 3) * STG + swz;
        size_t ko = (size_t)s * 128;        // 64 fp16 = 128B along K
        #pragma unroll
        for (int i = 0; i < TM/32; i++)
            cp16(base + i*4096u, gA + ko + i*rstep_a);
        #pragma unroll
        for (int i = 0; i < 4; i++)
            cp16(base + A_BYTES + i*4096u, gB + ko + i*rstep_b);
        cp_commit();
    };

    const u32 a_row = (u32)(wm + ((lane >> 3) & 1) * 8 + (lane & 7));
    const u32 a_kb  = (u32)((lane >> 4) * 16);
    const u32 b_row = (u32)(wn + (lane >> 4) * 8 + (lane & 7));
    const u32 b_kb  = (u32)(((lane >> 3) & 1) * 16);

    float acc[MI][4][4];
    #pragma unroll
    for (int mi = 0; mi < MI; mi++)
        #pragma unroll
        for (int ni = 0; ni < 4; ni++)
            #pragma unroll
            for (int q = 0; q < 4; q++) acc[mi][ni][q] = 0.f;

    auto compute_stage = [&](u32 base){
        #pragma unroll
        for (int kk = 0; kk < 4; kk++){
            u32 aa[MI][4], bb[2][4];
            #pragma unroll
            for (int mi = 0; mi < MI; mi++){
                u32 off = (a_row + mi*16u) * 128u + (u32)kk*32u + a_kb;
                off ^= (off >> 3) & 0x70;
                ldsm4(aa[mi], base + off);
            }
            #pragma unroll
            for (int nj = 0; nj < 2; nj++){
                u32 off = (b_row + nj*16u) * 128u + (u32)kk*32u + b_kb;
                off ^= (off >> 3) & 0x70;
                ldsm4(bb[nj], base + A_BYTES + off);
            }
            #pragma unroll
            for (int mi = 0; mi < MI; mi++)
                #pragma unroll
                for (int ni = 0; ni < 4; ni++){
                    const u32* pb = &bb[ni >> 1][(ni & 1) * 2];
                    hmma16(acc[mi][ni], aa[mi], pb[0], pb[1]);
                }
        }
    };

    const int NS = K >> 6;
    load_stage(0);
    load_stage(1);
    for (int s = 0; s < NS; s++){
        if (s + 1 < NS) cp_wait<1>(); else cp_wait<0>();
        __syncthreads();
        if (s + 2 < NS) load_stage(s + 2);
        compute_stage(sb + (u32)(s % 3) * STG);
    }

    #pragma unroll
    for (int mi = 0; mi < MI; mi++){
        #pragma unroll
        for (int ni = 0; ni < 4; ni++){
            const int n = n0 + wn + ni*8 + (lane & 3)*2;
            if (n >= nvalid) continue;
            #pragma unroll
            for (int half = 0; half < 2; half++){
                const int m = m0 + wm + mi*16 + (lane >> 2) + half*8;
                const size_t idx = (size_t)m * ldc + n;
                float v0 = acc[mi][ni][half*2 + 0];
                float v1 = acc[mi][ni][half*2 + 1];
                if (EPI == TC_RELU2H){
                    float r0 = v0 > 0.f ? v0 : 0.f;
                    float r1 = v1 > 0.f ? v1 : 0.f;
                    __half2 hp;
                    hp.x = __float2half_rn(r0 * r0);
                    hp.y = __float2half_rn(r1 * r1);
                    *reinterpret_cast<__half2*>(Ch + idx) = hp;
                    continue;
                }
                if (EPI == TC_TANH16){
                    __half2 hp;
                    hp.x = __float2half_rn(tanhf(v0));
                    hp.y = __float2half_rn(tanhf(v1));
                    *reinterpret_cast<__half2*>(Ch + idx) = hp;
                    continue;
                }
                if (EPI == TC_MIX){
                    // aux0/aux1 carry fp16 h/xx (halved epilogue traffic)
                    const __half2 hh = *reinterpret_cast<const __half2*>(
                        reinterpret_cast<const __half*>(aux0) + idx);
                    const __half2 xv = *reinterpret_cast<const __half2*>(
                        reinterpret_cast<const __half*>(aux1) + idx);
                    float o0 = __half2float(hh.x) + __half2float(xv.x) * (aux2[n]     + v0);
                    float o1 = __half2float(hh.y) + __half2float(xv.y) * (aux2[n + 1] + v1);
                    __half2 hp;
                    hp.x = __float2half_rn(o0);
                    hp.y = __float2half_rn(o1);
                    *reinterpret_cast<__half2*>(Ch + idx) = hp;
                    continue;
                }
                if (EPI == TC_DECAY){
                    v0 = expf(-expf(v0 + aux2[n]));
                    v1 = expf(-expf(v1 + aux2[n + 1]));
                } else if (EPI == TC_SILU){
                    v0 = v0 / (1.f + expf(-v0));
                    v1 = v1 / (1.f + expf(-v1));
                } else if (EPI == TC_ADDX){
                    v0 += aux0[idx]; v1 += aux0[idx + 1];
                } else if (EPI == TC_SIGM){
                    v0 = 1.f / (1.f + expf(-v0));
                    v1 = 1.f / (1.f + expf(-v1));
                } else if (EPI == TC_CVMIX){
                    v0 = aux0[idx]     + aux1[idx]     * v0;
                    v1 = aux0[idx + 1] + aux1[idx + 1] * v1;
                }
                float2 o; o.x = v0; o.y = v1;
                *reinterpret_cast<float2*>(C + idx) = o;
            }
        }
    }
}

template<int EPI, int TM>
__global__ __launch_bounds__(256, 2)
void gemm_mma(const __half* __restrict__ A16, const __half* __restrict__ B16,
              float* __restrict__ C, int M, int N, int K, int lda, int ldb,
              int ldc, int nvalid,
              const float* __restrict__ aux0, const float* __restrict__ aux1,
              const float* __restrict__ aux2, __half* __restrict__ Ch)
{
    mma_body<EPI, TM>(A16, B16, C, M, N, K, lda, ldb, ldc, nvalid,
                      aux0, aux1, aux2, Ch);
}

// mix GEMM: z = f in [0,5). A = a16 + f*32 (lda=320), B = w2T[f] (ldb=128, K=64).
__global__ __launch_bounds__(256, 2)
void gemm_mix(const __half* __restrict__ a16, const __half* __restrict__ w2T,
              const float* __restrict__ tm_maa,
              const __half* __restrict__ h16, const __half* __restrict__ xx16,
              __half* __restrict__ xw16, __half* __restrict__ a4)
{
    const int f = blockIdx.z;
    const int slot = (f == 1) ? 1 : (f == 2) ? 2 : (f == 3) ? 0 : 3;
    __half* Ch = (f == 0) ? xw16 : a4 + (size_t)slot * MM * Cc;
    mma_body<TC_MIX, 128>(a16 + f*32, w2T + (size_t)f * Cc * 128, nullptr,
                          MM, Cc, 64, LDA_A, 128, Cc, Cc,
                          reinterpret_cast<const float*>(h16),
                          reinterpret_cast<const float*>(xx16),
                          tm_maa + (size_t)(1 + f) * Cc, Ch);
}

// merged r/k/v/g + td GEMM: z=0..3 rkvg (z==3 silu); z==4: td tanh -> fp16 wt
__global__ __launch_bounds__(256, 2)
void gemm_rkvg5(const __half* __restrict__ A4, const __half* __restrict__ W4,
                float* __restrict__ C4,
                const __half* __restrict__ xw16, const __half* __restrict__ tdT,
                __half* __restrict__ wt16)
{
    const int z = blockIdx.z;
    if (z == 4){
        if (blockIdx.x != 0) return;
        mma_body<TC_TANH16, 128>(xw16, tdT, nullptr, MM, 128, Cc, Cc, Cc, 64, 64,
                                 nullptr, nullptr, nullptr, wt16);
        return;
    }
    const size_t ao = (size_t)z * MM * Cc;
    const size_t wo = (size_t)z * Cc * Cc;
    if (z == 3)
        mma_body<TC_SILU, 128>(A4 + ao, W4 + wo, C4 + ao, MM, Cc, Cc, Cc, Cc, Cc, Cc,
                               nullptr, nullptr, nullptr, nullptr);
    else
        mma_body<TC_NONE, 128>(A4 + ao, W4 + wo, C4 + ao, MM, Cc, Cc, Cc, Cc, Cc, Cc,
                               nullptr, nullptr, nullptr, nullptr);
}

// merged ffn1: grid (72, 32). Tiles [0,56): relu2(xk2@Wck)->kf16.
// Tiles [56,72): sigmoid(xr2@Wcr)->psig (bases shifted by -Ff to rebase n).
__global__ __launch_bounds__(256, 2)
void gemm_ffn1(const __half* __restrict__ xk2, const __half* __restrict__ xr2,
               const __half* __restrict__ Wf, __half* __restrict__ kf,
               float* __restrict__ sig, int split)
{
    if ((int)blockIdx.x < split){
        mma_body<TC_RELU2H, 128>(xk2, Wf, nullptr, MM, Ff, Cc, Cc, Cc, Ff, Ff,
                                 nullptr, nullptr, nullptr, kf);
    } else {
        mma_body<TC_SIGM, 128>(xr2, Wf, sig - Ff, MM, NF1, Cc, Cc, Cc, Cc, NF1,
                               nullptr, nullptr, nullptr, nullptr);
    }
}

// ---------------- merged weight prep: all transposes in one launch ----------
#define WT_TOTAL 54464
__global__ __launch_bounds__(256)
void wtrans_all(const float* __restrict__ Wr, const float* __restrict__ Wk,
                const float* __restrict__ Wv, const float* __restrict__ Wg,
                const float* __restrict__ Wo, const float* __restrict__ Wcr,
                const float* __restrict__ Wck, const float* __restrict__ Wcv,
                const float* __restrict__ maa_w1, const float* __restrict__ td_w1,
                const float* __restrict__ td_w2, const float* __restrict__ maa_w2,
                __half* __restrict__ T4, __half* __restrict__ To,
                __half* __restrict__ Tcr, __half* __restrict__ Tck,
                __half* __restrict__ Tcv, __half* __restrict__ TmaaT,
                __half* __restrict__ TtdT, __half* __restrict__ Ttd2,
                __half* __restrict__ w2T)
{
    __shared__ float s[32][33];
    const int t = blockIdx.x;
    const int tx = threadIdx.x & 31, ty = threadIdx.x >> 5;

    if (t >= 54016 && t < 54336){
        const int r = t - 54016;
        const int f = r >> 6;
        const int c0 = (r & 63) * 32;
        #pragma unroll
        for (int rr = 0; rr < 32; rr += 8)
            s[ty + rr][tx] = maa_w2[((size_t)f * 32 + ty + rr) * Cc + c0 + tx];
        __syncthreads();
        const int c = threadIdx.x >> 3;
        const int dseg = (threadIdx.x & 7) * 16;
        __half* outp = w2T + ((size_t)f * Cc + c0 + c) * 128 + dseg;
        #pragma unroll
        for (int dd = 0; dd < 16; dd += 2){
            int d0 = dseg + dd;
            __half2 hp;
            hp.x = __float2half_rn(d0     < 32 ? s[d0][c]     : 0.f);
            hp.y = __float2half_rn(d0 + 1 < 32 ? s[d0 + 1][c] : 0.f);
            *reinterpret_cast<__half2*>(outp + dd) = hp;
        }
        return;
    }

    const float* W; __half* T; int K, N, bx, by; bool pad = false;
    if (t < 24576){
        int z = t >> 12, r = t & 4095;
        W = (z==0)?Wr:(z==1)?Wk:(z==2)?Wv:(z==3)?Wg:(z==4)?Wo:Wcr;
        T = (z < 4) ? T4 + (size_t)z * Cc * Cc : (z == 4 ? To : Tcr);
        K = Cc; N = Cc; bx = r & 63; by = r >> 6;
    } else if (t < 38912){
        int r = t - 24576;
        W = Wck; T = Tck; K = Cc; N = Ff; bx = r % 224; by = r / 224;
    } else if (t < 53248){
        int r = t - 38912;
        W = Wcv; T = Tcv; K = Ff; N = Cc; bx = r & 63; by = r >> 6;
    } else if (t < 53760){
        int r = t - 53248;
        W = maa_w1; T = TmaaT; K = Cc; N = 160; pad = true; bx = r & 7; by = r >> 3;
    } else if (t < 54016){
        int r = t - 53760;
        W = td_w1; T = TtdT; K = Cc; N = 64; pad = true; bx = r & 3; by = r >> 2;
    } else {
        int r = t - 54336;                      // [0,128): td_w2 [64,2048] -> [2048,64]
        W = td_w2; T = Ttd2; K = 64; N = Cc; bx = r & 63; by = r >> 6;
    }

    const int n0 = bx * 32, k0 = by * 32;
    #pragma unroll
    for (int rr = 0; rr < 32; rr += 8){
        int n = n0 + tx;
        s[ty + rr][tx] = (!pad || n < N) ? W[(size_t)(k0 + ty + rr) * N + n] : 0.f;
    }
    __syncthreads();
    #pragma unroll
    for (int rr = 0; rr < 32; rr += 8)
        T[(size_t)(n0 + ty + rr) * K + k0 + tx] = __float2half_rn(s[tx][ty + rr]);
}

// ---------------- fused LN + token-shift (time mixing) ----------------
// Outputs: g_h16, g_xx16 (fp16, mix epilogue), g_xxx16.
__global__ __launch_bounds__(256)
void lnshift1_kernel(const float* __restrict__ x, const float* __restrict__ w,
                     const float* __restrict__ b, const float* __restrict__ tm_maa)
{
    const int token = blockIdx.x;
    const int t = token % Tt;
    const size_t base = (size_t)token * Cc;
    const int tid = threadIdx.x;

    float cur[8], prv[8];
    float sA = 0.f, qA = 0.f, sB = 0.f, qB = 0.f;
    #pragma unroll
    for (int k = 0; k < 8; k++){
        int c = k * 256 + tid;
        float v = x[base + c];
        cur[k] = v; sA += v; qA += v * v;
        float p = (t > 0) ? x[base - Cc + c] : 0.f;
        prv[k] = p; sB += p; qB += p * p;
    }
    #pragma unroll
    for (int o = 16; o; o >>= 1){
        sA += __shfl_xor_sync(0xffffffffu, sA, o);
        qA += __shfl_xor_sync(0xffffffffu, qA, o);
        sB += __shfl_xor_sync(0xffffffffu, sB, o);
        qB += __shfl_xor_sync(0xffffffffu, qB, o);
    }
    __shared__ float r1[8], r2[8], r3[8], r4[8];
    int wid = tid >> 5, lane = tid & 31;
    if (!lane){ r1[wid] = sA; r2[wid] = qA; r3[wid] = sB; r4[wid] = qB; }
    __syncthreads();
    if (tid == 0){
        float a = 0.f, c2 = 0.f, d = 0.f, e = 0.f;
        #pragma unroll
        for (int i = 0; i < 8; i++){ a += r1[i]; c2 += r2[i]; d += r3[i]; e += r4[i]; }
        float mA = a / (float)Cc, mB = d / (float)Cc;
        r1[0] = mA; r2[0] = rsqrtf(c2 / (float)Cc - mA*mA + 1e-5f);
        r3[0] = mB; r4[0] = rsqrtf(e  / (float)Cc - mB*mB + 1e-5f);
    }
    __syncthreads();
    float mA = r1[0], rA = r2[0], mB = r3[0], rB = r4[0];
    #pragma unroll
    for (int k = 0; k < 8; k++){
        int c = k * 256 + tid;
        float hv = (cur[k] - mA) * rA * w[c] + b[c];
        float hp = (t > 0) ? (prv[k] - mB) * rB * w[c] + b[c] : 0.f;
        float d = hp - hv;
        g_h16 [base + c] = __float2half_rn(hv);
        g_xx16[base + c] = __float2half_rn(d);
        g_xxx16[base + c] = __float2half_rn(hv + d * tm_maa[c]);
    }
}

// ---------------- fused LN + token-shift (channel mixing) ----------------
__global__ __launch_bounds__(256)
void lnshift2_kernel(const float* __restrict__ x, const float* __restrict__ w,
                     const float* __restrict__ b, const float* __restrict__ cm_maa)
{
    const int token = blockIdx.x;
    const int t = token % Tt;
    const size_t base = (size_t)token * Cc;
    const int tid = threadIdx.x;

    float cur[8], prv[8];
    float sA = 0.f, qA = 0.f, sB = 0.f, qB = 0.f;
    #pragma unroll
    for (int k = 0; k < 8; k++){
        int c = k * 256 + tid;
        float v = x[base + c];
        cur[k] = v; sA += v; qA += v * v;
        float p = (t > 0) ? x[base - Cc + c] : 0.f;
        prv[k] = p; sB += p; qB += p * p;
    }
    #pragma unroll
    for (int o = 16; o; o >>= 1){
        sA += __shfl_xor_sync(0xffffffffu, sA, o);
        qA += __shfl_xor_sync(0xffffffffu, qA, o);
        sB += __shfl_xor_sync(0xffffffffu, sB, o);
        qB += __shfl_xor_sync(0xffffffffu, qB, o);
    }
    __shared__ float r1[8], r2[8], r3[8], r4[8];
    int wid = tid >> 5, lane = tid & 31;
    if (!lane){ r1[wid] = sA; r2[wid] = qA; r3[wid] = sB; r4[wid] = qB; }
    __syncthreads();
    if (tid == 0){
        float a = 0.f, c2 = 0.f, d = 0.f, e = 0.f;
        #pragma unroll
        for (int i = 0; i < 8; i++){ a += r1[i]; c2 += r2[i]; d += r3[i]; e += r4[i]; }
        float mA = a / (float)Cc, mB = d / (float)Cc;
        r1[0] = mA; r2[0] = rsqrtf(c2 / (float)Cc - mA*mA + 1e-5f);
        r3[0] = mB; r4[0] = rsqrtf(e  / (float)Cc - mB*mB + 1e-5f);
    }
    __syncthreads();
    float mA = r1[0], rA = r2[0], mB = r3[0], rB = r4[0];
    #pragma unroll
    for (int k = 0; k < 8; k++){
        int c = k * 256 + tid;
        float hv = (cur[k] - mA) * rA * w[c] + b[c];
        float hp = (t > 0) ? (prv[k] - mB) * rB * w[c] + b[c] : 0.f;
        float d = hp - hv;
        g_xk216[base + c] = __float2half_rn(hv + d * cm_maa[c]);
        g_xr216[base + c] = __float2half_rn(hv + d * cm_maa[Cc + c]);
    }
}

// ---------------- WKV6 chunk-parallel scan (decay precomputed) ----------
__global__ __launch_bounds__(256)
void wkv6_partA(const float* __restrict__ u,
                const float* __restrict__ rr, const float* __restrict__ kk,
                const float* __restrict__ vv, const float* __restrict__ dd,
                float* __restrict__ yy, float* __restrict__ rq,
                float* __restrict__ Pc, float* __restrict__ Dc)
{
    const int blk = blockIdx.x;
    const int bh = blk >> 4;
    const int ch = blk & (CH - 1);
    const int b = bh >> 5, hh = bh & 31;
    const int tid = threadIdx.x;
    const int j = tid & 63;
    const int ib = (tid >> 6) * 16;
    __shared__ float4 sv[64];
    __shared__ float  yp[256];
    float S[16];
    #pragma unroll
    for (int i = 0; i < 16; i++) S[i] = 0.f;
    size_t off = (size_t)b * Tt * Cc + (size_t)ch * CL * Cc + (size_t)hh * Nn;
    float ur = (tid < 64) ? u[hh * Nn + j] : 0.f;
    float cum = 1.f;

    float rn = 0.f, kn = 0.f, dn = 0.f, vn;
    if (tid < 64){ rn = rr[off + j]; kn = kk[off + j]; dn = dd[off + j]; }
    vn = vv[off + j];

    for (int t = 0; t < CL; t++) {
        float rc = rn, kc = kn, dc = dn, vc = vn;
        size_t offn = off + Cc;
        if (t + 1 < CL){
            if (tid < 64){ rn = rr[offn + j]; kn = kk[offn + j]; dn = dd[offn + j]; }
            vn = vv[offn + j];
        }
        if (tid < 64){
            rq[off + j] = rc * cum;
            cum *= dc;
            sv[j] = make_float4(rc, kc, ur * kc, dc);
        }
        __syncthreads();
        float a0 = 0.f, a1 = 0.f;
        #pragma unroll
        for (int ii = 0; ii < 16; ii += 2) {
            float4 q0 = sv[ib + ii];
            float4 q1 = sv[ib + ii + 1];
            a0 = fmaf(q0.x, fmaf(q0.z, vc, S[ii]), a0);
            S[ii] = fmaf(S[ii], q0.w, q0.y * vc);
            a1 = fmaf(q1.x, fmaf(q1.z, vc, S[ii + 1]), a1);
            S[ii + 1] = fmaf(S[ii + 1], q1.w, q1.y * vc);
        }
        yp[tid] = a0 + a1;
        __syncthreads();
        if (tid < 64) yy[off + j] = yp[j] + yp[64 + j] + yp[128 + j] + yp[192 + j];
        off = offn;
    }
    const size_t pbase = ((size_t)bh * CH + ch) * 4096;
    #pragma unroll
    for (int ii = 0; ii < 16; ii++)
        Pc[pbase + (size_t)(ib + ii) * 64 + j] = S[ii];
    if (tid < 64) Dc[((size_t)bh * CH + ch) * 64 + j] = cum;
}

__global__ __launch_bounds__(256)
void wkv6_partB(const float* __restrict__ Pc, const float* __restrict__ Dc,
                float* __restrict__ S0)
{
    const int bh = blockIdx.x;
    const int tid = threadIdx.x;
    const int e0 = tid * 16;
    const int i  = e0 >> 6;
    float4 s[4];
    #pragma unroll
    for (int q = 0; q < 4; q++) s[q] = make_float4(0.f, 0.f, 0.f, 0.f);
    for (int ch = 0; ch < CH; ch++){
        const size_t base = ((size_t)bh * CH + ch) * 4096 + e0;
        #pragma unroll
        for (int q = 0; q < 4; q++)
            *reinterpret_cast<float4*>(&S0[base + q*4]) = s[q];
        const float d = Dc[((size_t)bh * CH + ch) * 64 + i];
        #pragma unroll
        for (int q = 0; q < 4; q++){
            float4 p = *reinterpret_cast<const float4*>(&Pc[base + q*4]);
            s[q].x = fmaf(s[q].x, d, p.x);
            s[q].y = fmaf(s[q].y, d, p.y);
            s[q].z = fmaf(s[q].z, d, p.z);
            s[q].w = fmaf(s[q].w, d, p.w);
        }
    }
}

__global__ __launch_bounds__(256)
void wkv6_partC(const float* __restrict__ rq, const float* __restrict__ S0,
                float* __restrict__ yy)
{
    const int x = blockIdx.x;
    const int half = x & 1;
    const int ch = (x >> 1) & (CH - 1);
    const int bh = x >> 5;
    if (ch == 0) return;
    const int b = bh >> 5, hh = bh & 31;
    __shared__ float sS0[64][68];
    __shared__ float sRq[64][68];
    const int tid = threadIdx.x;
    const size_t off = (size_t)b * Tt * Cc
                     + (size_t)(ch * CL + half * 64) * Cc + (size_t)hh * Nn;
    const size_t sbase = ((size_t)bh * CH + ch) * 4096;

    {
        const int e0 = tid * 16;
        const int r = e0 >> 6, c = e0 & 63;
        #pragma unroll
        for (int q = 0; q < 4; q++){
            float4 v = *reinterpret_cast<const float4*>(&S0[sbase + e0 + q*4]);
            *reinterpret_cast<float4*>(&sS0[r][c + q*4]) = v;
            float4 w = *reinterpret_cast<const float4*>(&rq[off + (size_t)r * Cc + c + q*4]);
            *reinterpret_cast<float4*>(&sRq[r][c + q*4]) = w;
        }
    }
    __syncthreads();

    const int tr = tid >> 2;
    const int jq = (tid & 3) * 16;
    float acc[16];
    #pragma unroll
    for (int q = 0; q < 16; q++) acc[q] = 0.f;
    #pragma unroll 4
    for (int i = 0; i < 64; i++){
        float rv = sRq[tr][i];
        #pragma unroll
        for (int q = 0; q < 16; q++)
            acc[q] = fmaf(rv, sS0[i][jq + q], acc[q]);
    }
    const size_t ybase = off + (size_t)tr * Cc + jq;
    #pragma unroll
    for (int q = 0; q < 16; q += 4){
        float4 y4 = *reinterpret_cast<float4*>(&yy[ybase + q]);
        y4.x += acc[q];     y4.y += acc[q + 1];
        y4.z += acc[q + 2]; y4.w += acc[q + 3];
        *reinterpret_cast<float4*>(&yy[ybase + q]) = y4;
    }
}

// ---------------- GroupNorm(H) * silu-gate -> att fp16 ----------------
__global__ __launch_bounds__(256)
void gnsilu_kernel(const float* __restrict__ lnw, const float* __restrict__ lnb,
                   const float* __restrict__ gg, const float* __restrict__ yy)
{
    int gw  = blockIdx.x * 8 + (threadIdx.x >> 5);
    int lane = threadIdx.x & 31;
    int t  = gw >> 5;
    int hh = gw & 31;
    size_t base = (size_t)t * Cc + (size_t)hh * Nn;
    float y0 = yy[base + lane], y1 = yy[base + 32 + lane];
    float sum = y0 + y1, sq = y0*y0 + y1*y1;
    #pragma unroll
    for (int o = 16; o; o >>= 1) {
        sum += __shfl_xor_sync(0xffffffffu, sum, o);
        sq  += __shfl_xor_sync(0xffffffffu, sq,  o);
    }
    float m = sum * (1.f / 64.f);
    float rstd = rsqrtf(sq * (1.f / 64.f) - m*m + 6.4e-4f);
    int ch = hh * Nn + lane;
    float gv0 = gg[base + lane], gv1 = gg[base + 32 + lane];
    float o0 = ((y0 - m) * rstd * lnw[ch]      + lnb[ch])      * gv0;
    float o1 = ((y1 - m) * rstd * lnw[ch + 32] + lnb[ch + 32]) * gv1;
    g_att16[base + lane]      = __float2half_rn(o0);
    g_att16[base + 32 + lane] = __float2half_rn(o1);
}

// ---------------- host launch (single stream) ----------------
#define SYMADDR(v, s) cudaGetSymbolAddress((void**)&v, s)

extern "C" void kernel_launch(void* const* d_in, const int* in_sizes, int n_in,
                              void* d_out, int out_size)
{
    (void)in_sizes; (void)n_in; (void)out_size;
    const float* x          = (const float*)d_in[0];
    const float* ln1_w      = (const float*)d_in[1];
    const float* ln1_b      = (const float*)d_in[2];
    const float* ln2_w      = (const float*)d_in[3];
    const float* ln2_b      = (const float*)d_in[4];
    const float* tm_maa     = (const float*)d_in[5];
    const float* maa_w1     = (const float*)d_in[6];
    const float* maa_w2     = (const float*)d_in[7];
    const float* time_decay = (const float*)d_in[8];
    const float* td_w1      = (const float*)d_in[9];
    const float* td_w2      = (const float*)d_in[10];
    const float* time_faaaa = (const float*)d_in[11];
    const float* Wr  = (const float*)d_in[12];
    const float* Wk  = (const float*)d_in[13];
    const float* Wv  = (const float*)d_in[14];
    const float* Wg  = (const float*)d_in[15];
    const float* Wo  = (const float*)d_in[16];
    const float* lnx_w = (const float*)d_in[17];
    const float* lnx_b = (const float*)d_in[18];
    const float* cm_maa = (const float*)d_in[19];
    const float* Wck = (const float*)d_in[20];
    const float* Wcr = (const float*)d_in[21];
    const float* Wcv = (const float*)d_in[22];
    float* out = (float*)d_out;

    float *pw, *py, *px1, *psig, *pout4, *prq, *pP, *pD, *pS0;
    SYMADDR(pw, g_w);   SYMADDR(py, g_y);
    SYMADDR(px1, g_x1); SYMADDR(psig, g_sig); SYMADDR(pout4, g_out4);
    SYMADDR(prq, g_rq); SYMADDR(pP, g_P);   SYMADDR(pD, g_D);  SYMADDR(pS0, g_S0);

    __half *h16,*xx16,*a16,*xxx16,*xw16,*wt16,*a4,*att16,*xk216,*xr216,*kf16;
    SYMADDR(h16, g_h16); SYMADDR(xx16, g_xx16);
    SYMADDR(a16, g_a16);
    SYMADDR(xxx16, g_xxx16); SYMADDR(xw16, g_xw16);
    SYMADDR(wt16, g_wt16);
    SYMADDR(a4, g_act4);     SYMADDR(att16, g_att16);
    SYMADDR(xk216, g_xk216); SYMADDR(xr216, g_xr216);
    SYMADDR(kf16, g_kf16);

    __half *w4,*wo16,*wffn1,*wcv16,*maaT,*tdT,*td2T,*w2T;
    SYMADDR(w4, g_W4_16);    SYMADDR(wo16, g_Wo16);
    SYMADDR(wffn1, g_Wffn1); SYMADDR(wcv16, g_Wcv16);
    SYMADDR(maaT, g_maaw1T); SYMADDR(tdT, g_tdw1T);
    SYMADDR(td2T, g_tdw2T);  SYMADDR(w2T, g_w2T);

    cudaFuncSetAttribute((const void*)gemm_mma<TC_TANH16,64>, cudaFuncAttributeMaxDynamicSharedMemorySize, SM_MMA_64);
    cudaFuncSetAttribute((const void*)gemm_mma<TC_DECAY,128>, cudaFuncAttributeMaxDynamicSharedMemorySize, SM_MMA_128);
    cudaFuncSetAttribute((const void*)gemm_mma<TC_ADDX,128>,  cudaFuncAttributeMaxDynamicSharedMemorySize, SM_MMA_128);
    cudaFuncSetAttribute((const void*)gemm_mma<TC_CVMIX,128>, cudaFuncAttributeMaxDynamicSharedMemorySize, SM_MMA_128);
    cudaFuncSetAttribute((const void*)gemm_mix,               cudaFuncAttributeMaxDynamicSharedMemorySize, SM_MMA_128);
    cudaFuncSetAttribute((const void*)gemm_rkvg5,             cudaFuncAttributeMaxDynamicSharedMemorySize, SM_MMA_128);
    cudaFuncSetAttribute((const void*)gemm_ffn1,              cudaFuncAttributeMaxDynamicSharedMemorySize, SM_MMA_128);

    // ---- weight prep: one launch ----
    wtrans_all<<<WT_TOTAL, 256>>>(Wr, Wk, Wv, Wg, Wo, Wcr, Wck, Wcv,
        maa_w1, td_w1, td_w2, maa_w2,
        w4, wo16, wffn1 + (size_t)Ff * Cc, wffn1, wcv16, maaT, tdT, td2T, w2T);

    // ---- time mixing ----
    lnshift1_kernel<<<MM, 256>>>(x, ln1_w, ln1_b, tm_maa);
    gemm_mma<TC_TANH16,64><<<dim3(256/128, MM/64), 256, SM_MMA_64>>>(xxx16, maaT, nullptr,
        MM, 256, Cc, Cc, Cc, LDA_A, 192, nullptr, nullptr, nullptr, a16);
    gemm_mix<<<dim3(Cc/128, MM/128, 5), 256, SM_MMA_128>>>(a16, w2T, tm_maa,
        h16, xx16, xw16, a4);
    gemm_rkvg5<<<dim3(Cc/128, MM/128, 5), 256, SM_MMA_128>>>(a4, w4, pout4,
        xw16, tdT, wt16);
    gemm_mma<TC_DECAY,128><<<dim3(Cc/128, MM/128), 256, SM_MMA_128>>>(wt16, td2T, pw,
        MM, Cc, 64, 64, 64, Cc, Cc, nullptr, nullptr, time_decay, nullptr);
    wkv6_partA<<<64 * CH, 256>>>(time_faaaa,
        pout4 + (size_t)0*MM*Cc, pout4 + (size_t)1*MM*Cc, pout4 + (size_t)2*MM*Cc,
        pw, py, prq, pP, pD);
    wkv6_partB<<<64, 256>>>(pP, pD, pS0);
    wkv6_partC<<<64 * CH * 2, 256>>>(prq, pS0, py);
    gnsilu_kernel<<<MM * Hh / 8, 256>>>(lnx_w, lnx_b, pout4 + (size_t)3*MM*Cc, py);
    gemm_mma<TC_ADDX,128><<<dim3(Cc/128, MM/128), 256, SM_MMA_128>>>(att16, wo16, px1,
        MM, Cc, Cc, Cc, Cc, Cc, Cc, x, nullptr, nullptr, nullptr);

    // ---- channel mixing ----
    lnshift2_kernel<<<MM, 256>>>(px1, ln2_w, ln2_b, cm_maa);
    gemm_ffn1<<<dim3(NF1/128, MM/128), 256, SM_MMA_128>>>(xk216, xr216, wffn1,
        kf16, psig, Ff/128);
    gemm_mma<TC_CVMIX,128><<<dim3(Cc/128, MM/128), 256, SM_MMA_128>>>(kf16, wcv16, out,
        MM, Cc, Ff, Ff, Ff, Cc, Cc, px1, psig, nullptr, nullptr);
}

// round 16
// speedup vs baseline: 1.0999x; 1.0034x over previous
#include <cuda_runtime.h>
#include <cuda_fp16.h>
#include <math.h>

// ---------------- problem constants ----------------
#define Bq 2
#define Tt 2048
#define Cc 2048
#define Hh 32
#define Nn 64
#define Ff 7168
#define MM (Bq*Tt)          // 4096 tokens
#define NF1 (Ff + Cc)       // 9216 rows in merged [Wck^T ; Wcr^T] buffer
#define CH 16               // scan chunks
#define CL (Tt/CH)          // 128 steps per chunk
#define LDA_A 320           // padded a16 row stride

typedef unsigned int u32;
typedef unsigned long long u64;

// ---------------- device scratch (no allocs allowed) ----------------
__device__ float g_w  [(size_t)MM*Cc];      // decay d = exp(-exp(w))
__device__ float g_y  [(size_t)MM*Cc];
__device__ float g_x1 [(size_t)MM*Cc];
__device__ float g_sig[(size_t)MM*Cc];
__device__ float g_out4[(size_t)4*MM*Cc];   // r,k,v,g
__device__ float g_rq [(size_t)MM*Cc];      // r * cumdecay (scan phase A)
__device__ float g_P  [(size_t)64*CH*4096]; // chunk-final local states
__device__ float g_D  [(size_t)64*CH*64];   // chunk decay products
__device__ float g_S0 [(size_t)64*CH*4096]; // chunk initial states

// fp16 activations
__device__ __align__(16) __half g_h16  [(size_t)MM*Cc];     // LN1 output (mix epilogue only)
__device__ __align__(16) __half g_xx16 [(size_t)MM*Cc];     // token-shift delta
__device__ __align__(16) __half g_a16  [(size_t)MM*LDA_A];  // tanh(xxx@maa_w1), padded
__device__ __align__(16) __half g_xxx16[(size_t)MM*Cc];
__device__ __align__(16) __half g_xw16 [(size_t)MM*Cc];
__device__ __align__(16) __half g_wt16 [(size_t)MM*64 + 256];
__device__ __align__(16) __half g_act4 [(size_t)4*MM*Cc];   // xr,xk,xv,xg
__device__ __align__(16) __half g_att16[(size_t)MM*Cc];
__device__ __align__(16) __half g_xk216[(size_t)MM*Cc];
__device__ __align__(16) __half g_xr216[(size_t)MM*Cc];
__device__ __align__(16) __half g_kf16 [(size_t)MM*Ff];

// fp16 transposed weights ([N,K] K-major)
__device__ __align__(16) __half g_W4_16 [(size_t)4*Cc*Cc];  // Wr,Wk,Wv,Wg
__device__ __align__(16) __half g_Wo16  [(size_t)Cc*Cc];
__device__ __align__(16) __half g_Wffn1 [(size_t)NF1*Cc];   // [Wck^T ; Wcr^T]
__device__ __align__(16) __half g_Wcv16 [(size_t)Ff*Cc];    // [2048,7168]
__device__ __align__(16) __half g_maaw1T[(size_t)256*Cc];   // padded [256,2048]
__device__ __align__(16) __half g_tdw1T [(size_t)128*Cc];   // padded [128,2048]
__device__ __align__(16) __half g_tdw2T [(size_t)Cc*64 + 256]; // [2048,64]
__device__ __align__(16) __half g_w2T   [(size_t)5*Cc*128]; // per-f [2048,128], cols>=32 zero

// ---------------- PTX helpers (baseline PTX; no sm_103a-only features) ----
__device__ __forceinline__ u32 smem_u32(const void* p){
    u32 a;
    asm("{ .reg .u64 t; cvta.to.shared.u64 t, %1; cvt.u32.u64 %0, t; }" : "=r"(a) : "l"(p));
    return a;
}
__device__ __forceinline__ void cp16(u32 s, const void* g){
    asm volatile("cp.async.cg.shared.global [%0], [%1], 16;" :: "r"(s), "l"(g) : "memory");
}
__device__ __forceinline__ void cp_commit(){
    asm volatile("cp.async.commit_group;" ::: "memory");
}
template<int NG> __device__ __forceinline__ void cp_wait(){
    asm volatile("cp.async.wait_group %0;" :: "n"(NG) : "memory");
}
__device__ __forceinline__ void ldsm4(u32* r, u32 a){
    asm volatile("ldmatrix.sync.aligned.m8n8.x4.shared.b16 {%0,%1,%2,%3}, [%4];"
        : "=r"(r[0]), "=r"(r[1]), "=r"(r[2]), "=r"(r[3]) : "r"(a));
}
__device__ __forceinline__ void hmma16(float* c, const u32* a, u32 b0, u32 b1){
    asm volatile(
        "mma.sync.aligned.m16n8k16.row.col.f32.f16.f16.f32 "
        "{%0,%1,%2,%3},{%4,%5,%6,%7},{%8,%9},{%0,%1,%2,%3};"
        : "+f"(c[0]), "+f"(c[1]), "+f"(c[2]), "+f"(c[3])
        : "r"(a[0]), "r"(a[1]), "r"(a[2]), "r"(a[3]), "r"(b0), "r"(b1));
}

// ---------------- fp16 HMMA GEMM body, templated tile-M ----------------
enum { TC_NONE=0, TC_SILU, TC_ADDX, TC_SIGM, TC_CVMIX, TC_RELU2H,
       TC_TANH16, TC_DECAY };

#define SM_MMA_128 (3*32768)   // 3 stages x (A 16K + B 16K)
#define SM_MMA_64  (3*24576)   // 3 stages x (A 8K  + B 16K)
#define SM_MIX     (2*32768)   // 2 f-buffers x (A 16K + B 16K)

template<int EPI, int TM>
__device__ __forceinline__
void mma_body(const __half* __restrict__ A16, const __half* __restrict__ B16,
              float* __restrict__ C, int M, int N, int K, int lda, int ldb,
              int ldc, int nvalid,
              const float* __restrict__ aux0, const float* __restrict__ aux1,
              const float* __restrict__ aux2, __half* __restrict__ Ch)
{
    constexpr int MI = TM / 32;             // warp m-subtiles of 16 rows
    constexpr u32 A_BYTES = (u32)TM * 128u;
    constexpr u32 STG = A_BYTES + 16384u;

    extern __shared__ char sm_dyn[];
    const u32 sb = smem_u32(sm_dyn);
    const int tid  = threadIdx.x;
    const int wid  = tid >> 5;
    const int lane = tid & 31;
    const int m0 = blockIdx.y * TM;
    const int n0 = blockIdx.x * 128;
    const int wm = (wid & 1) * (TM / 2);
    const int wn = (wid >> 1) * 32;

    const int col16 = tid & 7;
    const int lrow  = tid >> 3;             // 0..31
    const u32 soff  = (u32)(lrow * 128 + col16 * 16);
    const u32 swz   = soff ^ ((soff >> 3) & 0x70);
    const size_t rstep_a = (size_t)32 * lda * 2;
    const size_t rstep_b = (size_t)32 * ldb * 2;
    const char* gA = (const char*)A16 + ((size_t)(m0 + lrow) * lda + col16 * 8) * 2;
    const char* gB = (const char*)B16 + ((size_t)(n0 + lrow) * ldb + col16 * 8) * 2;

    auto load_stage = [&](int s){
        u32 base = sb + (u32)(s % 3) * STG + swz;
        size_t ko = (size_t)s * 128;        // 64 fp16 = 128B along K
        #pragma unroll
        for (int i = 0; i < TM/32; i++)
            cp16(base + i*4096u, gA + ko + i*rstep_a);
        #pragma unroll
        for (int i = 0; i < 4; i++)
            cp16(base + A_BYTES + i*4096u, gB + ko + i*rstep_b);
        cp_commit();
    };

    const u32 a_row = (u32)(wm + ((lane >> 3) & 1) * 8 + (lane & 7));
    const u32 a_kb  = (u32)((lane >> 4) * 16);
    const u32 b_row = (u32)(wn + (lane >> 4) * 8 + (lane & 7));
    const u32 b_kb  = (u32)(((lane >> 3) & 1) * 16);

    float acc[MI][4][4];
    #pragma unroll
    for (int mi = 0; mi < MI; mi++)
        #pragma unroll
        for (int ni = 0; ni < 4; ni++)
            #pragma unroll
            for (int q = 0; q < 4; q++) acc[mi][ni][q] = 0.f;

    auto compute_stage = [&](u32 base){
        #pragma unroll
        for (int kk = 0; kk < 4; kk++){
            u32 aa[MI][4], bb[2][4];
            #pragma unroll
            for (int mi = 0; mi < MI; mi++){
                u32 off = (a_row + mi*16u) * 128u + (u32)kk*32u + a_kb;
                off ^= (off >> 3) & 0x70;
                ldsm4(aa[mi], base + off);
            }
            #pragma unroll
            for (int nj = 0; nj < 2; nj++){
                u32 off = (b_row + nj*16u) * 128u + (u32)kk*32u + b_kb;
                off ^= (off >> 3) & 0x70;
                ldsm4(bb[nj], base + A_BYTES + off);
            }
            #pragma unroll
            for (int mi = 0; mi < MI; mi++)
                #pragma unroll
                for (int ni = 0; ni < 4; ni++){
                    const u32* pb = &bb[ni >> 1][(ni & 1) * 2];
                    hmma16(acc[mi][ni], aa[mi], pb[0], pb[1]);
                }
        }
    };

    const int NS = K >> 6;
    load_stage(0);
    load_stage(1);
    for (int s = 0; s < NS; s++){
        if (s + 1 < NS) cp_wait<1>(); else cp_wait<0>();
        __syncthreads();
        if (s + 2 < NS) load_stage(s + 2);
        compute_stage(sb + (u32)(s % 3) * STG);
    }

    #pragma unroll
    for (int mi = 0; mi < MI; mi++){
        #pragma unroll
        for (int ni = 0; ni < 4; ni++){
            const int n = n0 + wn + ni*8 + (lane & 3)*2;
            if (n >= nvalid) continue;
            #pragma unroll
            for (int half = 0; half < 2; half++){
                const int m = m0 + wm + mi*16 + (lane >> 2) + half*8;
                const size_t idx = (size_t)m * ldc + n;
                float v0 = acc[mi][ni][half*2 + 0];
                float v1 = acc[mi][ni][half*2 + 1];
                if (EPI == TC_RELU2H){
                    float r0 = v0 > 0.f ? v0 : 0.f;
                    float r1 = v1 > 0.f ? v1 : 0.f;
                    __half2 hp;
                    hp.x = __float2half_rn(r0 * r0);
                    hp.y = __float2half_rn(r1 * r1);
                    *reinterpret_cast<__half2*>(Ch + idx) = hp;
                    continue;
                }
                if (EPI == TC_TANH16){
                    __half2 hp;
                    hp.x = __float2half_rn(tanhf(v0));
                    hp.y = __float2half_rn(tanhf(v1));
                    *reinterpret_cast<__half2*>(Ch + idx) = hp;
                    continue;
                }
                if (EPI == TC_DECAY){
                    v0 = expf(-expf(v0 + aux2[n]));
                    v1 = expf(-expf(v1 + aux2[n + 1]));
                } else if (EPI == TC_SILU){
                    v0 = v0 / (1.f + expf(-v0));
                    v1 = v1 / (1.f + expf(-v1));
                } else if (EPI == TC_ADDX){
                    v0 += aux0[idx]; v1 += aux0[idx + 1];
                } else if (EPI == TC_SIGM){
                    v0 = 1.f / (1.f + expf(-v0));
                    v1 = 1.f / (1.f + expf(-v1));
                } else if (EPI == TC_CVMIX){
                    v0 = aux0[idx]     + aux1[idx]     * v0;
                    v1 = aux0[idx + 1] + aux1[idx + 1] * v1;
                }
                float2 o; o.x = v0; o.y = v1;
                *reinterpret_cast<float2*>(C + idx) = o;
            }
        }
    }
}

template<int EPI, int TM>
__global__ __launch_bounds__(256, 2)
void gemm_mma(const __half* __restrict__ A16, const __half* __restrict__ B16,
              float* __restrict__ C, int M, int N, int K, int lda, int ldb,
              int ldc, int nvalid,
              const float* __restrict__ aux0, const float* __restrict__ aux1,
              const float* __restrict__ aux2, __half* __restrict__ Ch)
{
    mma_body<EPI, TM>(A16, B16, C, M, N, K, lda, ldb, ldc, nvalid,
                      aux0, aux1, aux2, Ch);
}

// fused 5-slice mix: one CTA per (m,n) tile, f-loop inside with double-buffered
// cp.async. h16/xx16 epilogue reads repeat per f within the CTA -> L2 hits.
__global__ __launch_bounds__(256, 2)
void gemm_mix5(const __half* __restrict__ a16, const __half* __restrict__ w2T,
               const float* __restrict__ tm_maa,
               const __half* __restrict__ h16, const __half* __restrict__ xx16,
               __half* __restrict__ xw16, __half* __restrict__ a4)
{
    extern __shared__ char sm_dyn[];
    const u32 sb = smem_u32(sm_dyn);
    const int tid  = threadIdx.x;
    const int wid  = tid >> 5;
    const int lane = tid & 31;
    const int m0 = blockIdx.y * 128;
    const int n0 = blockIdx.x * 128;
    const int wm = (wid & 1) * 64;
    const int wn = (wid >> 1) * 32;

    const int col16 = tid & 7;
    const int lrow  = tid >> 3;
    const u32 soff  = (u32)(lrow * 128 + col16 * 16);
    const u32 swz   = soff ^ ((soff >> 3) & 0x70);

    auto load_f = [&](int f, int buf){
        u32 base = sb + (u32)buf * 32768u + swz;
        const char* gA = (const char*)a16 +
            ((size_t)(m0 + lrow) * LDA_A + f * 32 + col16 * 8) * 2;
        const char* gB = (const char*)(w2T + (size_t)f * Cc * 128) +
            ((size_t)(n0 + lrow) * 128 + col16 * 8) * 2;
        #pragma unroll
        for (int i = 0; i < 4; i++){
            cp16(base +          i*4096u, gA + (size_t)i * 32 * LDA_A * 2);
            cp16(base + 16384u + i*4096u, gB + (size_t)i * 32 * 128 * 2);
        }
        cp_commit();
    };

    const u32 a_row = (u32)(wm + ((lane >> 3) & 1) * 8 + (lane & 7));
    const u32 a_kb  = (u32)((lane >> 4) * 16);
    const u32 b_row = (u32)(wn + (lane >> 4) * 8 + (lane & 7));
    const u32 b_kb  = (u32)(((lane >> 3) & 1) * 16);

    load_f(0, 0);
    load_f(1, 1);

    #pragma unroll 1
    for (int f = 0; f < 5; f++){
        if (f < 4) cp_wait<1>(); else cp_wait<0>();
        __syncthreads();
        const u32 base = sb + (u32)(f & 1) * 32768u;

        float acc[4][4][4];
        #pragma unroll
        for (int mi = 0; mi < 4; mi++)
            #pragma unroll
            for (int ni = 0; ni < 4; ni++)
                #pragma unroll
                for (int q = 0; q < 4; q++) acc[mi][ni][q] = 0.f;

        #pragma unroll
        for (int kk = 0; kk < 4; kk++){
            u32 aa[4][4], bb[2][4];
            #pragma unroll
            for (int mi = 0; mi < 4; mi++){
                u32 off = (a_row + mi*16u) * 128u + (u32)kk*32u + a_kb;
                off ^= (off >> 3) & 0x70;
                ldsm4(aa[mi], base + off);
            }
            #pragma unroll
            for (int nj = 0; nj < 2; nj++){
                u32 off = (b_row + nj*16u) * 128u + (u32)kk*32u + b_kb;
                off ^= (off >> 3) & 0x70;
                ldsm4(bb[nj], base + 16384u + off);
            }
            #pragma unroll
            for (int mi = 0; mi < 4; mi++)
                #pragma unroll
                for (int ni = 0; ni < 4; ni++){
                    const u32* pb = &bb[ni >> 1][(ni & 1) * 2];
                    hmma16(acc[mi][ni], aa[mi], pb[0], pb[1]);
                }
        }
        __syncthreads();                  // all warps done reading buf (f&1)
        if (f + 2 < 5) load_f(f + 2, f & 1);

        const int slot = (f == 1) ? 1 : (f == 2) ? 2 : (f == 3) ? 0 : 3;
        __half* Ch = (f == 0) ? xw16 : a4 + (size_t)slot * MM * Cc;
        const float* maa = tm_maa + (size_t)(1 + f) * Cc;

        #pragma unroll
        for (int mi = 0; mi < 4; mi++){
            #pragma unroll
            for (int ni = 0; ni < 4; ni++){
                const int n = n0 + wn + ni*8 + (lane & 3)*2;
                #pragma unroll
                for (int half = 0; half < 2; half++){
                    const int m = m0 + wm + mi*16 + (lane >> 2) + half*8;
                    const size_t idx = (size_t)m * Cc + n;
                    const __half2 hh = *reinterpret_cast<const __half2*>(h16 + idx);
                    const __half2 xv = *reinterpret_cast<const __half2*>(xx16 + idx);
                    float o0 = __half2float(hh.x)
                             + __half2float(xv.x) * (maa[n]     + acc[mi][ni][half*2 + 0]);
                    float o1 = __half2float(hh.y)
                             + __half2float(xv.y) * (maa[n + 1] + acc[mi][ni][half*2 + 1]);
                    __half2 hp;
                    hp.x = __float2half_rn(o0);
                    hp.y = __float2half_rn(o1);
                    *reinterpret_cast<__half2*>(Ch + idx) = hp;
                }
            }
        }
    }
}

// merged r/k/v/g + td GEMM: z=0..3 rkvg (z==3 silu); z==4: td tanh -> fp16 wt
__global__ __launch_bounds__(256, 2)
void gemm_rkvg5(const __half* __restrict__ A4, const __half* __restrict__ W4,
                float* __restrict__ C4,
                const __half* __restrict__ xw16, const __half* __restrict__ tdT,
                __half* __restrict__ wt16)
{
    const int z = blockIdx.z;
    if (z == 4){
        if (blockIdx.x != 0) return;
        mma_body<TC_TANH16, 128>(xw16, tdT, nullptr, MM, 128, Cc, Cc, Cc, 64, 64,
                                 nullptr, nullptr, nullptr, wt16);
        return;
    }
    const size_t ao = (size_t)z * MM * Cc;
    const size_t wo = (size_t)z * Cc * Cc;
    if (z == 3)
        mma_body<TC_SILU, 128>(A4 + ao, W4 + wo, C4 + ao, MM, Cc, Cc, Cc, Cc, Cc, Cc,
                               nullptr, nullptr, nullptr, nullptr);
    else
        mma_body<TC_NONE, 128>(A4 + ao, W4 + wo, C4 + ao, MM, Cc, Cc, Cc, Cc, Cc, Cc,
                               nullptr, nullptr, nullptr, nullptr);
}

// merged ffn1: grid (72, 32). Tiles [0,56): relu2(xk2@Wck)->kf16.
// Tiles [56,72): sigmoid(xr2@Wcr)->psig (bases shifted by -Ff to rebase n).
__global__ __launch_bounds__(256, 2)
void gemm_ffn1(const __half* __restrict__ xk2, const __half* __restrict__ xr2,
               const __half* __restrict__ Wf, __half* __restrict__ kf,
               float* __restrict__ sig, int split)
{
    if ((int)blockIdx.x < split){
        mma_body<TC_RELU2H, 128>(xk2, Wf, nullptr, MM, Ff, Cc, Cc, Cc, Ff, Ff,
                                 nullptr, nullptr, nullptr, kf);
    } else {
        mma_body<TC_SIGM, 128>(xr2, Wf, sig - Ff, MM, NF1, Cc, Cc, Cc, Cc, NF1,
                               nullptr, nullptr, nullptr, nullptr);
    }
}

// ---------------- merged weight prep: all transposes in one launch ----------
#define WT_TOTAL 54464
__global__ __launch_bounds__(256)
void wtrans_all(const float* __restrict__ Wr, const float* __restrict__ Wk,
                const float* __restrict__ Wv, const float* __restrict__ Wg,
                const float* __restrict__ Wo, const float* __restrict__ Wcr,
                const float* __restrict__ Wck, const float* __restrict__ Wcv,
                const float* __restrict__ maa_w1, const float* __restrict__ td_w1,
                const float* __restrict__ td_w2, const float* __restrict__ maa_w2,
                __half* __restrict__ T4, __half* __restrict__ To,
                __half* __restrict__ Tcr, __half* __restrict__ Tck,
                __half* __restrict__ Tcv, __half* __restrict__ TmaaT,
                __half* __restrict__ TtdT, __half* __restrict__ Ttd2,
                __half* __restrict__ w2T)
{
    __shared__ float s[32][33];
    const int t = blockIdx.x;
    const int tx = threadIdx.x & 31, ty = threadIdx.x >> 5;

    if (t >= 54016 && t < 54336){
        const int r = t - 54016;
        const int f = r >> 6;
        const int c0 = (r & 63) * 32;
        #pragma unroll
        for (int rr = 0; rr < 32; rr += 8)
            s[ty + rr][tx] = maa_w2[((size_t)f * 32 + ty + rr) * Cc + c0 + tx];
        __syncthreads();
        const int c = threadIdx.x >> 3;
        const int dseg = (threadIdx.x & 7) * 16;
        __half* outp = w2T + ((size_t)f * Cc + c0 + c) * 128 + dseg;
        #pragma unroll
        for (int dd = 0; dd < 16; dd += 2){
            int d0 = dseg + dd;
            __half2 hp;
            hp.x = __float2half_rn(d0     < 32 ? s[d0][c]     : 0.f);
            hp.y = __float2half_rn(d0 + 1 < 32 ? s[d0 + 1][c] : 0.f);
            *reinterpret_cast<__half2*>(outp + dd) = hp;
        }
        return;
    }

    const float* W; __half* T; int K, N, bx, by; bool pad = false;
    if (t < 24576){
        int z = t >> 12, r = t & 4095;
        W = (z==0)?Wr:(z==1)?Wk:(z==2)?Wv:(z==3)?Wg:(z==4)?Wo:Wcr;
        T = (z < 4) ? T4 + (size_t)z * Cc * Cc : (z == 4 ? To : Tcr);
        K = Cc; N = Cc; bx = r & 63; by = r >> 6;
    } else if (t < 38912){
        int r = t - 24576;
        W = Wck; T = Tck; K = Cc; N = Ff; bx = r % 224; by = r / 224;
    } else if (t < 53248){
        int r = t - 38912;
        W = Wcv; T = Tcv; K = Ff; N = Cc; bx = r & 63; by = r >> 6;
    } else if (t < 53760){
        int r = t - 53248;
        W = maa_w1; T = TmaaT; K = Cc; N = 160; pad = true; bx = r & 7; by = r >> 3;
    } else if (t < 54016){
        int r = t - 53760;
        W = td_w1; T = TtdT; K = Cc; N = 64; pad = true; bx = r & 3; by = r >> 2;
    } else {
        int r = t - 54336;                      // [0,128): td_w2 [64,2048] -> [2048,64]
        W = td_w2; T = Ttd2; K = 64; N = Cc; bx = r & 63; by = r >> 6;
    }

    const int n0 = bx * 32, k0 = by * 32;
    #pragma unroll
    for (int rr = 0; rr < 32; rr += 8){
        int n = n0 + tx;
        s[ty + rr][tx] = (!pad || n < N) ? W[(size_t)(k0 + ty + rr) * N + n] : 0.f;
    }
    __syncthreads();
    #pragma unroll
    for (int rr = 0; rr < 32; rr += 8)
        T[(size_t)(n0 + ty + rr) * K + k0 + tx] = __float2half_rn(s[tx][ty + rr]);
}

// ---------------- fused LN + token-shift (time mixing) ----------------
__global__ __launch_bounds__(256)
void lnshift1_kernel(const float* __restrict__ x, const float* __restrict__ w,
                     const float* __restrict__ b, const float* __restrict__ tm_maa)
{
    const int token = blockIdx.x;
    const int t = token % Tt;
    const size_t base = (size_t)token * Cc;
    const int tid = threadIdx.x;

    float cur[8], prv[8];
    float sA = 0.f, qA = 0.f, sB = 0.f, qB = 0.f;
    #pragma unroll
    for (int k = 0; k < 8; k++){
        int c = k * 256 + tid;
        float v = x[base + c];
        cur[k] = v; sA += v; qA += v * v;
        float p = (t > 0) ? x[base - Cc + c] : 0.f;
        prv[k] = p; sB += p; qB += p * p;
    }
    #pragma unroll
    for (int o = 16; o; o >>= 1){
        sA += __shfl_xor_sync(0xffffffffu, sA, o);
        qA += __shfl_xor_sync(0xffffffffu, qA, o);
        sB += __shfl_xor_sync(0xffffffffu, sB, o);
        qB += __shfl_xor_sync(0xffffffffu, qB, o);
    }
    __shared__ float r1[8], r2[8], r3[8], r4[8];
    int wid = tid >> 5, lane = tid & 31;
    if (!lane){ r1[wid] = sA; r2[wid] = qA; r3[wid] = sB; r4[wid] = qB; }
    __syncthreads();
    if (tid == 0){
        float a = 0.f, c2 = 0.f, d = 0.f, e = 0.f;
        #pragma unroll
        for (int i = 0; i < 8; i++){ a += r1[i]; c2 += r2[i]; d += r3[i]; e += r4[i]; }
        float mA = a / (float)Cc, mB = d / (float)Cc;
        r1[0] = mA; r2[0] = rsqrtf(c2 / (float)Cc - mA*mA + 1e-5f);
        r3[0] = mB; r4[0] = rsqrtf(e  / (float)Cc - mB*mB + 1e-5f);
    }
    __syncthreads();
    float mA = r1[0], rA = r2[0], mB = r3[0], rB = r4[0];
    #pragma unroll
    for (int k = 0; k < 8; k++){
        int c = k * 256 + tid;
        float hv = (cur[k] - mA) * rA * w[c] + b[c];
        float hp = (t > 0) ? (prv[k] - mB) * rB * w[c] + b[c] : 0.f;
        float d = hp - hv;
        g_h16 [base + c] = __float2half_rn(hv);
        g_xx16[base + c] = __float2half_rn(d);
        g_xxx16[base + c] = __float2half_rn(hv + d * tm_maa[c]);
    }
}

// ---------------- fused LN + token-shift (channel mixing) ----------------
__global__ __launch_bounds__(256)
void lnshift2_kernel(const float* __restrict__ x, const float* __restrict__ w,
                     const float* __restrict__ b, const float* __restrict__ cm_maa)
{
    const int token = blockIdx.x;
    const int t = token % Tt;
    const size_t base = (size_t)token * Cc;
    const int tid = threadIdx.x;

    float cur[8], prv[8];
    float sA = 0.f, qA = 0.f, sB = 0.f, qB = 0.f;
    #pragma unroll
    for (int k = 0; k < 8; k++){
        int c = k * 256 + tid;
        float v = x[base + c];
        cur[k] = v; sA += v; qA += v * v;
        float p = (t > 0) ? x[base - Cc + c] : 0.f;
        prv[k] = p; sB += p; qB += p * p;
    }
    #pragma unroll
    for (int o = 16; o; o >>= 1){
        sA += __shfl_xor_sync(0xffffffffu, sA, o);
        qA += __shfl_xor_sync(0xffffffffu, qA, o);
        sB += __shfl_xor_sync(0xffffffffu, sB, o);
        qB += __shfl_xor_sync(0xffffffffu, qB, o);
    }
    __shared__ float r1[8], r2[8], r3[8], r4[8];
    int wid = tid >> 5, lane = tid & 31;
    if (!lane){ r1[wid] = sA; r2[wid] = qA; r3[wid] = sB; r4[wid] = qB; }
    __syncthreads();
    if (tid == 0){
        float a = 0.f, c2 = 0.f, d = 0.f, e = 0.f;
        #pragma unroll
        for (int i = 0; i < 8; i++){ a += r1[i]; c2 += r2[i]; d += r3[i]; e += r4[i]; }
        float mA = a / (float)Cc, mB = d / (float)Cc;
        r1[0] = mA; r2[0] = rsqrtf(c2 / (float)Cc - mA*mA + 1e-5f);
        r3[0] = mB; r4[0] = rsqrtf(e  / (float)Cc - mB*mB + 1e-5f);
    }
    __syncthreads();
    float mA = r1[0], rA = r2[0], mB = r3[0], rB = r4[0];
    #pragma unroll
    for (int k = 0; k < 8; k++){
        int c = k * 256 + tid;
        float hv = (cur[k] - mA) * rA * w[c] + b[c];
        float hp = (t > 0) ? (prv[k] - mB) * rB * w[c] + b[c] : 0.f;
        float d = hp - hv;
        g_xk216[base + c] = __float2half_rn(hv + d * cm_maa[c]);
        g_xr216[base + c] = __float2half_rn(hv + d * cm_maa[Cc + c]);
    }
}

// ---------------- WKV6 chunk-parallel scan (decay precomputed) ----------
__global__ __launch_bounds__(256)
void wkv6_partA(const float* __restrict__ u,
                const float* __restrict__ rr, const float* __restrict__ kk,
                const float* __restrict__ vv, const float* __restrict__ dd,
                float* __restrict__ yy, float* __restrict__ rq,
                float* __restrict__ Pc, float* __restrict__ Dc)
{
    const int blk = blockIdx.x;
    const int bh = blk >> 4;
    const int ch = blk & (CH - 1);
    const int b = bh >> 5, hh = bh & 31;
    const int tid = threadIdx.x;
    const int j = tid & 63;
    const int ib = (tid >> 6) * 16;
    __shared__ float4 sv[64];
    __shared__ float  yp[256];
    float S[16];
    #pragma unroll
    for (int i = 0; i < 16; i++) S[i] = 0.f;
    size_t off = (size_t)b * Tt * Cc + (size_t)ch * CL * Cc + (size_t)hh * Nn;
    float ur = (tid < 64) ? u[hh * Nn + j] : 0.f;
    float cum = 1.f;

    float rn = 0.f, kn = 0.f, dn = 0.f, vn;
    if (tid < 64){ rn = rr[off + j]; kn = kk[off + j]; dn = dd[off + j]; }
    vn = vv[off + j];

    for (int t = 0; t < CL; t++) {
        float rc = rn, kc = kn, dc = dn, vc = vn;
        size_t offn = off + Cc;
        if (t + 1 < CL){
            if (tid < 64){ rn = rr[offn + j]; kn = kk[offn + j]; dn = dd[offn + j]; }
            vn = vv[offn + j];
        }
        if (tid < 64){
            rq[off + j] = rc * cum;
            cum *= dc;
            sv[j] = make_float4(rc, kc, ur * kc, dc);
        }
        __syncthreads();
        float a0 = 0.f, a1 = 0.f;
        #pragma unroll
        for (int ii = 0; ii < 16; ii += 2) {
            float4 q0 = sv[ib + ii];
            float4 q1 = sv[ib + ii + 1];
            a0 = fmaf(q0.x, fmaf(q0.z, vc, S[ii]), a0);
            S[ii] = fmaf(S[ii], q0.w, q0.y * vc);
            a1 = fmaf(q1.x, fmaf(q1.z, vc, S[ii + 1]), a1);
            S[ii + 1] = fmaf(S[ii + 1], q1.w, q1.y * vc);
        }
        yp[tid] = a0 + a1;
        __syncthreads();
        if (tid < 64) yy[off + j] = yp[j] + yp[64 + j] + yp[128 + j] + yp[192 + j];
        off = offn;
    }
    const size_t pbase = ((size_t)bh * CH + ch) * 4096;
    #pragma unroll
    for (int ii = 0; ii < 16; ii++)
        Pc[pbase + (size_t)(ib + ii) * 64 + j] = S[ii];
    if (tid < 64) Dc[((size_t)bh * CH + ch) * 64 + j] = cum;
}

__global__ __launch_bounds__(256)
void wkv6_partB(const float* __restrict__ Pc, const float* __restrict__ Dc,
                float* __restrict__ S0)
{
    const int bh = blockIdx.x;
    const int tid = threadIdx.x;
    const int e0 = tid * 16;
    const int i  = e0 >> 6;
    float4 s[4];
    #pragma unroll
    for (int q = 0; q < 4; q++) s[q] = make_float4(0.f, 0.f, 0.f, 0.f);
    for (int ch = 0; ch < CH; ch++){
        const size_t base = ((size_t)bh * CH + ch) * 4096 + e0;
        #pragma unroll
        for (int q = 0; q < 4; q++)
            *reinterpret_cast<float4*>(&S0[base + q*4]) = s[q];
        const float d = Dc[((size_t)bh * CH + ch) * 64 + i];
        #pragma unroll
        for (int q = 0; q < 4; q++){
            float4 p = *reinterpret_cast<const float4*>(&Pc[base + q*4]);
            s[q].x = fmaf(s[q].x, d, p.x);
            s[q].y = fmaf(s[q].y, d, p.y);
            s[q].z = fmaf(s[q].z, d, p.z);
            s[q].w = fmaf(s[q].w, d, p.w);
        }
    }
}

__global__ __launch_bounds__(256)
void wkv6_partC(const float* __restrict__ rq, const float* __restrict__ S0,
                float* __restrict__ yy)
{
    const int x = blockIdx.x;
    const int half = x & 1;
    const int ch = (x >> 1) & (CH - 1);
    const int bh = x >> 5;
    if (ch == 0) return;
    const int b = bh >> 5, hh = bh & 31;
    __shared__ float sS0[64][68];
    __shared__ float sRq[64][68];
    const int tid = threadIdx.x;
    const size_t off = (size_t)b * Tt * Cc
                     + (size_t)(ch * CL + half * 64) * Cc + (size_t)hh * Nn;
    const size_t sbase = ((size_t)bh * CH + ch) * 4096;

    {
        const int e0 = tid * 16;
        const int r = e0 >> 6, c = e0 & 63;
        #pragma unroll
        for (int q = 0; q < 4; q++){
            float4 v = *reinterpret_cast<const float4*>(&S0[sbase + e0 + q*4]);
            *reinterpret_cast<float4*>(&sS0[r][c + q*4]) = v;
            float4 w = *reinterpret_cast<const float4*>(&rq[off + (size_t)r * Cc + c + q*4]);
            *reinterpret_cast<float4*>(&sRq[r][c + q*4]) = w;
        }
    }
    __syncthreads();

    const int tr = tid >> 2;
    const int jq = (tid & 3) * 16;
    float acc[16];
    #pragma unroll
    for (int q = 0; q < 16; q++) acc[q] = 0.f;
    #pragma unroll 4
    for (int i = 0; i < 64; i++){
        float rv = sRq[tr][i];
        #pragma unroll
        for (int q = 0; q < 16; q++)
            acc[q] = fmaf(rv, sS0[i][jq + q], acc[q]);
    }
    const size_t ybase = off + (size_t)tr * Cc + jq;
    #pragma unroll
    for (int q = 0; q < 16; q += 4){
        float4 y4 = *reinterpret_cast<float4*>(&yy[ybase + q]);
        y4.x += acc[q];     y4.y += acc[q + 1];
        y4.z += acc[q + 2]; y4.w += acc[q + 3];
        *reinterpret_cast<float4*>(&yy[ybase + q]) = y4;
    }
}

// ---------------- GroupNorm(H) * silu-gate -> att fp16 ----------------
__global__ __launch_bounds__(256)
void gnsilu_kernel(const float* __restrict__ lnw, const float* __restrict__ lnb,
                   const float* __restrict__ gg, const float* __restrict__ yy)
{
    int gw  = blockIdx.x * 8 + (threadIdx.x >> 5);
    int lane = threadIdx.x & 31;
    int t  = gw >> 5;
    int hh = gw & 31;
    size_t base = (size_t)t * Cc + (size_t)hh * Nn;
    float y0 = yy[base + lane], y1 = yy[base + 32 + lane];
    float sum = y0 + y1, sq = y0*y0 + y1*y1;
    #pragma unroll
    for (int o = 16; o; o >>= 1) {
        sum += __shfl_xor_sync(0xffffffffu, sum, o);
        sq  += __shfl_xor_sync(0xffffffffu, sq,  o);
    }
    float m = sum * (1.f / 64.f);
    float rstd = rsqrtf(sq * (1.f / 64.f) - m*m + 6.4e-4f);
    int ch = hh * Nn + lane;
    float gv0 = gg[base + lane], gv1 = gg[base + 32 + lane];
    float o0 = ((y0 - m) * rstd * lnw[ch]      + lnb[ch])      * gv0;
    float o1 = ((y1 - m) * rstd * lnw[ch + 32] + lnb[ch + 32]) * gv1;
    g_att16[base + lane]      = __float2half_rn(o0);
    g_att16[base + 32 + lane] = __float2half_rn(o1);
}

// ---------------- host launch (single stream) ----------------
#define SYMADDR(v, s) cudaGetSymbolAddress((void**)&v, s)

extern "C" void kernel_launch(void* const* d_in, const int* in_sizes, int n_in,
                              void* d_out, int out_size)
{
    (void)in_sizes; (void)n_in; (void)out_size;
    const float* x          = (const float*)d_in[0];
    const float* ln1_w      = (const float*)d_in[1];
    const float* ln1_b      = (const float*)d_in[2];
    const float* ln2_w      = (const float*)d_in[3];
    const float* ln2_b      = (const float*)d_in[4];
    const float* tm_maa     = (const float*)d_in[5];
    const float* maa_w1     = (const float*)d_in[6];
    const float* maa_w2     = (const float*)d_in[7];
    const float* time_decay = (const float*)d_in[8];
    const float* td_w1      = (const float*)d_in[9];
    const float* td_w2      = (const float*)d_in[10];
    const float* time_faaaa = (const float*)d_in[11];
    const float* Wr  = (const float*)d_in[12];
    const float* Wk  = (const float*)d_in[13];
    const float* Wv  = (const float*)d_in[14];
    const float* Wg  = (const float*)d_in[15];
    const float* Wo  = (const float*)d_in[16];
    const float* lnx_w = (const float*)d_in[17];
    const float* lnx_b = (const float*)d_in[18];
    const float* cm_maa = (const float*)d_in[19];
    const float* Wck = (const float*)d_in[20];
    const float* Wcr = (const float*)d_in[21];
    const float* Wcv = (const float*)d_in[22];
    float* out = (float*)d_out;

    float *pw, *py, *px1, *psig, *pout4, *prq, *pP, *pD, *pS0;
    SYMADDR(pw, g_w);   SYMADDR(py, g_y);
    SYMADDR(px1, g_x1); SYMADDR(psig, g_sig); SYMADDR(pout4, g_out4);
    SYMADDR(prq, g_rq); SYMADDR(pP, g_P);   SYMADDR(pD, g_D);  SYMADDR(pS0, g_S0);

    __half *h16,*xx16,*a16,*xxx16,*xw16,*wt16,*a4,*att16,*xk216,*xr216,*kf16;
    SYMADDR(h16, g_h16); SYMADDR(xx16, g_xx16);
    SYMADDR(a16, g_a16);
    SYMADDR(xxx16, g_xxx16); SYMADDR(xw16, g_xw16);
    SYMADDR(wt16, g_wt16);
    SYMADDR(a4, g_act4);     SYMADDR(att16, g_att16);
    SYMADDR(xk216, g_xk216); SYMADDR(xr216, g_xr216);
    SYMADDR(kf16, g_kf16);

    __half *w4,*wo16,*wffn1,*wcv16,*maaT,*tdT,*td2T,*w2T;
    SYMADDR(w4, g_W4_16);    SYMADDR(wo16, g_Wo16);
    SYMADDR(wffn1, g_Wffn1); SYMADDR(wcv16, g_Wcv16);
    SYMADDR(maaT, g_maaw1T); SYMADDR(tdT, g_tdw1T);
    SYMADDR(td2T, g_tdw2T);  SYMADDR(w2T, g_w2T);

    cudaFuncSetAttribute((const void*)gemm_mma<TC_TANH16,64>, cudaFuncAttributeMaxDynamicSharedMemorySize, SM_MMA_64);
    cudaFuncSetAttribute((const void*)gemm_mma<TC_DECAY,128>, cudaFuncAttributeMaxDynamicSharedMemorySize, SM_MMA_128);
    cudaFuncSetAttribute((const void*)gemm_mma<TC_ADDX,128>,  cudaFuncAttributeMaxDynamicSharedMemorySize, SM_MMA_128);
    cudaFuncSetAttribute((const void*)gemm_mma<TC_CVMIX,128>, cudaFuncAttributeMaxDynamicSharedMemorySize, SM_MMA_128);
    cudaFuncSetAttribute((const void*)gemm_mix5,              cudaFuncAttributeMaxDynamicSharedMemorySize, SM_MIX);
    cudaFuncSetAttribute((const void*)gemm_rkvg5,             cudaFuncAttributeMaxDynamicSharedMemorySize, SM_MMA_128);
    cudaFuncSetAttribute((const void*)gemm_ffn1,              cudaFuncAttributeMaxDynamicSharedMemorySize, SM_MMA_128);

    // ---- weight prep: one launch ----
    wtrans_all<<<WT_TOTAL, 256>>>(Wr, Wk, Wv, Wg, Wo, Wcr, Wck, Wcv,
        maa_w1, td_w1, td_w2, maa_w2,
        w4, wo16, wffn1 + (size_t)Ff * Cc, wffn1, wcv16, maaT, tdT, td2T, w2T);

    // ---- time mixing ----
    lnshift1_kernel<<<MM, 256>>>(x, ln1_w, ln1_b, tm_maa);
    gemm_mma<TC_TANH16,64><<<dim3(256/128, MM/64), 256, SM_MMA_64>>>(xxx16, maaT, nullptr,
        MM, 256, Cc, Cc, Cc, LDA_A, 192, nullptr, nullptr, nullptr, a16);
    gemm_mix5<<<dim3(Cc/128, MM/128), 256, SM_MIX>>>(a16, w2T, tm_maa,
        h16, xx16, xw16, a4);
    gemm_rkvg5<<<dim3(Cc/128, MM/128, 5), 256, SM_MMA_128>>>(a4, w4, pout4,
        xw16, tdT, wt16);
    gemm_mma<TC_DECAY,128><<<dim3(Cc/128, MM/128), 256, SM_MMA_128>>>(wt16, td2T, pw,
        MM, Cc, 64, 64, 64, Cc, Cc, nullptr, nullptr, time_decay, nullptr);
    wkv6_partA<<<64 * CH, 256>>>(time_faaaa,
        pout4 + (size_t)0*MM*Cc, pout4 + (size_t)1*MM*Cc, pout4 + (size_t)2*MM*Cc,
        pw, py, prq, pP, pD);
    wkv6_partB<<<64, 256>>>(pP, pD, pS0);
    wkv6_partC<<<64 * CH * 2, 256>>>(prq, pS0, py);
    gnsilu_kernel<<<MM * Hh / 8, 256>>>(lnx_w, lnx_b, pout4 + (size_t)3*MM*Cc, py);
    gemm_mma<TC_ADDX,128><<<dim3(Cc/128, MM/128), 256, SM_MMA_128>>>(att16, wo16, px1,
        MM, Cc, Cc, Cc, Cc, Cc, Cc, x, nullptr, nullptr, nullptr);

    // ---- channel mixing ----
    lnshift2_kernel<<<MM, 256>>>(px1, ln2_w, ln2_b, cm_maa);
    gemm_ffn1<<<dim3(NF1/128, MM/128), 256, SM_MMA_128>>>(xk216, xr216, wffn1,
        kf16, psig, Ff/128);
    gemm_mma<TC_CVMIX,128><<<dim3(Cc/128, MM/128), 256, SM_MMA_128>>>(kf16, wcv16, out,
        MM, Cc, Ff, Ff, Ff, Cc, Cc, px1, psig, nullptr, nullptr);
}

// round 17
// speedup vs baseline: 1.1189x; 1.0172x over previous
#include <cuda_runtime.h>
#include <cuda_fp16.h>
#include <math.h>

// ---------------- problem constants ----------------
#define Bq 2
#define Tt 2048
#define Cc 2048
#define Hh 32
#define Nn 64
#define Ff 7168
#define MM (Bq*Tt)          // 4096 tokens
#define NF1 (Ff + Cc)       // 9216 rows in merged [Wck^T ; Wcr^T] buffer
#define CH 16               // scan chunks
#define CL (Tt/CH)          // 128 steps per chunk
#define LDA_A 320           // padded a16 row stride

typedef unsigned int u32;
typedef unsigned long long u64;

// ---------------- device scratch (no allocs allowed) ----------------
__device__ float g_w  [(size_t)MM*Cc];      // decay d = exp(-exp(w))
__device__ float g_y  [(size_t)MM*Cc];
__device__ float g_x1 [(size_t)MM*Cc];
__device__ float g_sig[(size_t)MM*Cc];
__device__ float g_out4[(size_t)4*MM*Cc];   // r,k,v,g
__device__ float g_rq [(size_t)MM*Cc];      // r * cumdecay (scan phase A)
__device__ float g_P  [(size_t)64*CH*4096]; // chunk-final local states
__device__ float g_D  [(size_t)64*CH*64];   // chunk decay products
__device__ float g_S0 [(size_t)64*CH*4096]; // chunk initial states

// fp16 activations
__device__ __align__(16) __half g_h16  [(size_t)MM*Cc];     // LN1 output (mix epilogue only)
__device__ __align__(16) __half g_xx16 [(size_t)MM*Cc];     // token-shift delta
__device__ __align__(16) __half g_a16  [(size_t)MM*LDA_A];  // tanh(xxx@maa_w1), padded
__device__ __align__(16) __half g_xxx16[(size_t)MM*Cc];
__device__ __align__(16) __half g_xw16 [(size_t)MM*Cc];
__device__ __align__(16) __half g_wt16 [(size_t)MM*64 + 256];
__device__ __align__(16) __half g_act4 [(size_t)4*MM*Cc];   // xr,xk,xv,xg
__device__ __align__(16) __half g_att16[(size_t)MM*Cc];
__device__ __align__(16) __half g_xk216[(size_t)MM*Cc];
__device__ __align__(16) __half g_xr216[(size_t)MM*Cc];
__device__ __align__(16) __half g_kf16 [(size_t)MM*Ff];

// fp16 transposed weights ([N,K] K-major)
__device__ __align__(16) __half g_W4_16 [(size_t)4*Cc*Cc];  // Wr,Wk,Wv,Wg
__device__ __align__(16) __half g_Wo16  [(size_t)Cc*Cc];
__device__ __align__(16) __half g_Wffn1 [(size_t)NF1*Cc];   // [Wck^T ; Wcr^T]
__device__ __align__(16) __half g_Wcv16 [(size_t)Ff*Cc];    // [2048,7168]
__device__ __align__(16) __half g_maaw1T[(size_t)256*Cc];   // padded [256,2048]
__device__ __align__(16) __half g_tdw1T [(size_t)128*Cc];   // padded [128,2048]
__device__ __align__(16) __half g_tdw2T [(size_t)Cc*64 + 256]; // [2048,64]
__device__ __align__(16) __half g_w2T   [(size_t)5*Cc*128]; // per-f [2048,128], cols>=32 zero

// ---------------- PTX helpers (baseline PTX; no sm_103a-only features) ----
__device__ __forceinline__ u32 smem_u32(const void* p){
    u32 a;
    asm("{ .reg .u64 t; cvta.to.shared.u64 t, %1; cvt.u32.u64 %0, t; }" : "=r"(a) : "l"(p));
    return a;
}
__device__ __forceinline__ void cp16(u32 s, const void* g){
    asm volatile("cp.async.cg.shared.global [%0], [%1], 16;" :: "r"(s), "l"(g) : "memory");
}
__device__ __forceinline__ void cp_commit(){
    asm volatile("cp.async.commit_group;" ::: "memory");
}
template<int NG> __device__ __forceinline__ void cp_wait(){
    asm volatile("cp.async.wait_group %0;" :: "n"(NG) : "memory");
}
__device__ __forceinline__ void ldsm4(u32* r, u32 a){
    asm volatile("ldmatrix.sync.aligned.m8n8.x4.shared.b16 {%0,%1,%2,%3}, [%4];"
        : "=r"(r[0]), "=r"(r[1]), "=r"(r[2]), "=r"(r[3]) : "r"(a));
}
__device__ __forceinline__ void hmma16(float* c, const u32* a, u32 b0, u32 b1){
    asm volatile(
        "mma.sync.aligned.m16n8k16.row.col.f32.f16.f16.f32 "
        "{%0,%1,%2,%3},{%4,%5,%6,%7},{%8,%9},{%0,%1,%2,%3};"
        : "+f"(c[0]), "+f"(c[1]), "+f"(c[2]), "+f"(c[3])
        : "r"(a[0]), "r"(a[1]), "r"(a[2]), "r"(a[3]), "r"(b0), "r"(b1));
}

// ---------------- fp16 HMMA GEMM body, templated tile-M ----------------
enum { TC_NONE=0, TC_SILU, TC_ADDX, TC_SIGM, TC_CVMIX, TC_RELU2H,
       TC_TANH16, TC_DECAY };

#define SM_MMA_128 (3*32768)   // 3 stages x (A 16K + B 16K)
#define SM_MMA_64  (3*24576)   // 3 stages x (A 8K  + B 16K)
// mix5: 2 f-buffers (64K) + h tile (34K) + xx tile (34K)
#define HX_STRIDE  272         // padded row stride (bytes) for h/xx smem tiles
#define HX_BYTES   (128*HX_STRIDE)
#define SM_MIX     (2*32768 + 2*HX_BYTES)

template<int EPI, int TM>
__device__ __forceinline__
void mma_body(const __half* __restrict__ A16, const __half* __restrict__ B16,
              float* __restrict__ C, int M, int N, int K, int lda, int ldb,
              int ldc, int nvalid,
              const float* __restrict__ aux0, const float* __restrict__ aux1,
              const float* __restrict__ aux2, __half* __restrict__ Ch)
{
    constexpr int MI = TM / 32;             // warp m-subtiles of 16 rows
    constexpr u32 A_BYTES = (u32)TM * 128u;
    constexpr u32 STG = A_BYTES + 16384u;

    extern __shared__ char sm_dyn[];
    const u32 sb = smem_u32(sm_dyn);
    const int tid  = threadIdx.x;
    const int wid  = tid >> 5;
    const int lane = tid & 31;
    const int m0 = blockIdx.y * TM;
    const int n0 = blockIdx.x * 128;
    const int wm = (wid & 1) * (TM / 2);
    const int wn = (wid >> 1) * 32;

    const int col16 = tid & 7;
    const int lrow  = tid >> 3;             // 0..31
    const u32 soff  = (u32)(lrow * 128 + col16 * 16);
    const u32 swz   = soff ^ ((soff >> 3) & 0x70);
    const size_t rstep_a = (size_t)32 * lda * 2;
    const size_t rstep_b = (size_t)32 * ldb * 2;
    const char* gA = (const char*)A16 + ((size_t)(m0 + lrow) * lda + col16 * 8) * 2;
    const char* gB = (const char*)B16 + ((size_t)(n0 + lrow) * ldb + col16 * 8) * 2;

    auto load_stage = [&](int s){
        u32 base = sb + (u32)(s % 3) * STG + swz;
        size_t ko = (size_t)s * 128;        // 64 fp16 = 128B along K
        #pragma unroll
        for (int i = 0; i < TM/32; i++)
            cp16(base + i*4096u, gA + ko + i*rstep_a);
        #pragma unroll
        for (int i = 0; i < 4; i++)
            cp16(base + A_BYTES + i*4096u, gB + ko + i*rstep_b);
        cp_commit();
    };

    const u32 a_row = (u32)(wm + ((lane >> 3) & 1) * 8 + (lane & 7));
    const u32 a_kb  = (u32)((lane >> 4) * 16);
    const u32 b_row = (u32)(wn + (lane >> 4) * 8 + (lane & 7));
    const u32 b_kb  = (u32)(((lane >> 3) & 1) * 16);

    float acc[MI][4][4];
    #pragma unroll
    for (int mi = 0; mi < MI; mi++)
        #pragma unroll
        for (int ni = 0; ni < 4; ni++)
            #pragma unroll
            for (int q = 0; q < 4; q++) acc[mi][ni][q] = 0.f;

    auto compute_stage = [&](u32 base){
        #pragma unroll
        for (int kk = 0; kk < 4; kk++){
            u32 aa[MI][4], bb[2][4];
            #pragma unroll
            for (int mi = 0; mi < MI; mi++){
                u32 off = (a_row + mi*16u) * 128u + (u32)kk*32u + a_kb;
                off ^= (off >> 3) & 0x70;
                ldsm4(aa[mi], base + off);
            }
            #pragma unroll
            for (int nj = 0; nj < 2; nj++){
                u32 off = (b_row + nj*16u) * 128u + (u32)kk*32u + b_kb;
                off ^= (off >> 3) & 0x70;
                ldsm4(bb[nj], base + A_BYTES + off);
            }
            #pragma unroll
            for (int mi = 0; mi < MI; mi++)
                #pragma unroll
                for (int ni = 0; ni < 4; ni++){
                    const u32* pb = &bb[ni >> 1][(ni & 1) * 2];
                    hmma16(acc[mi][ni], aa[mi], pb[0], pb[1]);
                }
        }
    };

    const int NS = K >> 6;
    load_stage(0);
    load_stage(1);
    for (int s = 0; s < NS; s++){
        if (s + 1 < NS) cp_wait<1>(); else cp_wait<0>();
        __syncthreads();
        if (s + 2 < NS) load_stage(s + 2);
        compute_stage(sb + (u32)(s % 3) * STG);
    }

    #pragma unroll
    for (int mi = 0; mi < MI; mi++){
        #pragma unroll
        for (int ni = 0; ni < 4; ni++){
            const int n = n0 + wn + ni*8 + (lane & 3)*2;
            if (n >= nvalid) continue;
            #pragma unroll
            for (int half = 0; half < 2; half++){
                const int m = m0 + wm + mi*16 + (lane >> 2) + half*8;
                const size_t idx = (size_t)m * ldc + n;
                float v0 = acc[mi][ni][half*2 + 0];
                float v1 = acc[mi][ni][half*2 + 1];
                if (EPI == TC_RELU2H){
                    float r0 = v0 > 0.f ? v0 : 0.f;
                    float r1 = v1 > 0.f ? v1 : 0.f;
                    __half2 hp;
                    hp.x = __float2half_rn(r0 * r0);
                    hp.y = __float2half_rn(r1 * r1);
                    *reinterpret_cast<__half2*>(Ch + idx) = hp;
                    continue;
                }
                if (EPI == TC_TANH16){
                    __half2 hp;
                    hp.x = __float2half_rn(tanhf(v0));
                    hp.y = __float2half_rn(tanhf(v1));
                    *reinterpret_cast<__half2*>(Ch + idx) = hp;
                    continue;
                }
                if (EPI == TC_DECAY){
                    v0 = expf(-expf(v0 + aux2[n]));
                    v1 = expf(-expf(v1 + aux2[n + 1]));
                } else if (EPI == TC_SILU){
                    v0 = v0 / (1.f + expf(-v0));
                    v1 = v1 / (1.f + expf(-v1));
                } else if (EPI == TC_ADDX){
                    v0 += aux0[idx]; v1 += aux0[idx + 1];
                } else if (EPI == TC_SIGM){
                    v0 = 1.f / (1.f + expf(-v0));
                    v1 = 1.f / (1.f + expf(-v1));
                } else if (EPI == TC_CVMIX){
                    v0 = aux0[idx]     + aux1[idx]     * v0;
                    v1 = aux0[idx + 1] + aux1[idx + 1] * v1;
                }
                float2 o; o.x = v0; o.y = v1;
                *reinterpret_cast<float2*>(C + idx) = o;
            }
        }
    }
}

template<int EPI, int TM>
__global__ __launch_bounds__(256, 2)
void gemm_mma(const __half* __restrict__ A16, const __half* __restrict__ B16,
              float* __restrict__ C, int M, int N, int K, int lda, int ldb,
              int ldc, int nvalid,
              const float* __restrict__ aux0, const float* __restrict__ aux1,
              const float* __restrict__ aux2, __half* __restrict__ Ch)
{
    mma_body<EPI, TM>(A16, B16, C, M, N, K, lda, ldb, ldc, nvalid,
                      aux0, aux1, aux2, Ch);
}

// fused 5-slice mix: one CTA per (m,n) tile, f-loop inside. h16/xx16 tiles are
// staged to smem ONCE (cp.async, overlapped with f0/f1 operand loads); the per-f
// epilogue reads become 29-cyc LDS instead of 234-cyc L2 LDG.
__global__ __launch_bounds__(256, 1)
void gemm_mix5(const __half* __restrict__ a16, const __half* __restrict__ w2T,
               const float* __restrict__ tm_maa,
               const __half* __restrict__ h16, const __half* __restrict__ xx16,
               __half* __restrict__ xw16, __half* __restrict__ a4)
{
    extern __shared__ char sm_dyn[];
    const u32 sb = smem_u32(sm_dyn);
    const u32 hx_h  = sb + 2u*32768u;
    const u32 hx_xx = hx_h + (u32)HX_BYTES;
    const int tid  = threadIdx.x;
    const int wid  = tid >> 5;
    const int lane = tid & 31;
    const int m0 = blockIdx.y * 128;
    const int n0 = blockIdx.x * 128;
    const int wm = (wid & 1) * 64;
    const int wn = (wid >> 1) * 32;

    const int col16 = tid & 7;
    const int lrow  = tid >> 3;
    const u32 soff  = (u32)(lrow * 128 + col16 * 16);
    const u32 swz   = soff ^ ((soff >> 3) & 0x70);

    auto load_f = [&](int f, int buf){
        u32 base = sb + (u32)buf * 32768u + swz;
        const char* gA = (const char*)a16 +
            ((size_t)(m0 + lrow) * LDA_A + f * 32 + col16 * 8) * 2;
        const char* gB = (const char*)(w2T + (size_t)f * Cc * 128) +
            ((size_t)(n0 + lrow) * 128 + col16 * 8) * 2;
        #pragma unroll
        for (int i = 0; i < 4; i++){
            cp16(base +          i*4096u, gA + (size_t)i * 32 * LDA_A * 2);
            cp16(base + 16384u + i*4096u, gB + (size_t)i * 32 * 128 * 2);
        }
        cp_commit();
    };

    load_f(0, 0);
    // stage h/xx tiles: 128 rows x 256B each into 272B-stride smem rows.
    // 2048 16B-chunks per array; 256 threads x 8 iters.
    {
        #pragma unroll
        for (int i = 0; i < 8; i++){
            int idx = tid + i * 256;
            int row = idx >> 4, c16 = idx & 15;
            u32 dst = (u32)(row * HX_STRIDE + c16 * 16);
            const char* srcH = (const char*)h16 +
                ((size_t)(m0 + row) * Cc + n0) * 2 + c16 * 16;
            const char* srcX = (const char*)xx16 +
                ((size_t)(m0 + row) * Cc + n0) * 2 + c16 * 16;
            cp16(hx_h  + dst, srcH);
            cp16(hx_xx + dst, srcX);
        }
        cp_commit();
    }
    load_f(1, 1);

    const u32 a_row = (u32)(wm + ((lane >> 3) & 1) * 8 + (lane & 7));
    const u32 a_kb  = (u32)((lane >> 4) * 16);
    const u32 b_row = (u32)(wn + (lane >> 4) * 8 + (lane & 7));
    const u32 b_kb  = (u32)(((lane >> 3) & 1) * 16);

    #pragma unroll 1
    for (int f = 0; f < 5; f++){
        if (f == 0) cp_wait<2>();          // f0 operands ready (hx + f1 pending)
        else if (f < 4) cp_wait<1>();
        else cp_wait<0>();
        __syncthreads();
        const u32 base = sb + (u32)(f & 1) * 32768u;

        float acc[4][4][4];
        #pragma unroll
        for (int mi = 0; mi < 4; mi++)
            #pragma unroll
            for (int ni = 0; ni < 4; ni++)
                #pragma unroll
                for (int q = 0; q < 4; q++) acc[mi][ni][q] = 0.f;

        #pragma unroll
        for (int kk = 0; kk < 4; kk++){
            u32 aa[4][4], bb[2][4];
            #pragma unroll
            for (int mi = 0; mi < 4; mi++){
                u32 off = (a_row + mi*16u) * 128u + (u32)kk*32u + a_kb;
                off ^= (off >> 3) & 0x70;
                ldsm4(aa[mi], base + off);
            }
            #pragma unroll
            for (int nj = 0; nj < 2; nj++){
                u32 off = (b_row + nj*16u) * 128u + (u32)kk*32u + b_kb;
                off ^= (off >> 3) & 0x70;
                ldsm4(bb[nj], base + 16384u + off);
            }
            #pragma unroll
            for (int mi = 0; mi < 4; mi++)
                #pragma unroll
                for (int ni = 0; ni < 4; ni++){
                    const u32* pb = &bb[ni >> 1][(ni & 1) * 2];
                    hmma16(acc[mi][ni], aa[mi], pb[0], pb[1]);
                }
        }
        __syncthreads();                  // all warps done reading buf (f&1)
        if (f + 2 < 5) load_f(f + 2, f & 1);

        const int slot = (f == 1) ? 1 : (f == 2) ? 2 : (f == 3) ? 0 : 3;
        __half* Ch = (f == 0) ? xw16 : a4 + (size_t)slot * MM * Cc;
        const float* maa = tm_maa + (size_t)(1 + f) * Cc;

        #pragma unroll
        for (int mi = 0; mi < 4; mi++){
            #pragma unroll
            for (int ni = 0; ni < 4; ni++){
                const int n = n0 + wn + ni*8 + (lane & 3)*2;
                const int ln = n - n0;
                #pragma unroll
                for (int half = 0; half < 2; half++){
                    const int m = m0 + wm + mi*16 + (lane >> 2) + half*8;
                    const int lm = m - m0;
                    const size_t idx = (size_t)m * Cc + n;
                    const u32 hxo = (u32)(lm * HX_STRIDE + ln * 2);
                    __half2 hh, xv;
                    asm volatile("ld.shared.b32 %0, [%1];"
                        : "=r"(*reinterpret_cast<u32*>(&hh)) : "r"(hx_h + hxo));
                    asm volatile("ld.shared.b32 %0, [%1];"
                        : "=r"(*reinterpret_cast<u32*>(&xv)) : "r"(hx_xx + hxo));
                    float o0 = __half2float(hh.x)
                             + __half2float(xv.x) * (maa[n]     + acc[mi][ni][half*2 + 0]);
                    float o1 = __half2float(hh.y)
                             + __half2float(xv.y) * (maa[n + 1] + acc[mi][ni][half*2 + 1]);
                    __half2 hp;
                    hp.x = __float2half_rn(o0);
                    hp.y = __float2half_rn(o1);
                    *reinterpret_cast<__half2*>(Ch + idx) = hp;
                }
            }
        }
    }
}

// merged r/k/v/g + td GEMM: z=0..3 rkvg (z==3 silu); z==4: td tanh -> fp16 wt
__global__ __launch_bounds__(256, 2)
void gemm_rkvg5(const __half* __restrict__ A4, const __half* __restrict__ W4,
                float* __restrict__ C4,
                const __half* __restrict__ xw16, const __half* __restrict__ tdT,
                __half* __restrict__ wt16)
{
    const int z = blockIdx.z;
    if (z == 4){
        if (blockIdx.x != 0) return;
        mma_body<TC_TANH16, 128>(xw16, tdT, nullptr, MM, 128, Cc, Cc, Cc, 64, 64,
                                 nullptr, nullptr, nullptr, wt16);
        return;
    }
    const size_t ao = (size_t)z * MM * Cc;
    const size_t wo = (size_t)z * Cc * Cc;
    if (z == 3)
        mma_body<TC_SILU, 128>(A4 + ao, W4 + wo, C4 + ao, MM, Cc, Cc, Cc, Cc, Cc, Cc,
                               nullptr, nullptr, nullptr, nullptr);
    else
        mma_body<TC_NONE, 128>(A4 + ao, W4 + wo, C4 + ao, MM, Cc, Cc, Cc, Cc, Cc, Cc,
                               nullptr, nullptr, nullptr, nullptr);
}

// merged ffn1: grid (72, 32). Tiles [0,56): relu2(xk2@Wck)->kf16.
// Tiles [56,72): sigmoid(xr2@Wcr)->psig (bases shifted by -Ff to rebase n).
__global__ __launch_bounds__(256, 2)
void gemm_ffn1(const __half* __restrict__ xk2, const __half* __restrict__ xr2,
               const __half* __restrict__ Wf, __half* __restrict__ kf,
               float* __restrict__ sig, int split)
{
    if ((int)blockIdx.x < split){
        mma_body<TC_RELU2H, 128>(xk2, Wf, nullptr, MM, Ff, Cc, Cc, Cc, Ff, Ff,
                                 nullptr, nullptr, nullptr, kf);
    } else {
        mma_body<TC_SIGM, 128>(xr2, Wf, sig - Ff, MM, NF1, Cc, Cc, Cc, Cc, NF1,
                               nullptr, nullptr, nullptr, nullptr);
    }
}

// ---------------- merged weight prep: all transposes in one launch ----------
#define WT_TOTAL 54464
__global__ __launch_bounds__(256)
void wtrans_all(const float* __restrict__ Wr, const float* __restrict__ Wk,
                const float* __restrict__ Wv, const float* __restrict__ Wg,
                const float* __restrict__ Wo, const float* __restrict__ Wcr,
                const float* __restrict__ Wck, const float* __restrict__ Wcv,
                const float* __restrict__ maa_w1, const float* __restrict__ td_w1,
                const float* __restrict__ td_w2, const float* __restrict__ maa_w2,
                __half* __restrict__ T4, __half* __restrict__ To,
                __half* __restrict__ Tcr, __half* __restrict__ Tck,
                __half* __restrict__ Tcv, __half* __restrict__ TmaaT,
                __half* __restrict__ TtdT, __half* __restrict__ Ttd2,
                __half* __restrict__ w2T)
{
    __shared__ float s[32][33];
    const int t = blockIdx.x;
    const int tx = threadIdx.x & 31, ty = threadIdx.x >> 5;

    if (t >= 54016 && t < 54336){
        const int r = t - 54016;
        const int f = r >> 6;
        const int c0 = (r & 63) * 32;
        #pragma unroll
        for (int rr = 0; rr < 32; rr += 8)
            s[ty + rr][tx] = maa_w2[((size_t)f * 32 + ty + rr) * Cc + c0 + tx];
        __syncthreads();
        const int c = threadIdx.x >> 3;
        const int dseg = (threadIdx.x & 7) * 16;
        __half* outp = w2T + ((size_t)f * Cc + c0 + c) * 128 + dseg;
        #pragma unroll
        for (int dd = 0; dd < 16; dd += 2){
            int d0 = dseg + dd;
            __half2 hp;
            hp.x = __float2half_rn(d0     < 32 ? s[d0][c]     : 0.f);
            hp.y = __float2half_rn(d0 + 1 < 32 ? s[d0 + 1][c] : 0.f);
            *reinterpret_cast<__half2*>(outp + dd) = hp;
        }
        return;
    }

    const float* W; __half* T; int K, N, bx, by; bool pad = false;
    if (t < 24576){
        int z = t >> 12, r = t & 4095;
        W = (z==0)?Wr:(z==1)?Wk:(z==2)?Wv:(z==3)?Wg:(z==4)?Wo:Wcr;
        T = (z < 4) ? T4 + (size_t)z * Cc * Cc : (z == 4 ? To : Tcr);
        K = Cc; N = Cc; bx = r & 63; by = r >> 6;
    } else if (t < 38912){
        int r = t - 24576;
        W = Wck; T = Tck; K = Cc; N = Ff; bx = r % 224; by = r / 224;
    } else if (t < 53248){
        int r = t - 38912;
        W = Wcv; T = Tcv; K = Ff; N = Cc; bx = r & 63; by = r >> 6;
    } else if (t < 53760){
        int r = t - 53248;
        W = maa_w1; T = TmaaT; K = Cc; N = 160; pad = true; bx = r & 7; by = r >> 3;
    } else if (t < 54016){
        int r = t - 53760;
        W = td_w1; T = TtdT; K = Cc; N = 64; pad = true; bx = r & 3; by = r >> 2;
    } else {
        int r = t - 54336;                      // [0,128): td_w2 [64,2048] -> [2048,64]
        W = td_w2; T = Ttd2; K = 64; N = Cc; bx = r & 63; by = r >> 6;
    }

    const int n0 = bx * 32, k0 = by * 32;
    #pragma unroll
    for (int rr = 0; rr < 32; rr += 8){
        int n = n0 + tx;
        s[ty + rr][tx] = (!pad || n < N) ? W[(size_t)(k0 + ty + rr) * N + n] : 0.f;
    }
    __syncthreads();
    #pragma unroll
    for (int rr = 0; rr < 32; rr += 8)
        T[(size_t)(n0 + ty + rr) * K + k0 + tx] = __float2half_rn(s[tx][ty + rr]);
}

// ---------------- fused LN + token-shift (time mixing) ----------------
__global__ __launch_bounds__(256)
void lnshift1_kernel(const float* __restrict__ x, const float* __restrict__ w,
                     const float* __restrict__ b, const float* __restrict__ tm_maa)
{
    const int token = blockIdx.x;
    const int t = token % Tt;
    const size_t base = (size_t)token * Cc;
    const int tid = threadIdx.x;

    float cur[8], prv[8];
    float sA = 0.f, qA = 0.f, sB = 0.f, qB = 0.f;
    #pragma unroll
    for (int k = 0; k < 8; k++){
        int c = k * 256 + tid;
        float v = x[base + c];
        cur[k] = v; sA += v; qA += v * v;
        float p = (t > 0) ? x[base - Cc + c] : 0.f;
        prv[k] = p; sB += p; qB += p * p;
    }
    #pragma unroll
    for (int o = 16; o; o >>= 1){
        sA += __shfl_xor_sync(0xffffffffu, sA, o);
        qA += __shfl_xor_sync(0xffffffffu, qA, o);
        sB += __shfl_xor_sync(0xffffffffu, sB, o);
        qB += __shfl_xor_sync(0xffffffffu, qB, o);
    }
    __shared__ float r1[8], r2[8], r3[8], r4[8];
    int wid = tid >> 5, lane = tid & 31;
    if (!lane){ r1[wid] = sA; r2[wid] = qA; r3[wid] = sB; r4[wid] = qB; }
    __syncthreads();
    if (tid == 0){
        float a = 0.f, c2 = 0.f, d = 0.f, e = 0.f;
        #pragma unroll
        for (int i = 0; i < 8; i++){ a += r1[i]; c2 += r2[i]; d += r3[i]; e += r4[i]; }
        float mA = a / (float)Cc, mB = d / (float)Cc;
        r1[0] = mA; r2[0] = rsqrtf(c2 / (float)Cc - mA*mA + 1e-5f);
        r3[0] = mB; r4[0] = rsqrtf(e  / (float)Cc - mB*mB + 1e-5f);
    }
    __syncthreads();
    float mA = r1[0], rA = r2[0], mB = r3[0], rB = r4[0];
    #pragma unroll
    for (int k = 0; k < 8; k++){
        int c = k * 256 + tid;
        float hv = (cur[k] - mA) * rA * w[c] + b[c];
        float hp = (t > 0) ? (prv[k] - mB) * rB * w[c] + b[c] : 0.f;
        float d = hp - hv;
        g_h16 [base + c] = __float2half_rn(hv);
        g_xx16[base + c] = __float2half_rn(d);
        g_xxx16[base + c] = __float2half_rn(hv + d * tm_maa[c]);
    }
}

// ---------------- fused LN + token-shift (channel mixing) ----------------
__global__ __launch_bounds__(256)
void lnshift2_kernel(const float* __restrict__ x, const float* __restrict__ w,
                     const float* __restrict__ b, const float* __restrict__ cm_maa)
{
    const int token = blockIdx.x;
    const int t = token % Tt;
    const size_t base = (size_t)token * Cc;
    const int tid = threadIdx.x;

    float cur[8], prv[8];
    float sA = 0.f, qA = 0.f, sB = 0.f, qB = 0.f;
    #pragma unroll
    for (int k = 0; k < 8; k++){
        int c = k * 256 + tid;
        float v = x[base + c];
        cur[k] = v; sA += v; qA += v * v;
        float p = (t > 0) ? x[base - Cc + c] : 0.f;
        prv[k] = p; sB += p; qB += p * p;
    }
    #pragma unroll
    for (int o = 16; o; o >>= 1){
        sA += __shfl_xor_sync(0xffffffffu, sA, o);
        qA += __shfl_xor_sync(0xffffffffu, qA, o);
        sB += __shfl_xor_sync(0xffffffffu, sB, o);
        qB += __shfl_xor_sync(0xffffffffu, qB, o);
    }
    __shared__ float r1[8], r2[8], r3[8], r4[8];
    int wid = tid >> 5, lane = tid & 31;
    if (!lane){ r1[wid] = sA; r2[wid] = qA; r3[wid] = sB; r4[wid] = qB; }
    __syncthreads();
    if (tid == 0){
        float a = 0.f, c2 = 0.f, d = 0.f, e = 0.f;
        #pragma unroll
        for (int i = 0; i < 8; i++){ a += r1[i]; c2 += r2[i]; d += r3[i]; e += r4[i]; }
        float mA = a / (float)Cc, mB = d / (float)Cc;
        r1[0] = mA; r2[0] = rsqrtf(c2 / (float)Cc - mA*mA + 1e-5f);
        r3[0] = mB; r4[0] = rsqrtf(e  / (float)Cc - mB*mB + 1e-5f);
    }
    __syncthreads();
    float mA = r1[0], rA = r2[0], mB = r3[0], rB = r4[0];
    #pragma unroll
    for (int k = 0; k < 8; k++){
        int c = k * 256 + tid;
        float hv = (cur[k] - mA) * rA * w[c] + b[c];
        float hp = (t > 0) ? (prv[k] - mB) * rB * w[c] + b[c] : 0.f;
        float d = hp - hv;
        g_xk216[base + c] = __float2half_rn(hv + d * cm_maa[c]);
        g_xr216[base + c] = __float2half_rn(hv + d * cm_maa[Cc + c]);
    }
}

// ---------------- WKV6 chunk-parallel scan (decay precomputed) ----------
__global__ __launch_bounds__(256)
void wkv6_partA(const float* __restrict__ u,
                const float* __restrict__ rr, const float* __restrict__ kk,
                const float* __restrict__ vv, const float* __restrict__ dd,
                float* __restrict__ yy, float* __restrict__ rq,
                float* __restrict__ Pc, float* __restrict__ Dc)
{
    const int blk = blockIdx.x;
    const int bh = blk >> 4;
    const int ch = blk & (CH - 1);
    const int b = bh >> 5, hh = bh & 31;
    const int tid = threadIdx.x;
    const int j = tid & 63;
    const int ib = (tid >> 6) * 16;
    __shared__ float4 sv[64];
    __shared__ float  yp[256];
    float S[16];
    #pragma unroll
    for (int i = 0; i < 16; i++) S[i] = 0.f;
    size_t off = (size_t)b * Tt * Cc + (size_t)ch * CL * Cc + (size_t)hh * Nn;
    float ur = (tid < 64) ? u[hh * Nn + j] : 0.f;
    float cum = 1.f;

    float rn = 0.f, kn = 0.f, dn = 0.f, vn;
    if (tid < 64){ rn = rr[off + j]; kn = kk[off + j]; dn = dd[off + j]; }
    vn = vv[off + j];

    for (int t = 0; t < CL; t++) {
        float rc = rn, kc = kn, dc = dn, vc = vn;
        size_t offn = off + Cc;
        if (t + 1 < CL){
            if (tid < 64){ rn = rr[offn + j]; kn = kk[offn + j]; dn = dd[offn + j]; }
            vn = vv[offn + j];
        }
        if (tid < 64){
            rq[off + j] = rc * cum;
            cum *= dc;
            sv[j] = make_float4(rc, kc, ur * kc, dc);
        }
        __syncthreads();
        float a0 = 0.f, a1 = 0.f;
        #pragma unroll
        for (int ii = 0; ii < 16; ii += 2) {
            float4 q0 = sv[ib + ii];
            float4 q1 = sv[ib + ii + 1];
            a0 = fmaf(q0.x, fmaf(q0.z, vc, S[ii]), a0);
            S[ii] = fmaf(S[ii], q0.w, q0.y * vc);
            a1 = fmaf(q1.x, fmaf(q1.z, vc, S[ii + 1]), a1);
            S[ii + 1] = fmaf(S[ii + 1], q1.w, q1.y * vc);
        }
        yp[tid] = a0 + a1;
        __syncthreads();
        if (tid < 64) yy[off + j] = yp[j] + yp[64 + j] + yp[128 + j] + yp[192 + j];
        off = offn;
    }
    const size_t pbase = ((size_t)bh * CH + ch) * 4096;
    #pragma unroll
    for (int ii = 0; ii < 16; ii++)
        Pc[pbase + (size_t)(ib + ii) * 64 + j] = S[ii];
    if (tid < 64) Dc[((size_t)bh * CH + ch) * 64 + j] = cum;
}

__global__ __launch_bounds__(256)
void wkv6_partB(const float* __restrict__ Pc, const float* __restrict__ Dc,
                float* __restrict__ S0)
{
    const int bh = blockIdx.x;
    const int tid = threadIdx.x;
    const int e0 = tid * 16;
    const int i  = e0 >> 6;
    float4 s[4];
    #pragma unroll
    for (int q = 0; q < 4; q++) s[q] = make_float4(0.f, 0.f, 0.f, 0.f);
    for (int ch = 0; ch < CH; ch++){
        const size_t base = ((size_t)bh * CH + ch) * 4096 + e0;
        #pragma unroll
        for (int q = 0; q < 4; q++)
            *reinterpret_cast<float4*>(&S0[base + q*4]) = s[q];
        const float d = Dc[((size_t)bh * CH + ch) * 64 + i];
        #pragma unroll
        for (int q = 0; q < 4; q++){
            float4 p = *reinterpret_cast<const float4*>(&Pc[base + q*4]);
            s[q].x = fmaf(s[q].x, d, p.x);
            s[q].y = fmaf(s[q].y, d, p.y);
            s[q].z = fmaf(s[q].z, d, p.z);
            s[q].w = fmaf(s[q].w, d, p.w);
        }
    }
}

__global__ __launch_bounds__(256)
void wkv6_partC(const float* __restrict__ rq, const float* __restrict__ S0,
                float* __restrict__ yy)
{
    const int x = blockIdx.x;
    const int half = x & 1;
    const int ch = (x >> 1) & (CH - 1);
    const int bh = x >> 5;
    if (ch == 0) return;
    const int b = bh >> 5, hh = bh & 31;
    __shared__ float sS0[64][68];
    __shared__ float sRq[64][68];
    const int tid = threadIdx.x;
    const size_t off = (size_t)b * Tt * Cc
                     + (size_t)(ch * CL + half * 64) * Cc + (size_t)hh * Nn;
    const size_t sbase = ((size_t)bh * CH + ch) * 4096;

    {
        const int e0 = tid * 16;
        const int r = e0 >> 6, c = e0 & 63;
        #pragma unroll
        for (int q = 0; q < 4; q++){
            float4 v = *reinterpret_cast<const float4*>(&S0[sbase + e0 + q*4]);
            *reinterpret_cast<float4*>(&sS0[r][c + q*4]) = v;
            float4 w = *reinterpret_cast<const float4*>(&rq[off + (size_t)r * Cc + c + q*4]);
            *reinterpret_cast<float4*>(&sRq[r][c + q*4]) = w;
        }
    }
    __syncthreads();

    const int tr = tid >> 2;
    const int jq = (tid & 3) * 16;
    float acc[16];
    #pragma unroll
    for (int q = 0; q < 16; q++) acc[q] = 0.f;
    #pragma unroll 4
    for (int i = 0; i < 64; i++){
        float rv = sRq[tr][i];
        #pragma unroll
        for (int q = 0; q < 16; q++)
            acc[q] = fmaf(rv, sS0[i][jq + q], acc[q]);
    }
    const size_t ybase = off + (size_t)tr * Cc + jq;
    #pragma unroll
    for (int q = 0; q < 16; q += 4){
        float4 y4 = *reinterpret_cast<float4*>(&yy[ybase + q]);
        y4.x += acc[q];     y4.y += acc[q + 1];
        y4.z += acc[q + 2]; y4.w += acc[q + 3];
        *reinterpret_cast<float4*>(&yy[ybase + q]) = y4;
    }
}

// ---------------- GroupNorm(H) * silu-gate -> att fp16 ----------------
__global__ __launch_bounds__(256)
void gnsilu_kernel(const float* __restrict__ lnw, const float* __restrict__ lnb,
                   const float* __restrict__ gg, const float* __restrict__ yy)
{
    int gw  = blockIdx.x * 8 + (threadIdx.x >> 5);
    int lane = threadIdx.x & 31;
    int t  = gw >> 5;
    int hh = gw & 31;
    size_t base = (size_t)t * Cc + (size_t)hh * Nn;
    float y0 = yy[base + lane], y1 = yy[base + 32 + lane];
    float sum = y0 + y1, sq = y0*y0 + y1*y1;
    #pragma unroll
    for (int o = 16; o; o >>= 1) {
        sum += __shfl_xor_sync(0xffffffffu, sum, o);
        sq  += __shfl_xor_sync(0xffffffffu, sq,  o);
    }
    float m = sum * (1.f / 64.f);
    float rstd = rsqrtf(sq * (1.f / 64.f) - m*m + 6.4e-4f);
    int ch = hh * Nn + lane;
    float gv0 = gg[base + lane], gv1 = gg[base + 32 + lane];
    float o0 = ((y0 - m) * rstd * lnw[ch]      + lnb[ch])      * gv0;
    float o1 = ((y1 - m) * rstd * lnw[ch + 32] + lnb[ch + 32]) * gv1;
    g_att16[base + lane]      = __float2half_rn(o0);
    g_att16[base + 32 + lane] = __float2half_rn(o1);
}

// ---------------- host launch (single stream) ----------------
#define SYMADDR(v, s) cudaGetSymbolAddress((void**)&v, s)

extern "C" void kernel_launch(void* const* d_in, const int* in_sizes, int n_in,
                              void* d_out, int out_size)
{
    (void)in_sizes; (void)n_in; (void)out_size;
    const float* x          = (const float*)d_in[0];
    const float* ln1_w      = (const float*)d_in[1];
    const float* ln1_b      = (const float*)d_in[2];
    const float* ln2_w      = (const float*)d_in[3];
    const float* ln2_b      = (const float*)d_in[4];
    const float* tm_maa     = (const float*)d_in[5];
    const float* maa_w1     = (const float*)d_in[6];
    const float* maa_w2     = (const float*)d_in[7];
    const float* time_decay = (const float*)d_in[8];
    const float* td_w1      = (const float*)d_in[9];
    const float* td_w2      = (const float*)d_in[10];
    const float* time_faaaa = (const float*)d_in[11];
    const float* Wr  = (const float*)d_in[12];
    const float* Wk  = (const float*)d_in[13];
    const float* Wv  = (const float*)d_in[14];
    const float* Wg  = (const float*)d_in[15];
    const float* Wo  = (const float*)d_in[16];
    const float* lnx_w = (const float*)d_in[17];
    const float* lnx_b = (const float*)d_in[18];
    const float* cm_maa = (const float*)d_in[19];
    const float* Wck = (const float*)d_in[20];
    const float* Wcr = (const float*)d_in[21];
    const float* Wcv = (const float*)d_in[22];
    float* out = (float*)d_out;

    float *pw, *py, *px1, *psig, *pout4, *prq, *pP, *pD, *pS0;
    SYMADDR(pw, g_w);   SYMADDR(py, g_y);
    SYMADDR(px1, g_x1); SYMADDR(psig, g_sig); SYMADDR(pout4, g_out4);
    SYMADDR(prq, g_rq); SYMADDR(pP, g_P);   SYMADDR(pD, g_D);  SYMADDR(pS0, g_S0);

    __half *h16,*xx16,*a16,*xxx16,*xw16,*wt16,*a4,*att16,*xk216,*xr216,*kf16;
    SYMADDR(h16, g_h16); SYMADDR(xx16, g_xx16);
    SYMADDR(a16, g_a16);
    SYMADDR(xxx16, g_xxx16); SYMADDR(xw16, g_xw16);
    SYMADDR(wt16, g_wt16);
    SYMADDR(a4, g_act4);     SYMADDR(att16, g_att16);
    SYMADDR(xk216, g_xk216); SYMADDR(xr216, g_xr216);
    SYMADDR(kf16, g_kf16);

    __half *w4,*wo16,*wffn1,*wcv16,*maaT,*tdT,*td2T,*w2T;
    SYMADDR(w4, g_W4_16);    SYMADDR(wo16, g_Wo16);
    SYMADDR(wffn1, g_Wffn1); SYMADDR(wcv16, g_Wcv16);
    SYMADDR(maaT, g_maaw1T); SYMADDR(tdT, g_tdw1T);
    SYMADDR(td2T, g_tdw2T);  SYMADDR(w2T, g_w2T);

    cudaFuncSetAttribute((const void*)gemm_mma<TC_TANH16,64>, cudaFuncAttributeMaxDynamicSharedMemorySize, SM_MMA_64);
    cudaFuncSetAttribute((const void*)gemm_mma<TC_DECAY,128>, cudaFuncAttributeMaxDynamicSharedMemorySize, SM_MMA_128);
    cudaFuncSetAttribute((const void*)gemm_mma<TC_ADDX,128>,  cudaFuncAttributeMaxDynamicSharedMemorySize, SM_MMA_128);
    cudaFuncSetAttribute((const void*)gemm_mma<TC_CVMIX,128>, cudaFuncAttributeMaxDynamicSharedMemorySize, SM_MMA_128);
    cudaFuncSetAttribute((const void*)gemm_mix5,              cudaFuncAttributeMaxDynamicSharedMemorySize, SM_MIX);
    cudaFuncSetAttribute((const void*)gemm_rkvg5,             cudaFuncAttributeMaxDynamicSharedMemorySize, SM_MMA_128);
    cudaFuncSetAttribute((const void*)gemm_ffn1,              cudaFuncAttributeMaxDynamicSharedMemorySize, SM_MMA_128);

    // ---- weight prep: one launch ----
    wtrans_all<<<WT_TOTAL, 256>>>(Wr, Wk, Wv, Wg, Wo, Wcr, Wck, Wcv,
        maa_w1, td_w1, td_w2, maa_w2,
        w4, wo16, wffn1 + (size_t)Ff * Cc, wffn1, wcv16, maaT, tdT, td2T, w2T);

    // ---- time mixing ----
    lnshift1_kernel<<<MM, 256>>>(x, ln1_w, ln1_b, tm_maa);
    gemm_mma<TC_TANH16,64><<<dim3(256/128, MM/64), 256, SM_MMA_64>>>(xxx16, maaT, nullptr,
        MM, 256, Cc, Cc, Cc, LDA_A, 192, nullptr, nullptr, nullptr, a16);
    gemm_mix5<<<dim3(Cc/128, MM/128), 256, SM_MIX>>>(a16, w2T, tm_maa,
        h16, xx16, xw16, a4);
    gemm_rkvg5<<<dim3(Cc/128, MM/128, 5), 256, SM_MMA_128>>>(a4, w4, pout4,
        xw16, tdT, wt16);
    gemm_mma<TC_DECAY,128><<<dim3(Cc/128, MM/128), 256, SM_MMA_128>>>(wt16, td2T, pw,
        MM, Cc, 64, 64, 64, Cc, Cc, nullptr, nullptr, time_decay, nullptr);
    wkv6_partA<<<64 * CH, 256>>>(time_faaaa,
        pout4 + (size_t)0*MM*Cc, pout4 + (size_t)1*MM*Cc, pout4 + (size_t)2*MM*Cc,
        pw, py, prq, pP, pD);
    wkv6_partB<<<64, 256>>>(pP, pD, pS0);
    wkv6_partC<<<64 * CH * 2, 256>>>(prq, pS0, py);
    gnsilu_kernel<<<MM * Hh / 8, 256>>>(lnx_w, lnx_b, pout4 + (size_t)3*MM*Cc, py);
    gemm_mma<TC_ADDX,128><<<dim3(Cc/128, MM/128), 256, SM_MMA_128>>>(att16, wo16, px1,
        MM, Cc, Cc, Cc, Cc, Cc, Cc, x, nullptr, nullptr, nullptr);

    // ---- channel mixing ----
    lnshift2_kernel<<<MM, 256>>>(px1, ln2_w, ln2_b, cm_maa);
    gemm_ffn1<<<dim3(NF1/128, MM/128), 256, SM_MMA_128>>>(xk216, xr216, wffn1,
        kf16, psig, Ff/128);
    gemm_mma<TC_CVMIX,128><<<dim3(Cc/128, MM/128), 256, SM_MMA_128>>>(kf16, wcv16, out,
        MM, Cc, Ff, Ff, Ff, Cc, Cc, px1, psig, nullptr, nullptr);
}